// round 9
// baseline (speedup 1.0000x reference)
#include <cuda_runtime.h>
#include <cuda_bf16.h>
#include <math.h>
#include <cstdint>

// Problem constants
#define BB 2
#define TT 2048
#define DD 2048
#define HH 16
#define KVH 4
#define HD 128
#define REP (HH / KVH)
#define NTOK (BB * TT)   // 4096

// Scratch (device globals — no allocation allowed)
__device__ float g_q[(size_t)NTOK * HH * HD];    // 32 MB
__device__ float g_k[(size_t)NTOK * KVH * HD];   // 8 MB
__device__ float g_v[(size_t)NTOK * KVH * HD];   // 8 MB
__device__ float g_att[(size_t)NTOK * HH * HD];  // 32 MB

__device__ __forceinline__ uint32_t f2tf32(float f) {
    uint32_t r;
    asm("cvt.rna.tf32.f32 %0, %1;" : "=r"(r) : "f"(f));
    return r;
}

__device__ __forceinline__ uint32_t smem_u32(const void* p) {
    uint32_t a;
    asm("{ .reg .u64 t; cvta.to.shared.u64 t, %1; cvt.u32.u64 %0, t; }"
        : "=r"(a) : "l"(p));
    return a;
}

__device__ __forceinline__ void mma_tf32(float c[4],
    uint32_t a0, uint32_t a1, uint32_t a2, uint32_t a3,
    uint32_t b0, uint32_t b1)
{
    asm volatile(
        "mma.sync.aligned.m16n8k8.row.col.f32.tf32.tf32.f32 "
        "{%0,%1,%2,%3}, {%4,%5,%6,%7}, {%8,%9}, {%0,%1,%2,%3};"
        : "+f"(c[0]), "+f"(c[1]), "+f"(c[2]), "+f"(c[3])
        : "r"(a0), "r"(a1), "r"(a2), "r"(a3), "r"(b0), "r"(b1));
}

__device__ __forceinline__ void cpa16(uint32_t dst, const float* src) {
    asm volatile("cp.async.cg.shared.global [%0], [%1], 16;"
                 :: "r"(dst), "l"(src));
}
#define CP_COMMIT() asm volatile("cp.async.commit_group;" ::: "memory")
#define CP_WAIT(n)  asm volatile("cp.async.wait_group %0;" :: "n"(n) : "memory")

// ===========================================================================
// tf32 mma.sync GEMM (unchanged — passing)
// ===========================================================================
#define GBM 128
#define GBN 128
#define GBK 16
#define ASTR (GBK + 4)
#define BSTR (GBN + 8)

__global__ __launch_bounds__(256) void gemm_mma(
    int M, int N, int K,
    const float* __restrict__ A, const float* __restrict__ B,
    float* __restrict__ C)
{
    __shared__ float As[2][GBM][ASTR];
    __shared__ float Bs[2][GBK][BSTR];

    const int tid  = threadIdx.x;
    const int wid  = tid >> 5;
    const int lane = tid & 31;
    const int gid  = lane >> 2;
    const int tid4 = lane & 3;

    const int warp_m = (wid & 1) * 64;
    const int warp_n = (wid >> 1) * 32;

    const int m0 = blockIdx.y * GBM;
    const int n0 = blockIdx.x * GBN;

    const int ar  = tid >> 2;
    const int ac4 = tid & 3;
    const int bk  = tid >> 5;
    const int bn4 = tid & 31;

    const float* aptr = A + (size_t)(m0 + ar) * K + ac4 * 4;
    const float* bptr = B + (size_t)bk * N + n0 + bn4 * 4;
    const size_t aoff2 = (size_t)64 * K;
    const size_t boff2 = (size_t)8 * N;

    float acc[4][4][4];
    #pragma unroll
    for (int i = 0; i < 4; i++)
        #pragma unroll
        for (int j = 0; j < 4; j++)
            #pragma unroll
            for (int r = 0; r < 4; r++) acc[i][j][r] = 0.f;

    const int nch = K / GBK;

    float4 pa0 = *(const float4*)(aptr);
    float4 pa1 = *(const float4*)(aptr + aoff2);
    float4 pb0 = *(const float4*)(bptr);
    float4 pb1 = *(const float4*)(bptr + boff2);

    {
        uint32_t t[4];
        t[0]=f2tf32(pa0.x); t[1]=f2tf32(pa0.y); t[2]=f2tf32(pa0.z); t[3]=f2tf32(pa0.w);
        *(uint4*)&As[0][ar][ac4 * 4] = *(uint4*)t;
        t[0]=f2tf32(pa1.x); t[1]=f2tf32(pa1.y); t[2]=f2tf32(pa1.z); t[3]=f2tf32(pa1.w);
        *(uint4*)&As[0][ar + 64][ac4 * 4] = *(uint4*)t;
        t[0]=f2tf32(pb0.x); t[1]=f2tf32(pb0.y); t[2]=f2tf32(pb0.z); t[3]=f2tf32(pb0.w);
        *(uint4*)&Bs[0][bk][bn4 * 4] = *(uint4*)t;
        t[0]=f2tf32(pb1.x); t[1]=f2tf32(pb1.y); t[2]=f2tf32(pb1.z); t[3]=f2tf32(pb1.w);
        *(uint4*)&Bs[0][bk + 8][bn4 * 4] = *(uint4*)t;
    }
    __syncthreads();

    for (int ch = 0; ch < nch; ch++) {
        const int buf = ch & 1;
        const int nxt = ch + 1;

        if (nxt < nch) {
            const float* ap = aptr + (size_t)nxt * GBK;
            const float* bp = bptr + (size_t)nxt * GBK * N;
            pa0 = *(const float4*)(ap);
            pa1 = *(const float4*)(ap + aoff2);
            pb0 = *(const float4*)(bp);
            pb1 = *(const float4*)(bp + boff2);
        }

        #pragma unroll
        for (int kk = 0; kk < 2; kk++) {
            const int kb = kk * 8;
            uint32_t af[4][4], bf[4][2];
            #pragma unroll
            for (int mi = 0; mi < 4; mi++) {
                const int r = warp_m + mi * 16 + gid;
                af[mi][0] = __float_as_uint(As[buf][r    ][kb + tid4]);
                af[mi][1] = __float_as_uint(As[buf][r + 8][kb + tid4]);
                af[mi][2] = __float_as_uint(As[buf][r    ][kb + tid4 + 4]);
                af[mi][3] = __float_as_uint(As[buf][r + 8][kb + tid4 + 4]);
            }
            #pragma unroll
            for (int ni = 0; ni < 4; ni++) {
                const int c = warp_n + ni * 8 + gid;
                bf[ni][0] = __float_as_uint(Bs[buf][kb + tid4    ][c]);
                bf[ni][1] = __float_as_uint(Bs[buf][kb + tid4 + 4][c]);
            }
            #pragma unroll
            for (int mi = 0; mi < 4; mi++)
                #pragma unroll
                for (int ni = 0; ni < 4; ni++)
                    mma_tf32(acc[mi][ni], af[mi][0], af[mi][1], af[mi][2], af[mi][3],
                             bf[ni][0], bf[ni][1]);
        }

        if (nxt < nch) {
            const int nb = nxt & 1;
            uint32_t t[4];
            t[0]=f2tf32(pa0.x); t[1]=f2tf32(pa0.y); t[2]=f2tf32(pa0.z); t[3]=f2tf32(pa0.w);
            *(uint4*)&As[nb][ar][ac4 * 4] = *(uint4*)t;
            t[0]=f2tf32(pa1.x); t[1]=f2tf32(pa1.y); t[2]=f2tf32(pa1.z); t[3]=f2tf32(pa1.w);
            *(uint4*)&As[nb][ar + 64][ac4 * 4] = *(uint4*)t;
            t[0]=f2tf32(pb0.x); t[1]=f2tf32(pb0.y); t[2]=f2tf32(pb0.z); t[3]=f2tf32(pb0.w);
            *(uint4*)&Bs[nb][bk][bn4 * 4] = *(uint4*)t;
            t[0]=f2tf32(pb1.x); t[1]=f2tf32(pb1.y); t[2]=f2tf32(pb1.z); t[3]=f2tf32(pb1.w);
            *(uint4*)&Bs[nb][bk + 8][bn4 * 4] = *(uint4*)t;
        }
        __syncthreads();
    }

    #pragma unroll
    for (int mi = 0; mi < 4; mi++) {
        const int r = m0 + warp_m + mi * 16 + gid;
        #pragma unroll
        for (int ni = 0; ni < 4; ni++) {
            const int c = n0 + warp_n + ni * 8 + tid4 * 2;
            *(float2*)(C + (size_t)r * N + c) =
                make_float2(acc[mi][ni][0], acc[mi][ni][1]);
            *(float2*)(C + (size_t)(r + 8) * N + c) =
                make_float2(acc[mi][ni][2], acc[mi][ni][3]);
        }
    }
}

// ---------------------------------------------------------------------------
// Fused RMSNorm+RoPE (q,k) + tf32 pre-round (q,k,v) — ONE launch.
// Pre-rounding k/v in global memory means flash's cp.async raw loads feed
// tf32 mma with exactly cvt.rna values (no truncation bias).
// block = (32, HH + 2*KVH) = (32, 24); grid = NTOK.
// ---------------------------------------------------------------------------
__global__ void norm_rope_round(float* __restrict__ q, float* __restrict__ k,
                                float* __restrict__ vv,
                                const float* __restrict__ qw,
                                const float* __restrict__ kw,
                                const float* __restrict__ fc,
                                const float* __restrict__ fs)
{
    const int token = blockIdx.x;
    const int t = token & (TT - 1);
    const int y = threadIdx.y;
    const int lane = threadIdx.x;

    if (y >= HH + KVH) {
        // v: round to tf32 only
        const int head = y - HH - KVH;
        float* base = vv + ((size_t)token * KVH + head) * HD;
        float4 val = *(float4*)(base + lane * 4);
        uint32_t r0 = f2tf32(val.x), r1 = f2tf32(val.y),
                 r2 = f2tf32(val.z), r3 = f2tf32(val.w);
        *(uint4*)(base + lane * 4) = make_uint4(r0, r1, r2, r3);
        return;
    }

    const bool isq = (y < HH);
    const int head = isq ? y : (y - HH);
    const int heads = isq ? HH : KVH;
    float* u = isq ? q : k;
    const float* w = isq ? qw : kw;

    float* base = u + ((size_t)token * heads + head) * HD;
    float4 v = *(float4*)(base + lane * 4);

    float ss = v.x * v.x + v.y * v.y + v.z * v.z + v.w * v.w;
    #pragma unroll
    for (int o = 16; o > 0; o >>= 1) ss += __shfl_xor_sync(0xFFFFFFFFu, ss, o);
    const float r = rsqrtf(ss * (1.f / HD) + 1e-6f);

    const float4 wv = *(const float4*)(w + lane * 4);
    const int p = lane * 2;
    const float c0 = fc[t * (HD / 2) + p],     s0 = fs[t * (HD / 2) + p];
    const float c1 = fc[t * (HD / 2) + p + 1], s1 = fs[t * (HD / 2) + p + 1];

    const float e0 = v.x * r * wv.x, o0 = v.y * r * wv.y;
    const float e1 = v.z * r * wv.z, o1 = v.w * r * wv.w;

    // rope + tf32 round (q and k both feed tf32 mma A/B operands)
    uint32_t r0 = f2tf32(e0 * c0 - o0 * s0);
    uint32_t r1 = f2tf32(e0 * s0 + o0 * c0);
    uint32_t r2 = f2tf32(e1 * c1 - o1 * s1);
    uint32_t r3 = f2tf32(e1 * s1 + o1 * c1);
    *(uint4*)(base + lane * 4) = make_uint4(r0, r1, r2, r3);
}

// ===========================================================================
// Tensor-core causal flash attention v3.1 — software pipelined, batched frags.
// TQ=128 (8 warps x m16), TK=64. cp.async double-buffered K/V (pre-rounded
// to tf32 in gmem). PV(kt) + S(kt+1) back-to-back mma, then one softmax.
// smem: 2*Ks[64][132] + 2*Vs[64][136] + Ps[128][68] = 172032 B. 1 CTA/SM.
// ===========================================================================
#define FTQ 128
#define FTK 64
#define KSTRK 132
#define KSTRV 136
#define PSTR 68
#define FA3_SMEM ((2 * FTK * KSTRK + 2 * FTK * KSTRV + FTQ * PSTR) * (int)sizeof(float))

__device__ __forceinline__ float redmax4(float x) {
    x = fmaxf(x, __shfl_xor_sync(0xFFFFFFFFu, x, 1));
    x = fmaxf(x, __shfl_xor_sync(0xFFFFFFFFu, x, 2));
    return x;
}
__device__ __forceinline__ float redsum4(float x) {
    x += __shfl_xor_sync(0xFFFFFFFFu, x, 1);
    x += __shfl_xor_sync(0xFFFFFFFFu, x, 2);
    return x;
}

__device__ __forceinline__ void issue_kv_tile(
    const float* __restrict__ src, int b, int g, int kt, uint32_t smem_base,
    int stride, int tid)
{
    const int t0 = b * TT + kt * FTK;
    #pragma unroll
    for (int it = 0; it < 8; it++) {
        const int i = tid + it * 256;
        const int r = i >> 5, c4 = i & 31;
        const float* s = src + ((size_t)(t0 + r) * KVH + g) * HD + c4 * 4;
        cpa16(smem_base + (uint32_t)(r * stride + c4 * 4) * 4u, s);
    }
}

__global__ __launch_bounds__(256) void flash_tc(
    const float* __restrict__ q, const float* __restrict__ k,
    const float* __restrict__ v, float* __restrict__ o)
{
    extern __shared__ float sm[];
    float* Ks0 = sm;
    float* Ks1 = Ks0 + FTK * KSTRK;
    float* Vs0 = Ks1 + FTK * KSTRK;
    float* Vs1 = Vs0 + FTK * KSTRV;
    float* Ps  = Vs1 + FTK * KSTRV;
    const uint32_t ks0u = smem_u32(Ks0);
    const uint32_t ks1u = smem_u32(Ks1);
    const uint32_t vs0u = smem_u32(Vs0);
    const uint32_t vs1u = smem_u32(Vs1);

    // LPT schedule: longest q-tiles first
    const int qt = (TT / FTQ - 1) - blockIdx.y;
    const int hb = blockIdx.x;            // b*HH + h
    const int h  = hb % HH;
    const int b  = hb / HH;
    const int g  = h / REP;
    const int tid  = threadIdx.x;
    const int wid  = tid >> 5;
    const int lane = tid & 31;
    const int gid  = lane >> 2;
    const int tid4 = lane & 3;
    const int q0 = qt * FTQ;
    const int wq = wid * 16;

    // --- Stage Q into Ks1/Vs1 scratch, pull fragments to regs ---
    // (q already tf32-rounded in gmem)
    const int sstr = (wid < 4) ? KSTRK : KSTRV;
    float* Sg = (wid < 4) ? (Ks1 + wq * KSTRK) : (Vs1 + (wq - 64) * KSTRV);
    #pragma unroll
    for (int it = 0; it < 16; it++) {
        const int i = lane + it * 32;
        const int r = i >> 5, c4 = i & 31;
        const float4 qv = *(const float4*)(
            q + ((size_t)(b * TT + q0 + wq + r) * HH + h) * HD + c4 * 4);
        *(float4*)&Sg[r * sstr + c4 * 4] = qv;
    }
    __syncwarp();
    uint32_t qf[16][4];
    #pragma unroll
    for (int kf = 0; kf < 16; kf++) {
        const int kb = kf * 8;
        qf[kf][0] = __float_as_uint(Sg[gid * sstr + kb + tid4]);
        qf[kf][1] = __float_as_uint(Sg[(gid + 8) * sstr + kb + tid4]);
        qf[kf][2] = __float_as_uint(Sg[gid * sstr + kb + tid4 + 4]);
        qf[kf][3] = __float_as_uint(Sg[(gid + 8) * sstr + kb + tid4 + 4]);
    }
    __syncthreads();   // all staging reads done before cp.async may land

    const int nkt = 2 * qt + 2;

    // Preload tile 0 (K then V as separate groups)
    issue_kv_tile(k, b, g, 0, ks0u, KSTRK, tid); CP_COMMIT();
    issue_kv_tile(v, b, g, 0, vs0u, KSTRV, tid); CP_COMMIT();

    float oacc[16][4];
    #pragma unroll
    for (int i = 0; i < 16; i++)
        #pragma unroll
        for (int j = 0; j < 4; j++) oacc[i][j] = 0.f;
    float m0r = -1e30f, m1r = -1e30f, l0r = 0.f, l1r = 0.f;

    const float scale = 0.08838834764831845f;  // 1/sqrt(128)
    const int r0 = q0 + wq + gid;
    const int r1 = r0 + 8;

    for (int kt = -1; kt < nkt; kt++) {
        const int cb = kt & 1;   // (-1)&1 == 1

        // s1: prefetch K(kt+2)
        if (kt + 2 < nkt) {
            issue_kv_tile(k, b, g, kt + 2, cb ? ks1u : ks0u, KSTRK, tid);
            CP_COMMIT();
        }
        // s2: wait until V(kt) and K(kt+1) have landed
        if (kt + 2 < nkt)      { CP_WAIT(2); }
        else if (kt + 1 < nkt) { CP_WAIT(1); }
        else                   { CP_WAIT(0); }
        __syncthreads();

        // s3a: O += P(kt) V(kt), batched fragment loads
        if (kt >= 0) {
            const float* Vb = cb ? Vs1 : Vs0;
            #pragma unroll
            for (int kf = 0; kf < 8; kf++) {
                const int kb = kf * 8;
                const uint32_t a0 = __float_as_uint(Ps[(wq + gid) * PSTR + kb + tid4]);
                const uint32_t a1 = __float_as_uint(Ps[(wq + gid + 8) * PSTR + kb + tid4]);
                const uint32_t a2 = __float_as_uint(Ps[(wq + gid) * PSTR + kb + tid4 + 4]);
                const uint32_t a3 = __float_as_uint(Ps[(wq + gid + 8) * PSTR + kb + tid4 + 4]);
                #pragma unroll
                for (int nh = 0; nh < 4; nh++) {   // batches of 4 n-tiles
                    uint32_t bb[4][2];
                    #pragma unroll
                    for (int j = 0; j < 4; j++) {
                        const int nt = nh * 4 + j;
                        bb[j][0] = __float_as_uint(Vb[(kb + tid4) * KSTRV + nt * 8 + gid]);
                        bb[j][1] = __float_as_uint(Vb[(kb + tid4 + 4) * KSTRV + nt * 8 + gid]);
                    }
                    #pragma unroll
                    for (int j = 0; j < 4; j++)
                        mma_tf32(oacc[nh * 4 + j], a0, a1, a2, a3, bb[j][0], bb[j][1]);
                }
            }
        }
        // s3b: S(kt+1) = Q K(kt+1)^T, batched fragment loads
        float sacc[8][4];
        if (kt + 1 < nkt) {
            const float* Kb = cb ? Ks0 : Ks1;   // parity (kt+1)&1
            #pragma unroll
            for (int nt = 0; nt < 8; nt++)
                #pragma unroll
                for (int j = 0; j < 4; j++) sacc[nt][j] = 0.f;
            #pragma unroll
            for (int kf = 0; kf < 16; kf++) {
                const int kb = kf * 8;
                #pragma unroll
                for (int nh = 0; nh < 2; nh++) {   // batches of 4 n-tiles
                    uint32_t bb[4][2];
                    #pragma unroll
                    for (int j = 0; j < 4; j++) {
                        const int nt = nh * 4 + j;
                        bb[j][0] = __float_as_uint(Kb[(nt * 8 + gid) * KSTRK + kb + tid4]);
                        bb[j][1] = __float_as_uint(Kb[(nt * 8 + gid) * KSTRK + kb + tid4 + 4]);
                    }
                    #pragma unroll
                    for (int j = 0; j < 4; j++)
                        mma_tf32(sacc[nh * 4 + j], qf[kf][0], qf[kf][1], qf[kf][2],
                                 qf[kf][3], bb[j][0], bb[j][1]);
                }
            }
        }

        // s4: all PV(kt) reads done -> prefetch V(kt+2)
        __syncthreads();
        if (kt + 2 < nkt) {
            issue_kv_tile(v, b, g, kt + 2, cb ? vs1u : vs0u, KSTRV, tid);
            CP_COMMIT();
        }

        // s5: softmax(kt+1)
        if (kt + 1 < nkt) {
            const int k0 = (kt + 1) * FTK;
            float mn0 = m0r, mn1 = m1r;
            if (k0 + FTK - 1 > q0 + wq) {   // warp-uniform diagonal check
                #pragma unroll
                for (int nt = 0; nt < 8; nt++) {
                    const int c = k0 + nt * 8 + tid4 * 2;
                    float s0 = sacc[nt][0] * scale, s1 = sacc[nt][1] * scale;
                    float s2 = sacc[nt][2] * scale, s3 = sacc[nt][3] * scale;
                    if (c     > r0) s0 = -1e30f;
                    if (c + 1 > r0) s1 = -1e30f;
                    if (c     > r1) s2 = -1e30f;
                    if (c + 1 > r1) s3 = -1e30f;
                    sacc[nt][0] = s0; sacc[nt][1] = s1; sacc[nt][2] = s2; sacc[nt][3] = s3;
                    mn0 = fmaxf(mn0, fmaxf(s0, s1));
                    mn1 = fmaxf(mn1, fmaxf(s2, s3));
                }
            } else {
                #pragma unroll
                for (int nt = 0; nt < 8; nt++) {
                    const float s0 = sacc[nt][0] * scale, s1 = sacc[nt][1] * scale;
                    const float s2 = sacc[nt][2] * scale, s3 = sacc[nt][3] * scale;
                    sacc[nt][0] = s0; sacc[nt][1] = s1; sacc[nt][2] = s2; sacc[nt][3] = s3;
                    mn0 = fmaxf(mn0, fmaxf(s0, s1));
                    mn1 = fmaxf(mn1, fmaxf(s2, s3));
                }
            }
            mn0 = redmax4(mn0);
            mn1 = redmax4(mn1);

            const float corr0 = __expf(m0r - mn0);
            const float corr1 = __expf(m1r - mn1);
            float ps0 = 0.f, ps1 = 0.f;
            #pragma unroll
            for (int nt = 0; nt < 8; nt++) {
                const float p0 = __expf(sacc[nt][0] - mn0);
                const float p1 = __expf(sacc[nt][1] - mn0);
                const float p2 = __expf(sacc[nt][2] - mn1);
                const float p3 = __expf(sacc[nt][3] - mn1);
                ps0 += p0 + p1;
                ps1 += p2 + p3;
                const int cc = nt * 8 + 2 * tid4;
                *(float2*)&Ps[(wq + gid) * PSTR + cc] =
                    make_float2(__uint_as_float(f2tf32(p0)), __uint_as_float(f2tf32(p1)));
                *(float2*)&Ps[(wq + gid + 8) * PSTR + cc] =
                    make_float2(__uint_as_float(f2tf32(p2)), __uint_as_float(f2tf32(p3)));
            }
            l0r = l0r * corr0 + redsum4(ps0);
            l1r = l1r * corr1 + redsum4(ps1);
            m0r = mn0; m1r = mn1;

            #pragma unroll
            for (int nt = 0; nt < 16; nt++) {
                oacc[nt][0] *= corr0; oacc[nt][1] *= corr0;
                oacc[nt][2] *= corr1; oacc[nt][3] *= corr1;
            }
            __syncwarp();   // Ps rows warp-private: writes visible to lanes
        }
    }

    // Epilogue: normalize and store
    const float rl0 = 1.f / l0r;
    const float rl1 = 1.f / l1r;
    float* ob0 = o + ((size_t)(b * TT + r0) * HH + h) * HD;
    float* ob1 = o + ((size_t)(b * TT + r1) * HH + h) * HD;
    #pragma unroll
    for (int nt = 0; nt < 16; nt++) {
        const int c = nt * 8 + 2 * tid4;
        *(float2*)(ob0 + c) = make_float2(oacc[nt][0] * rl0, oacc[nt][1] * rl0);
        *(float2*)(ob1 + c) = make_float2(oacc[nt][2] * rl1, oacc[nt][3] * rl1);
    }
}

// ---------------------------------------------------------------------------
extern "C" void kernel_launch(void* const* d_in, const int* in_sizes, int n_in,
                              void* d_out, int out_size)
{
    const float* x    = (const float*)d_in[0];
    const float* wq   = (const float*)d_in[1];
    const float* wk   = (const float*)d_in[2];
    const float* wv   = (const float*)d_in[3];
    const float* wo   = (const float*)d_in[4];
    const float* qnw  = (const float*)d_in[5];
    const float* knw  = (const float*)d_in[6];
    const float* fcos = (const float*)d_in[7];
    const float* fsin = (const float*)d_in[8];
    float* out = (float*)d_out;

    float *q, *k, *v, *att;
    cudaGetSymbolAddress((void**)&q,   g_q);
    cudaGetSymbolAddress((void**)&k,   g_k);
    cudaGetSymbolAddress((void**)&v,   g_v);
    cudaGetSymbolAddress((void**)&att, g_att);

    cudaFuncSetAttribute(flash_tc, cudaFuncAttributeMaxDynamicSharedMemorySize, FA3_SMEM);

    // Projections (tensor core tf32 via mma.sync)          [launches 1-3]
    gemm_mma<<<dim3((HH * HD) / GBN, NTOK / GBM), 256>>>(NTOK, HH * HD, DD, x, wq, q);
    gemm_mma<<<dim3((KVH * HD) / GBN, NTOK / GBM), 256>>>(NTOK, KVH * HD, DD, x, wk, k);
    gemm_mma<<<dim3((KVH * HD) / GBN, NTOK / GBM), 256>>>(NTOK, KVH * HD, DD, x, wv, v);

    // Fused RMSNorm+RoPE (q,k) + tf32 round (q,k,v)        [launch 4]
    norm_rope_round<<<NTOK, dim3(32, HH + 2 * KVH)>>>(q, k, v, qnw, knw, fcos, fsin);

    // Tensor-core flash attention (pipelined, LPT order)   [launch 5 — ncu slot]
    flash_tc<<<dim3(HH * BB, TT / FTQ), 256, FA3_SMEM>>>(q, k, v, att);

    // Output projection                                    [launch 6]
    gemm_mma<<<dim3(DD / GBN, NTOK / GBM), 256>>>(NTOK, DD, HH * HD, att, wo, out);
}

// round 11
// speedup vs baseline: 1.0103x; 1.0103x over previous
#include <cuda_runtime.h>
#include <cuda_bf16.h>
#include <math.h>
#include <cstdint>

// Problem constants
#define BB 2
#define TT 2048
#define DD 2048
#define HH 16
#define KVH 4
#define HD 128
#define REP (HH / KVH)
#define NTOK (BB * TT)   // 4096

// Scratch (device globals — no allocation allowed)
__device__ float g_q[(size_t)NTOK * HH * HD];    // 32 MB
__device__ float g_k[(size_t)NTOK * KVH * HD];   // 8 MB
__device__ float g_v[(size_t)NTOK * KVH * HD];   // 8 MB
__device__ float g_att[(size_t)NTOK * HH * HD];  // 32 MB

__device__ __forceinline__ uint32_t f2tf32(float f) {
    uint32_t r;
    asm("cvt.rna.tf32.f32 %0, %1;" : "=r"(r) : "f"(f));
    return r;
}

__device__ __forceinline__ uint32_t smem_u32(const void* p) {
    uint32_t a;
    asm("{ .reg .u64 t; cvta.to.shared.u64 t, %1; cvt.u32.u64 %0, t; }"
        : "=r"(a) : "l"(p));
    return a;
}

__device__ __forceinline__ void mma_tf32(float c[4],
    uint32_t a0, uint32_t a1, uint32_t a2, uint32_t a3,
    uint32_t b0, uint32_t b1)
{
    asm volatile(
        "mma.sync.aligned.m16n8k8.row.col.f32.tf32.tf32.f32 "
        "{%0,%1,%2,%3}, {%4,%5,%6,%7}, {%8,%9}, {%0,%1,%2,%3};"
        : "+f"(c[0]), "+f"(c[1]), "+f"(c[2]), "+f"(c[3])
        : "r"(a0), "r"(a1), "r"(a2), "r"(a3), "r"(b0), "r"(b1));
}

__device__ __forceinline__ void cpa16(uint32_t dst, const float* src) {
    asm volatile("cp.async.cg.shared.global [%0], [%1], 16;"
                 :: "r"(dst), "l"(src));
}
#define CP_COMMIT() asm volatile("cp.async.commit_group;" ::: "memory")
#define CP_WAIT(n)  asm volatile("cp.async.wait_group %0;" :: "n"(n) : "memory")

// ===========================================================================
// tf32 mma.sync GEMM (unchanged — passing)
// ===========================================================================
#define GBM 128
#define GBN 128
#define GBK 16
#define ASTR (GBK + 4)
#define BSTR (GBN + 8)

__global__ __launch_bounds__(256) void gemm_mma(
    int M, int N, int K,
    const float* __restrict__ A, const float* __restrict__ B,
    float* __restrict__ C)
{
    __shared__ float As[2][GBM][ASTR];
    __shared__ float Bs[2][GBK][BSTR];

    const int tid  = threadIdx.x;
    const int wid  = tid >> 5;
    const int lane = tid & 31;
    const int gid  = lane >> 2;
    const int tid4 = lane & 3;

    const int warp_m = (wid & 1) * 64;
    const int warp_n = (wid >> 1) * 32;

    const int m0 = blockIdx.y * GBM;
    const int n0 = blockIdx.x * GBN;

    const int ar  = tid >> 2;
    const int ac4 = tid & 3;
    const int bk  = tid >> 5;
    const int bn4 = tid & 31;

    const float* aptr = A + (size_t)(m0 + ar) * K + ac4 * 4;
    const float* bptr = B + (size_t)bk * N + n0 + bn4 * 4;
    const size_t aoff2 = (size_t)64 * K;
    const size_t boff2 = (size_t)8 * N;

    float acc[4][4][4];
    #pragma unroll
    for (int i = 0; i < 4; i++)
        #pragma unroll
        for (int j = 0; j < 4; j++)
            #pragma unroll
            for (int r = 0; r < 4; r++) acc[i][j][r] = 0.f;

    const int nch = K / GBK;

    float4 pa0 = *(const float4*)(aptr);
    float4 pa1 = *(const float4*)(aptr + aoff2);
    float4 pb0 = *(const float4*)(bptr);
    float4 pb1 = *(const float4*)(bptr + boff2);

    {
        uint32_t t[4];
        t[0]=f2tf32(pa0.x); t[1]=f2tf32(pa0.y); t[2]=f2tf32(pa0.z); t[3]=f2tf32(pa0.w);
        *(uint4*)&As[0][ar][ac4 * 4] = *(uint4*)t;
        t[0]=f2tf32(pa1.x); t[1]=f2tf32(pa1.y); t[2]=f2tf32(pa1.z); t[3]=f2tf32(pa1.w);
        *(uint4*)&As[0][ar + 64][ac4 * 4] = *(uint4*)t;
        t[0]=f2tf32(pb0.x); t[1]=f2tf32(pb0.y); t[2]=f2tf32(pb0.z); t[3]=f2tf32(pb0.w);
        *(uint4*)&Bs[0][bk][bn4 * 4] = *(uint4*)t;
        t[0]=f2tf32(pb1.x); t[1]=f2tf32(pb1.y); t[2]=f2tf32(pb1.z); t[3]=f2tf32(pb1.w);
        *(uint4*)&Bs[0][bk + 8][bn4 * 4] = *(uint4*)t;
    }
    __syncthreads();

    for (int ch = 0; ch < nch; ch++) {
        const int buf = ch & 1;
        const int nxt = ch + 1;

        if (nxt < nch) {
            const float* ap = aptr + (size_t)nxt * GBK;
            const float* bp = bptr + (size_t)nxt * GBK * N;
            pa0 = *(const float4*)(ap);
            pa1 = *(const float4*)(ap + aoff2);
            pb0 = *(const float4*)(bp);
            pb1 = *(const float4*)(bp + boff2);
        }

        #pragma unroll
        for (int kk = 0; kk < 2; kk++) {
            const int kb = kk * 8;
            uint32_t af[4][4], bf[4][2];
            #pragma unroll
            for (int mi = 0; mi < 4; mi++) {
                const int r = warp_m + mi * 16 + gid;
                af[mi][0] = __float_as_uint(As[buf][r    ][kb + tid4]);
                af[mi][1] = __float_as_uint(As[buf][r + 8][kb + tid4]);
                af[mi][2] = __float_as_uint(As[buf][r    ][kb + tid4 + 4]);
                af[mi][3] = __float_as_uint(As[buf][r + 8][kb + tid4 + 4]);
            }
            #pragma unroll
            for (int ni = 0; ni < 4; ni++) {
                const int c = warp_n + ni * 8 + gid;
                bf[ni][0] = __float_as_uint(Bs[buf][kb + tid4    ][c]);
                bf[ni][1] = __float_as_uint(Bs[buf][kb + tid4 + 4][c]);
            }
            #pragma unroll
            for (int mi = 0; mi < 4; mi++)
                #pragma unroll
                for (int ni = 0; ni < 4; ni++)
                    mma_tf32(acc[mi][ni], af[mi][0], af[mi][1], af[mi][2], af[mi][3],
                             bf[ni][0], bf[ni][1]);
        }

        if (nxt < nch) {
            const int nb = nxt & 1;
            uint32_t t[4];
            t[0]=f2tf32(pa0.x); t[1]=f2tf32(pa0.y); t[2]=f2tf32(pa0.z); t[3]=f2tf32(pa0.w);
            *(uint4*)&As[nb][ar][ac4 * 4] = *(uint4*)t;
            t[0]=f2tf32(pa1.x); t[1]=f2tf32(pa1.y); t[2]=f2tf32(pa1.z); t[3]=f2tf32(pa1.w);
            *(uint4*)&As[nb][ar + 64][ac4 * 4] = *(uint4*)t;
            t[0]=f2tf32(pb0.x); t[1]=f2tf32(pb0.y); t[2]=f2tf32(pb0.z); t[3]=f2tf32(pb0.w);
            *(uint4*)&Bs[nb][bk][bn4 * 4] = *(uint4*)t;
            t[0]=f2tf32(pb1.x); t[1]=f2tf32(pb1.y); t[2]=f2tf32(pb1.z); t[3]=f2tf32(pb1.w);
            *(uint4*)&Bs[nb][bk + 8][bn4 * 4] = *(uint4*)t;
        }
        __syncthreads();
    }

    #pragma unroll
    for (int mi = 0; mi < 4; mi++) {
        const int r = m0 + warp_m + mi * 16 + gid;
        #pragma unroll
        for (int ni = 0; ni < 4; ni++) {
            const int c = n0 + warp_n + ni * 8 + tid4 * 2;
            *(float2*)(C + (size_t)r * N + c) =
                make_float2(acc[mi][ni][0], acc[mi][ni][1]);
            *(float2*)(C + (size_t)(r + 8) * N + c) =
                make_float2(acc[mi][ni][2], acc[mi][ni][3]);
        }
    }
}

// ---------------------------------------------------------------------------
// Fused RMSNorm+RoPE (q,k) + tf32 pre-round (q,k,v) — ONE launch. (unchanged)
// ---------------------------------------------------------------------------
__global__ void norm_rope_round(float* __restrict__ q, float* __restrict__ k,
                                float* __restrict__ vv,
                                const float* __restrict__ qw,
                                const float* __restrict__ kw,
                                const float* __restrict__ fc,
                                const float* __restrict__ fs)
{
    const int token = blockIdx.x;
    const int t = token & (TT - 1);
    const int y = threadIdx.y;
    const int lane = threadIdx.x;

    if (y >= HH + KVH) {
        const int head = y - HH - KVH;
        float* base = vv + ((size_t)token * KVH + head) * HD;
        float4 val = *(float4*)(base + lane * 4);
        uint32_t r0 = f2tf32(val.x), r1 = f2tf32(val.y),
                 r2 = f2tf32(val.z), r3 = f2tf32(val.w);
        *(uint4*)(base + lane * 4) = make_uint4(r0, r1, r2, r3);
        return;
    }

    const bool isq = (y < HH);
    const int head = isq ? y : (y - HH);
    const int heads = isq ? HH : KVH;
    float* u = isq ? q : k;
    const float* w = isq ? qw : kw;

    float* base = u + ((size_t)token * heads + head) * HD;
    float4 v = *(float4*)(base + lane * 4);

    float ss = v.x * v.x + v.y * v.y + v.z * v.z + v.w * v.w;
    #pragma unroll
    for (int o = 16; o > 0; o >>= 1) ss += __shfl_xor_sync(0xFFFFFFFFu, ss, o);
    const float r = rsqrtf(ss * (1.f / HD) + 1e-6f);

    const float4 wv = *(const float4*)(w + lane * 4);
    const int p = lane * 2;
    const float c0 = fc[t * (HD / 2) + p],     s0 = fs[t * (HD / 2) + p];
    const float c1 = fc[t * (HD / 2) + p + 1], s1 = fs[t * (HD / 2) + p + 1];

    const float e0 = v.x * r * wv.x, o0 = v.y * r * wv.y;
    const float e1 = v.z * r * wv.z, o1 = v.w * r * wv.w;

    uint32_t r0 = f2tf32(e0 * c0 - o0 * s0);
    uint32_t r1 = f2tf32(e0 * s0 + o0 * c0);
    uint32_t r2 = f2tf32(e1 * c1 - o1 * s1);
    uint32_t r3 = f2tf32(e1 * s1 + o1 * c1);
    *(uint4*)(base + lane * 4) = make_uint4(r0, r1, r2, r3);
}

// ===========================================================================
// Tensor-core causal flash attention v4 — 2 CTAs/SM phase overlap.
// TQ=64 (4 warps x m16), TK=64, 128 threads/CTA, single-buffered K/V.
// smem: Ks[64][132] + Vs[64][136] + Ps[64][68] = 86016 B -> 2 CTAs/SM.
// Co-resident CTA hides softmax/barrier/load phases (desynchronized).
// ===========================================================================
#define FTQ 64
#define FTK 64
#define KSTRK 132
#define KSTRV 136
#define PSTR 68
#define FA4_SMEM ((FTK * KSTRK + FTK * KSTRV + FTQ * PSTR) * (int)sizeof(float))

__device__ __forceinline__ float redmax4(float x) {
    x = fmaxf(x, __shfl_xor_sync(0xFFFFFFFFu, x, 1));
    x = fmaxf(x, __shfl_xor_sync(0xFFFFFFFFu, x, 2));
    return x;
}
__device__ __forceinline__ float redsum4(float x) {
    x += __shfl_xor_sync(0xFFFFFFFFu, x, 1);
    x += __shfl_xor_sync(0xFFFFFFFFu, x, 2);
    return x;
}

__device__ __forceinline__ void issue_kv_tile4(
    const float* __restrict__ kp, const float* __restrict__ vp,
    int b, int g, int kt, uint32_t ksu, uint32_t vsu, int tid)
{
    const int t0 = b * TT + kt * FTK;
    #pragma unroll
    for (int it = 0; it < 16; it++) {
        const int i = tid + it * 128;
        const int r = i >> 5, c4 = i & 31;
        const size_t go = ((size_t)(t0 + r) * KVH + g) * HD + c4 * 4;
        cpa16(ksu + (uint32_t)(r * KSTRK + c4 * 4) * 4u, kp + go);
        cpa16(vsu + (uint32_t)(r * KSTRV + c4 * 4) * 4u, vp + go);
    }
}

__global__ __launch_bounds__(128) void flash_tc(
    const float* __restrict__ q, const float* __restrict__ k,
    const float* __restrict__ v, float* __restrict__ o)
{
    extern __shared__ float sm[];
    float* Ks = sm;                       // [64][132]
    float* Vs = Ks + FTK * KSTRK;         // [64][136]
    float* Ps = Vs + FTK * KSTRV;         // [64][68]
    const uint32_t ksu = smem_u32(Ks);
    const uint32_t vsu = smem_u32(Vs);

    // LPT schedule: longest q-tiles first
    const int qt = (TT / FTQ - 1) - blockIdx.y;
    const int hb = blockIdx.x;            // b*HH + h
    const int h  = hb % HH;
    const int b  = hb / HH;
    const int g  = h / REP;
    const int tid  = threadIdx.x;
    const int wid  = tid >> 5;            // 0..3
    const int lane = tid & 31;
    const int gid  = lane >> 2;
    const int tid4 = lane & 3;
    const int q0 = qt * FTQ;
    const int wq = wid * 16;

    // --- Stage Q: warps 0-1 via Ks rows, warps 2-3 via Vs rows ---
    const int sstr = (wid < 2) ? KSTRK : KSTRV;
    float* Sg = (wid < 2) ? (Ks + wq * KSTRK) : (Vs + (wq - 32) * KSTRV);
    #pragma unroll
    for (int it = 0; it < 16; it++) {
        const int i = lane + it * 32;
        const int r = i >> 5, c4 = i & 31;
        const float4 qv = *(const float4*)(
            q + ((size_t)(b * TT + q0 + wq + r) * HH + h) * HD + c4 * 4);
        *(float4*)&Sg[r * sstr + c4 * 4] = qv;
    }
    __syncwarp();
    uint32_t qf[16][4];
    #pragma unroll
    for (int kf = 0; kf < 16; kf++) {
        const int kb = kf * 8;
        qf[kf][0] = __float_as_uint(Sg[gid * sstr + kb + tid4]);
        qf[kf][1] = __float_as_uint(Sg[(gid + 8) * sstr + kb + tid4]);
        qf[kf][2] = __float_as_uint(Sg[gid * sstr + kb + tid4 + 4]);
        qf[kf][3] = __float_as_uint(Sg[(gid + 8) * sstr + kb + tid4 + 4]);
    }
    __syncthreads();   // staging reads done before cp.async may land

    const int nkt = qt + 1;

    // Preload tile 0
    issue_kv_tile4(k, v, b, g, 0, ksu, vsu, tid);
    CP_COMMIT();

    float oacc[16][4];
    #pragma unroll
    for (int i = 0; i < 16; i++)
        #pragma unroll
        for (int j = 0; j < 4; j++) oacc[i][j] = 0.f;
    float m0r = -1e30f, m1r = -1e30f, l0r = 0.f, l1r = 0.f;

    const float scale = 0.08838834764831845f;  // 1/sqrt(128)
    const int r0 = q0 + wq + gid;
    const int r1 = r0 + 8;

    for (int kt = 0; kt < nkt; kt++) {
        CP_WAIT(0);
        __syncthreads();   // K/V(kt) visible to all

        // --- S = Q K^T : 8 n-tiles x 16 k-frags, Q from registers ---
        float sacc[8][4];
        #pragma unroll
        for (int nt = 0; nt < 8; nt++)
            #pragma unroll
            for (int j = 0; j < 4; j++) sacc[nt][j] = 0.f;
        #pragma unroll
        for (int kf = 0; kf < 16; kf++) {
            const int kb = kf * 8;
            #pragma unroll
            for (int nt = 0; nt < 8; nt++) {
                const uint32_t b0 = __float_as_uint(Ks[(nt * 8 + gid) * KSTRK + kb + tid4]);
                const uint32_t b1 = __float_as_uint(Ks[(nt * 8 + gid) * KSTRK + kb + tid4 + 4]);
                mma_tf32(sacc[nt], qf[kf][0], qf[kf][1], qf[kf][2], qf[kf][3], b0, b1);
            }
        }

        // --- scale + (conditional) causal mask + row max ---
        const int k0 = kt * FTK;
        float mn0 = m0r, mn1 = m1r;
        if (kt == nkt - 1) {   // diagonal tile (warp-uniform)
            #pragma unroll
            for (int nt = 0; nt < 8; nt++) {
                const int c = k0 + nt * 8 + tid4 * 2;
                float s0 = sacc[nt][0] * scale, s1 = sacc[nt][1] * scale;
                float s2 = sacc[nt][2] * scale, s3 = sacc[nt][3] * scale;
                if (c     > r0) s0 = -1e30f;
                if (c + 1 > r0) s1 = -1e30f;
                if (c     > r1) s2 = -1e30f;
                if (c + 1 > r1) s3 = -1e30f;
                sacc[nt][0] = s0; sacc[nt][1] = s1; sacc[nt][2] = s2; sacc[nt][3] = s3;
                mn0 = fmaxf(mn0, fmaxf(s0, s1));
                mn1 = fmaxf(mn1, fmaxf(s2, s3));
            }
        } else {
            #pragma unroll
            for (int nt = 0; nt < 8; nt++) {
                const float s0 = sacc[nt][0] * scale, s1 = sacc[nt][1] * scale;
                const float s2 = sacc[nt][2] * scale, s3 = sacc[nt][3] * scale;
                sacc[nt][0] = s0; sacc[nt][1] = s1; sacc[nt][2] = s2; sacc[nt][3] = s3;
                mn0 = fmaxf(mn0, fmaxf(s0, s1));
                mn1 = fmaxf(mn1, fmaxf(s2, s3));
            }
        }
        mn0 = redmax4(mn0);
        mn1 = redmax4(mn1);

        // --- online softmax: rescale, exp, write P (tf32) ---
        const float corr0 = __expf(m0r - mn0);
        const float corr1 = __expf(m1r - mn1);
        float ps0 = 0.f, ps1 = 0.f;
        #pragma unroll
        for (int nt = 0; nt < 8; nt++) {
            const float p0 = __expf(sacc[nt][0] - mn0);
            const float p1 = __expf(sacc[nt][1] - mn0);
            const float p2 = __expf(sacc[nt][2] - mn1);
            const float p3 = __expf(sacc[nt][3] - mn1);
            ps0 += p0 + p1;
            ps1 += p2 + p3;
            const int cc = nt * 8 + 2 * tid4;
            *(float2*)&Ps[(wq + gid) * PSTR + cc] =
                make_float2(__uint_as_float(f2tf32(p0)), __uint_as_float(f2tf32(p1)));
            *(float2*)&Ps[(wq + gid + 8) * PSTR + cc] =
                make_float2(__uint_as_float(f2tf32(p2)), __uint_as_float(f2tf32(p3)));
        }
        l0r = l0r * corr0 + redsum4(ps0);
        l1r = l1r * corr1 + redsum4(ps1);
        m0r = mn0; m1r = mn1;

        #pragma unroll
        for (int nt = 0; nt < 16; nt++) {
            oacc[nt][0] *= corr0; oacc[nt][1] *= corr0;
            oacc[nt][2] *= corr1; oacc[nt][3] *= corr1;
        }
        __syncwarp();   // Ps rows warp-private: writes visible to lanes

        // --- O += P V : 16 n-tiles x 8 k-frags ---
        #pragma unroll
        for (int kf = 0; kf < 8; kf++) {
            const int kb = kf * 8;
            const uint32_t a0 = __float_as_uint(Ps[(wq + gid) * PSTR + kb + tid4]);
            const uint32_t a1 = __float_as_uint(Ps[(wq + gid + 8) * PSTR + kb + tid4]);
            const uint32_t a2 = __float_as_uint(Ps[(wq + gid) * PSTR + kb + tid4 + 4]);
            const uint32_t a3 = __float_as_uint(Ps[(wq + gid + 8) * PSTR + kb + tid4 + 4]);
            #pragma unroll
            for (int nt = 0; nt < 16; nt++) {
                const uint32_t b0 = __float_as_uint(Vs[(kb + tid4) * KSTRV + nt * 8 + gid]);
                const uint32_t b1 = __float_as_uint(Vs[(kb + tid4 + 4) * KSTRV + nt * 8 + gid]);
                mma_tf32(oacc[nt], a0, a1, a2, a3, b0, b1);
            }
        }

        __syncthreads();   // all K/V reads done before next tile overwrites
        if (kt + 1 < nkt) {
            issue_kv_tile4(k, v, b, g, kt + 1, ksu, vsu, tid);
            CP_COMMIT();
        }
    }

    // Epilogue: normalize and store
    const float rl0 = 1.f / l0r;
    const float rl1 = 1.f / l1r;
    float* ob0 = o + ((size_t)(b * TT + r0) * HH + h) * HD;
    float* ob1 = o + ((size_t)(b * TT + r1) * HH + h) * HD;
    #pragma unroll
    for (int nt = 0; nt < 16; nt++) {
        const int c = nt * 8 + 2 * tid4;
        *(float2*)(ob0 + c) = make_float2(oacc[nt][0] * rl0, oacc[nt][1] * rl0);
        *(float2*)(ob1 + c) = make_float2(oacc[nt][2] * rl1, oacc[nt][3] * rl1);
    }
}

// ---------------------------------------------------------------------------
extern "C" void kernel_launch(void* const* d_in, const int* in_sizes, int n_in,
                              void* d_out, int out_size)
{
    const float* x    = (const float*)d_in[0];
    const float* wq   = (const float*)d_in[1];
    const float* wk   = (const float*)d_in[2];
    const float* wv   = (const float*)d_in[3];
    const float* wo   = (const float*)d_in[4];
    const float* qnw  = (const float*)d_in[5];
    const float* knw  = (const float*)d_in[6];
    const float* fcos = (const float*)d_in[7];
    const float* fsin = (const float*)d_in[8];
    float* out = (float*)d_out;

    float *q, *k, *v, *att;
    cudaGetSymbolAddress((void**)&q,   g_q);
    cudaGetSymbolAddress((void**)&k,   g_k);
    cudaGetSymbolAddress((void**)&v,   g_v);
    cudaGetSymbolAddress((void**)&att, g_att);

    cudaFuncSetAttribute(flash_tc, cudaFuncAttributeMaxDynamicSharedMemorySize, FA4_SMEM);

    // Projections (tensor core tf32 via mma.sync)
    gemm_mma<<<dim3((HH * HD) / GBN, NTOK / GBM), 256>>>(NTOK, HH * HD, DD, x, wq, q);
    gemm_mma<<<dim3((KVH * HD) / GBN, NTOK / GBM), 256>>>(NTOK, KVH * HD, DD, x, wk, k);
    gemm_mma<<<dim3((KVH * HD) / GBN, NTOK / GBM), 256>>>(NTOK, KVH * HD, DD, x, wv, v);

    // Fused RMSNorm+RoPE (q,k) + tf32 round (q,k,v)
    norm_rope_round<<<NTOK, dim3(32, HH + 2 * KVH)>>>(q, k, v, qnw, knw, fcos, fsin);

    // Tensor-core flash attention (2 CTAs/SM, LPT order)
    flash_tc<<<dim3(HH * BB, TT / FTQ), 128, FA4_SMEM>>>(q, k, v, att);

    // Output projection
    gemm_mma<<<dim3(DD / GBN, NTOK / GBM), 256>>>(NTOK, DD, HH * HD, att, wo, out);
}

// round 12
// speedup vs baseline: 1.0430x; 1.0324x over previous
#include <cuda_runtime.h>
#include <cuda_bf16.h>
#include <math.h>
#include <cstdint>

// Problem constants
#define BB 2
#define TT 2048
#define DD 2048
#define HH 16
#define KVH 4
#define HD 128
#define REP (HH / KVH)
#define NTOK (BB * TT)   // 4096

// Scratch (device globals — no allocation allowed)
__device__ float g_q[(size_t)NTOK * HH * HD];    // 32 MB
__device__ float g_k[(size_t)NTOK * KVH * HD];   // 8 MB
__device__ float g_v[(size_t)NTOK * KVH * HD];   // 8 MB
__device__ float g_att[(size_t)NTOK * HH * HD];  // 32 MB

__device__ __forceinline__ uint32_t f2tf32(float f) {
    uint32_t r;
    asm("cvt.rna.tf32.f32 %0, %1;" : "=r"(r) : "f"(f));
    return r;
}

__device__ __forceinline__ uint32_t smem_u32(const void* p) {
    uint32_t a;
    asm("{ .reg .u64 t; cvta.to.shared.u64 t, %1; cvt.u32.u64 %0, t; }"
        : "=r"(a) : "l"(p));
    return a;
}

__device__ __forceinline__ void mma_tf32(float c[4],
    uint32_t a0, uint32_t a1, uint32_t a2, uint32_t a3,
    uint32_t b0, uint32_t b1)
{
    asm volatile(
        "mma.sync.aligned.m16n8k8.row.col.f32.tf32.tf32.f32 "
        "{%0,%1,%2,%3}, {%4,%5,%6,%7}, {%8,%9}, {%0,%1,%2,%3};"
        : "+f"(c[0]), "+f"(c[1]), "+f"(c[2]), "+f"(c[3])
        : "r"(a0), "r"(a1), "r"(a2), "r"(a3), "r"(b0), "r"(b1));
}

__device__ __forceinline__ void cpa16(uint32_t dst, const float* src) {
    asm volatile("cp.async.cg.shared.global [%0], [%1], 16;"
                 :: "r"(dst), "l"(src));
}
#define CP_COMMIT() asm volatile("cp.async.commit_group;" ::: "memory")
#define CP_WAIT(n)  asm volatile("cp.async.wait_group %0;" :: "n"(n) : "memory")

// ===========================================================================
// tf32 mma.sync GEMM core (device function; two kernel wrappers below)
// ===========================================================================
#define GBM 128
#define GBN 128
#define GBK 16
#define ASTR (GBK + 4)
#define BSTR (GBN + 8)

__device__ __forceinline__ void gemm_core(
    int M, int N, int K,
    const float* __restrict__ A, const float* __restrict__ B,
    float* __restrict__ C, int m0, int n0)
{
    __shared__ float As[2][GBM][ASTR];
    __shared__ float Bs[2][GBK][BSTR];

    const int tid  = threadIdx.x;
    const int wid  = tid >> 5;
    const int lane = tid & 31;
    const int gid  = lane >> 2;
    const int tid4 = lane & 3;

    const int warp_m = (wid & 1) * 64;
    const int warp_n = (wid >> 1) * 32;

    const int ar  = tid >> 2;
    const int ac4 = tid & 3;
    const int bk  = tid >> 5;
    const int bn4 = tid & 31;

    const float* aptr = A + (size_t)(m0 + ar) * K + ac4 * 4;
    const float* bptr = B + (size_t)bk * N + n0 + bn4 * 4;
    const size_t aoff2 = (size_t)64 * K;
    const size_t boff2 = (size_t)8 * N;

    float acc[4][4][4];
    #pragma unroll
    for (int i = 0; i < 4; i++)
        #pragma unroll
        for (int j = 0; j < 4; j++)
            #pragma unroll
            for (int r = 0; r < 4; r++) acc[i][j][r] = 0.f;

    const int nch = K / GBK;

    float4 pa0 = *(const float4*)(aptr);
    float4 pa1 = *(const float4*)(aptr + aoff2);
    float4 pb0 = *(const float4*)(bptr);
    float4 pb1 = *(const float4*)(bptr + boff2);

    {
        uint32_t t[4];
        t[0]=f2tf32(pa0.x); t[1]=f2tf32(pa0.y); t[2]=f2tf32(pa0.z); t[3]=f2tf32(pa0.w);
        *(uint4*)&As[0][ar][ac4 * 4] = *(uint4*)t;
        t[0]=f2tf32(pa1.x); t[1]=f2tf32(pa1.y); t[2]=f2tf32(pa1.z); t[3]=f2tf32(pa1.w);
        *(uint4*)&As[0][ar + 64][ac4 * 4] = *(uint4*)t;
        t[0]=f2tf32(pb0.x); t[1]=f2tf32(pb0.y); t[2]=f2tf32(pb0.z); t[3]=f2tf32(pb0.w);
        *(uint4*)&Bs[0][bk][bn4 * 4] = *(uint4*)t;
        t[0]=f2tf32(pb1.x); t[1]=f2tf32(pb1.y); t[2]=f2tf32(pb1.z); t[3]=f2tf32(pb1.w);
        *(uint4*)&Bs[0][bk + 8][bn4 * 4] = *(uint4*)t;
    }
    __syncthreads();

    for (int ch = 0; ch < nch; ch++) {
        const int buf = ch & 1;
        const int nxt = ch + 1;

        if (nxt < nch) {
            const float* ap = aptr + (size_t)nxt * GBK;
            const float* bp = bptr + (size_t)nxt * GBK * N;
            pa0 = *(const float4*)(ap);
            pa1 = *(const float4*)(ap + aoff2);
            pb0 = *(const float4*)(bp);
            pb1 = *(const float4*)(bp + boff2);
        }

        #pragma unroll
        for (int kk = 0; kk < 2; kk++) {
            const int kb = kk * 8;
            uint32_t af[4][4], bf[4][2];
            #pragma unroll
            for (int mi = 0; mi < 4; mi++) {
                const int r = warp_m + mi * 16 + gid;
                af[mi][0] = __float_as_uint(As[buf][r    ][kb + tid4]);
                af[mi][1] = __float_as_uint(As[buf][r + 8][kb + tid4]);
                af[mi][2] = __float_as_uint(As[buf][r    ][kb + tid4 + 4]);
                af[mi][3] = __float_as_uint(As[buf][r + 8][kb + tid4 + 4]);
            }
            #pragma unroll
            for (int ni = 0; ni < 4; ni++) {
                const int c = warp_n + ni * 8 + gid;
                bf[ni][0] = __float_as_uint(Bs[buf][kb + tid4    ][c]);
                bf[ni][1] = __float_as_uint(Bs[buf][kb + tid4 + 4][c]);
            }
            #pragma unroll
            for (int mi = 0; mi < 4; mi++)
                #pragma unroll
                for (int ni = 0; ni < 4; ni++)
                    mma_tf32(acc[mi][ni], af[mi][0], af[mi][1], af[mi][2], af[mi][3],
                             bf[ni][0], bf[ni][1]);
        }

        if (nxt < nch) {
            const int nb = nxt & 1;
            uint32_t t[4];
            t[0]=f2tf32(pa0.x); t[1]=f2tf32(pa0.y); t[2]=f2tf32(pa0.z); t[3]=f2tf32(pa0.w);
            *(uint4*)&As[nb][ar][ac4 * 4] = *(uint4*)t;
            t[0]=f2tf32(pa1.x); t[1]=f2tf32(pa1.y); t[2]=f2tf32(pa1.z); t[3]=f2tf32(pa1.w);
            *(uint4*)&As[nb][ar + 64][ac4 * 4] = *(uint4*)t;
            t[0]=f2tf32(pb0.x); t[1]=f2tf32(pb0.y); t[2]=f2tf32(pb0.z); t[3]=f2tf32(pb0.w);
            *(uint4*)&Bs[nb][bk][bn4 * 4] = *(uint4*)t;
            t[0]=f2tf32(pb1.x); t[1]=f2tf32(pb1.y); t[2]=f2tf32(pb1.z); t[3]=f2tf32(pb1.w);
            *(uint4*)&Bs[nb][bk + 8][bn4 * 4] = *(uint4*)t;
        }
        __syncthreads();
    }

    #pragma unroll
    for (int mi = 0; mi < 4; mi++) {
        const int r = m0 + warp_m + mi * 16 + gid;
        #pragma unroll
        for (int ni = 0; ni < 4; ni++) {
            const int c = n0 + warp_n + ni * 8 + tid4 * 2;
            *(float2*)(C + (size_t)r * N + c) =
                make_float2(acc[mi][ni][0], acc[mi][ni][1]);
            *(float2*)(C + (size_t)(r + 8) * N + c) =
                make_float2(acc[mi][ni][2], acc[mi][ni][3]);
        }
    }
}

__global__ __launch_bounds__(256) void gemm_mma(
    int M, int N, int K,
    const float* __restrict__ A, const float* __restrict__ B,
    float* __restrict__ C)
{
    gemm_core(M, N, K, A, B, C, blockIdx.y * GBM, blockIdx.x * GBN);
}

// Fused K+V projection: blockIdx.x 0-3 -> (wk, k), 4-7 -> (wv, v). N=512 each.
__global__ __launch_bounds__(256) void gemm_kv(
    int M, int K,
    const float* __restrict__ A,
    const float* __restrict__ Bk, const float* __restrict__ Bv,
    float* __restrict__ Ck, float* __restrict__ Cv)
{
    const int nb = (int)blockIdx.x;
    const int NN = KVH * HD;  // 512
    if (nb < NN / GBN) {
        gemm_core(M, NN, K, A, Bk, Ck, blockIdx.y * GBM, nb * GBN);
    } else {
        gemm_core(M, NN, K, A, Bv, Cv, blockIdx.y * GBM, (nb - NN / GBN) * GBN);
    }
}

// ---------------------------------------------------------------------------
// Fused RMSNorm+RoPE (q,k) + tf32 pre-round (q,k,v) — ONE launch. (unchanged)
// ---------------------------------------------------------------------------
__global__ void norm_rope_round(float* __restrict__ q, float* __restrict__ k,
                                float* __restrict__ vv,
                                const float* __restrict__ qw,
                                const float* __restrict__ kw,
                                const float* __restrict__ fc,
                                const float* __restrict__ fs)
{
    const int token = blockIdx.x;
    const int t = token & (TT - 1);
    const int y = threadIdx.y;
    const int lane = threadIdx.x;

    if (y >= HH + KVH) {
        const int head = y - HH - KVH;
        float* base = vv + ((size_t)token * KVH + head) * HD;
        float4 val = *(float4*)(base + lane * 4);
        uint32_t r0 = f2tf32(val.x), r1 = f2tf32(val.y),
                 r2 = f2tf32(val.z), r3 = f2tf32(val.w);
        *(uint4*)(base + lane * 4) = make_uint4(r0, r1, r2, r3);
        return;
    }

    const bool isq = (y < HH);
    const int head = isq ? y : (y - HH);
    const int heads = isq ? HH : KVH;
    float* u = isq ? q : k;
    const float* w = isq ? qw : kw;

    float* base = u + ((size_t)token * heads + head) * HD;
    float4 v = *(float4*)(base + lane * 4);

    float ss = v.x * v.x + v.y * v.y + v.z * v.z + v.w * v.w;
    #pragma unroll
    for (int o = 16; o > 0; o >>= 1) ss += __shfl_xor_sync(0xFFFFFFFFu, ss, o);
    const float r = rsqrtf(ss * (1.f / HD) + 1e-6f);

    const float4 wv = *(const float4*)(w + lane * 4);
    const int p = lane * 2;
    const float c0 = fc[t * (HD / 2) + p],     s0 = fs[t * (HD / 2) + p];
    const float c1 = fc[t * (HD / 2) + p + 1], s1 = fs[t * (HD / 2) + p + 1];

    const float e0 = v.x * r * wv.x, o0 = v.y * r * wv.y;
    const float e1 = v.z * r * wv.z, o1 = v.w * r * wv.w;

    uint32_t r0 = f2tf32(e0 * c0 - o0 * s0);
    uint32_t r1 = f2tf32(e0 * s0 + o0 * c0);
    uint32_t r2 = f2tf32(e1 * c1 - o1 * s1);
    uint32_t r3 = f2tf32(e1 * s1 + o1 * c1);
    *(uint4*)(base + lane * 4) = make_uint4(r0, r1, r2, r3);
}

// ===========================================================================
// Tensor-core causal flash attention v4 (IDENTICAL to R10 — profiling target).
// TQ=64 (4 warps x m16), TK=64, 128 threads/CTA, single-buffered K/V.
// smem: Ks[64][132] + Vs[64][136] + Ps[64][68] = 86016 B -> 2 CTAs/SM.
// ===========================================================================
#define FTQ 64
#define FTK 64
#define KSTRK 132
#define KSTRV 136
#define PSTR 68
#define FA4_SMEM ((FTK * KSTRK + FTK * KSTRV + FTQ * PSTR) * (int)sizeof(float))

__device__ __forceinline__ float redmax4(float x) {
    x = fmaxf(x, __shfl_xor_sync(0xFFFFFFFFu, x, 1));
    x = fmaxf(x, __shfl_xor_sync(0xFFFFFFFFu, x, 2));
    return x;
}
__device__ __forceinline__ float redsum4(float x) {
    x += __shfl_xor_sync(0xFFFFFFFFu, x, 1);
    x += __shfl_xor_sync(0xFFFFFFFFu, x, 2);
    return x;
}

__device__ __forceinline__ void issue_kv_tile4(
    const float* __restrict__ kp, const float* __restrict__ vp,
    int b, int g, int kt, uint32_t ksu, uint32_t vsu, int tid)
{
    const int t0 = b * TT + kt * FTK;
    #pragma unroll
    for (int it = 0; it < 16; it++) {
        const int i = tid + it * 128;
        const int r = i >> 5, c4 = i & 31;
        const size_t go = ((size_t)(t0 + r) * KVH + g) * HD + c4 * 4;
        cpa16(ksu + (uint32_t)(r * KSTRK + c4 * 4) * 4u, kp + go);
        cpa16(vsu + (uint32_t)(r * KSTRV + c4 * 4) * 4u, vp + go);
    }
}

__global__ __launch_bounds__(128) void flash_tc(
    const float* __restrict__ q, const float* __restrict__ k,
    const float* __restrict__ v, float* __restrict__ o)
{
    extern __shared__ float sm[];
    float* Ks = sm;                       // [64][132]
    float* Vs = Ks + FTK * KSTRK;         // [64][136]
    float* Ps = Vs + FTK * KSTRV;         // [64][68]
    const uint32_t ksu = smem_u32(Ks);
    const uint32_t vsu = smem_u32(Vs);

    const int qt = (TT / FTQ - 1) - blockIdx.y;
    const int hb = blockIdx.x;
    const int h  = hb % HH;
    const int b  = hb / HH;
    const int g  = h / REP;
    const int tid  = threadIdx.x;
    const int wid  = tid >> 5;
    const int lane = tid & 31;
    const int gid  = lane >> 2;
    const int tid4 = lane & 3;
    const int q0 = qt * FTQ;
    const int wq = wid * 16;

    const int sstr = (wid < 2) ? KSTRK : KSTRV;
    float* Sg = (wid < 2) ? (Ks + wq * KSTRK) : (Vs + (wq - 32) * KSTRV);
    #pragma unroll
    for (int it = 0; it < 16; it++) {
        const int i = lane + it * 32;
        const int r = i >> 5, c4 = i & 31;
        const float4 qv = *(const float4*)(
            q + ((size_t)(b * TT + q0 + wq + r) * HH + h) * HD + c4 * 4);
        *(float4*)&Sg[r * sstr + c4 * 4] = qv;
    }
    __syncwarp();
    uint32_t qf[16][4];
    #pragma unroll
    for (int kf = 0; kf < 16; kf++) {
        const int kb = kf * 8;
        qf[kf][0] = __float_as_uint(Sg[gid * sstr + kb + tid4]);
        qf[kf][1] = __float_as_uint(Sg[(gid + 8) * sstr + kb + tid4]);
        qf[kf][2] = __float_as_uint(Sg[gid * sstr + kb + tid4 + 4]);
        qf[kf][3] = __float_as_uint(Sg[(gid + 8) * sstr + kb + tid4 + 4]);
    }
    __syncthreads();

    const int nkt = qt + 1;

    issue_kv_tile4(k, v, b, g, 0, ksu, vsu, tid);
    CP_COMMIT();

    float oacc[16][4];
    #pragma unroll
    for (int i = 0; i < 16; i++)
        #pragma unroll
        for (int j = 0; j < 4; j++) oacc[i][j] = 0.f;
    float m0r = -1e30f, m1r = -1e30f, l0r = 0.f, l1r = 0.f;

    const float scale = 0.08838834764831845f;
    const int r0 = q0 + wq + gid;
    const int r1 = r0 + 8;

    for (int kt = 0; kt < nkt; kt++) {
        CP_WAIT(0);
        __syncthreads();

        float sacc[8][4];
        #pragma unroll
        for (int nt = 0; nt < 8; nt++)
            #pragma unroll
            for (int j = 0; j < 4; j++) sacc[nt][j] = 0.f;
        #pragma unroll
        for (int kf = 0; kf < 16; kf++) {
            const int kb = kf * 8;
            #pragma unroll
            for (int nt = 0; nt < 8; nt++) {
                const uint32_t b0 = __float_as_uint(Ks[(nt * 8 + gid) * KSTRK + kb + tid4]);
                const uint32_t b1 = __float_as_uint(Ks[(nt * 8 + gid) * KSTRK + kb + tid4 + 4]);
                mma_tf32(sacc[nt], qf[kf][0], qf[kf][1], qf[kf][2], qf[kf][3], b0, b1);
            }
        }

        const int k0 = kt * FTK;
        float mn0 = m0r, mn1 = m1r;
        if (kt == nkt - 1) {
            #pragma unroll
            for (int nt = 0; nt < 8; nt++) {
                const int c = k0 + nt * 8 + tid4 * 2;
                float s0 = sacc[nt][0] * scale, s1 = sacc[nt][1] * scale;
                float s2 = sacc[nt][2] * scale, s3 = sacc[nt][3] * scale;
                if (c     > r0) s0 = -1e30f;
                if (c + 1 > r0) s1 = -1e30f;
                if (c     > r1) s2 = -1e30f;
                if (c + 1 > r1) s3 = -1e30f;
                sacc[nt][0] = s0; sacc[nt][1] = s1; sacc[nt][2] = s2; sacc[nt][3] = s3;
                mn0 = fmaxf(mn0, fmaxf(s0, s1));
                mn1 = fmaxf(mn1, fmaxf(s2, s3));
            }
        } else {
            #pragma unroll
            for (int nt = 0; nt < 8; nt++) {
                const float s0 = sacc[nt][0] * scale, s1 = sacc[nt][1] * scale;
                const float s2 = sacc[nt][2] * scale, s3 = sacc[nt][3] * scale;
                sacc[nt][0] = s0; sacc[nt][1] = s1; sacc[nt][2] = s2; sacc[nt][3] = s3;
                mn0 = fmaxf(mn0, fmaxf(s0, s1));
                mn1 = fmaxf(mn1, fmaxf(s2, s3));
            }
        }
        mn0 = redmax4(mn0);
        mn1 = redmax4(mn1);

        const float corr0 = __expf(m0r - mn0);
        const float corr1 = __expf(m1r - mn1);
        float ps0 = 0.f, ps1 = 0.f;
        #pragma unroll
        for (int nt = 0; nt < 8; nt++) {
            const float p0 = __expf(sacc[nt][0] - mn0);
            const float p1 = __expf(sacc[nt][1] - mn0);
            const float p2 = __expf(sacc[nt][2] - mn1);
            const float p3 = __expf(sacc[nt][3] - mn1);
            ps0 += p0 + p1;
            ps1 += p2 + p3;
            const int cc = nt * 8 + 2 * tid4;
            *(float2*)&Ps[(wq + gid) * PSTR + cc] =
                make_float2(__uint_as_float(f2tf32(p0)), __uint_as_float(f2tf32(p1)));
            *(float2*)&Ps[(wq + gid + 8) * PSTR + cc] =
                make_float2(__uint_as_float(f2tf32(p2)), __uint_as_float(f2tf32(p3)));
        }
        l0r = l0r * corr0 + redsum4(ps0);
        l1r = l1r * corr1 + redsum4(ps1);
        m0r = mn0; m1r = mn1;

        #pragma unroll
        for (int nt = 0; nt < 16; nt++) {
            oacc[nt][0] *= corr0; oacc[nt][1] *= corr0;
            oacc[nt][2] *= corr1; oacc[nt][3] *= corr1;
        }
        __syncwarp();

        #pragma unroll
        for (int kf = 0; kf < 8; kf++) {
            const int kb = kf * 8;
            const uint32_t a0 = __float_as_uint(Ps[(wq + gid) * PSTR + kb + tid4]);
            const uint32_t a1 = __float_as_uint(Ps[(wq + gid + 8) * PSTR + kb + tid4]);
            const uint32_t a2 = __float_as_uint(Ps[(wq + gid) * PSTR + kb + tid4 + 4]);
            const uint32_t a3 = __float_as_uint(Ps[(wq + gid + 8) * PSTR + kb + tid4 + 4]);
            #pragma unroll
            for (int nt = 0; nt < 16; nt++) {
                const uint32_t b0 = __float_as_uint(Vs[(kb + tid4) * KSTRV + nt * 8 + gid]);
                const uint32_t b1 = __float_as_uint(Vs[(kb + tid4 + 4) * KSTRV + nt * 8 + gid]);
                mma_tf32(oacc[nt], a0, a1, a2, a3, b0, b1);
            }
        }

        __syncthreads();
        if (kt + 1 < nkt) {
            issue_kv_tile4(k, v, b, g, kt + 1, ksu, vsu, tid);
            CP_COMMIT();
        }
    }

    const float rl0 = 1.f / l0r;
    const float rl1 = 1.f / l1r;
    float* ob0 = o + ((size_t)(b * TT + r0) * HH + h) * HD;
    float* ob1 = o + ((size_t)(b * TT + r1) * HH + h) * HD;
    #pragma unroll
    for (int nt = 0; nt < 16; nt++) {
        const int c = nt * 8 + 2 * tid4;
        *(float2*)(ob0 + c) = make_float2(oacc[nt][0] * rl0, oacc[nt][1] * rl0);
        *(float2*)(ob1 + c) = make_float2(oacc[nt][2] * rl1, oacc[nt][3] * rl1);
    }
}

// ---------------------------------------------------------------------------
extern "C" void kernel_launch(void* const* d_in, const int* in_sizes, int n_in,
                              void* d_out, int out_size)
{
    const float* x    = (const float*)d_in[0];
    const float* wq   = (const float*)d_in[1];
    const float* wk   = (const float*)d_in[2];
    const float* wv   = (const float*)d_in[3];
    const float* wo   = (const float*)d_in[4];
    const float* qnw  = (const float*)d_in[5];
    const float* knw  = (const float*)d_in[6];
    const float* fcos = (const float*)d_in[7];
    const float* fsin = (const float*)d_in[8];
    float* out = (float*)d_out;

    float *q, *k, *v, *att;
    cudaGetSymbolAddress((void**)&q,   g_q);
    cudaGetSymbolAddress((void**)&k,   g_k);
    cudaGetSymbolAddress((void**)&v,   g_v);
    cudaGetSymbolAddress((void**)&att, g_att);

    cudaFuncSetAttribute(flash_tc, cudaFuncAttributeMaxDynamicSharedMemorySize, FA4_SMEM);

    // [0] Q projection
    gemm_mma<<<dim3((HH * HD) / GBN, NTOK / GBM), 256>>>(NTOK, HH * HD, DD, x, wq, q);
    // [1] K+V projections fused (one launch)
    gemm_kv<<<dim3(2 * (KVH * HD) / GBN, NTOK / GBM), 256>>>(NTOK, DD, x, wk, wv, k, v);
    // [2] RMSNorm+RoPE+round
    norm_rope_round<<<NTOK, dim3(32, HH + 2 * KVH)>>>(q, k, v, qnw, knw, fcos, fsin);
    // [3] flash attention  <- ncu capture slot (overall launch index 5)
    flash_tc<<<dim3(HH * BB, TT / FTQ), 128, FA4_SMEM>>>(q, k, v, att);
    // [4] output projection
    gemm_mma<<<dim3(DD / GBN, NTOK / GBM), 256>>>(NTOK, DD, HH * HD, att, wo, out);
}

// round 13
// speedup vs baseline: 1.0950x; 1.0499x over previous
#include <cuda_runtime.h>
#include <cuda_bf16.h>
#include <math.h>
#include <cstdint>

// Problem constants
#define BB 2
#define TT 2048
#define DD 2048
#define HH 16
#define KVH 4
#define HD 128
#define REP (HH / KVH)
#define NTOK (BB * TT)   // 4096

// Scratch (device globals — no allocation allowed)
__device__ float g_q[(size_t)NTOK * HH * HD];    // 32 MB
__device__ float g_k[(size_t)NTOK * KVH * HD];   // 8 MB
__device__ float g_v[(size_t)NTOK * KVH * HD];   // 8 MB
__device__ float g_att[(size_t)NTOK * HH * HD];  // 32 MB
// tf32 pre-rounded operands (raw cp.async feeds mma directly)
__device__ float g_xr[(size_t)NTOK * DD];        // 32 MB
__device__ float g_wqr[(size_t)DD * HH * HD];    // 16 MB
__device__ float g_wkr[(size_t)DD * KVH * HD];   // 4 MB
__device__ float g_wvr[(size_t)DD * KVH * HD];   // 4 MB
__device__ float g_wor[(size_t)HH * HD * DD];    // 16 MB

__device__ __forceinline__ uint32_t f2tf32(float f) {
    uint32_t r;
    asm("cvt.rna.tf32.f32 %0, %1;" : "=r"(r) : "f"(f));
    return r;
}

__device__ __forceinline__ uint32_t smem_u32(const void* p) {
    uint32_t a;
    asm("{ .reg .u64 t; cvta.to.shared.u64 t, %1; cvt.u32.u64 %0, t; }"
        : "=r"(a) : "l"(p));
    return a;
}

__device__ __forceinline__ void mma_tf32(float c[4],
    uint32_t a0, uint32_t a1, uint32_t a2, uint32_t a3,
    uint32_t b0, uint32_t b1)
{
    asm volatile(
        "mma.sync.aligned.m16n8k8.row.col.f32.tf32.tf32.f32 "
        "{%0,%1,%2,%3}, {%4,%5,%6,%7}, {%8,%9}, {%0,%1,%2,%3};"
        : "+f"(c[0]), "+f"(c[1]), "+f"(c[2]), "+f"(c[3])
        : "r"(a0), "r"(a1), "r"(a2), "r"(a3), "r"(b0), "r"(b1));
}

__device__ __forceinline__ void cpa16(uint32_t dst, const float* src) {
    asm volatile("cp.async.cg.shared.global [%0], [%1], 16;"
                 :: "r"(dst), "l"(src));
}
#define CP_COMMIT() asm volatile("cp.async.commit_group;" ::: "memory")
#define CP_WAIT(n)  asm volatile("cp.async.wait_group %0;" :: "n"(n) : "memory")

// ---------------------------------------------------------------------------
// tf32 pre-round kernels (cvt.rna is idempotent: values identical to the
// previous cvt-at-STS scheme)
// ---------------------------------------------------------------------------
__global__ void preround_x(const float* __restrict__ x, float* __restrict__ xr)
{
    const size_t i = (size_t)blockIdx.x * 256 + threadIdx.x;   // float4 index
    const float4 v = ((const float4*)x)[i];
    ((uint4*)xr)[i] = make_uint4(f2tf32(v.x), f2tf32(v.y), f2tf32(v.z), f2tf32(v.w));
}

__global__ void preround_w(const float* __restrict__ wq, const float* __restrict__ wk,
                           const float* __restrict__ wv, const float* __restrict__ wo,
                           float* __restrict__ wqr, float* __restrict__ wkr,
                           float* __restrict__ wvr, float* __restrict__ wor)
{
    const size_t i = (size_t)blockIdx.x * 256 + threadIdx.x;   // float4 index
    const size_t NQ = (size_t)DD * HH * HD / 4;      // 1048576
    const size_t NK = (size_t)DD * KVH * HD / 4;     // 262144
    const float4* src; uint4* dst; size_t off;
    if (i < NQ)                    { src = (const float4*)wq; dst = (uint4*)wqr; off = i; }
    else if (i < NQ + NK)          { src = (const float4*)wk; dst = (uint4*)wkr; off = i - NQ; }
    else if (i < NQ + 2 * NK)      { src = (const float4*)wv; dst = (uint4*)wvr; off = i - NQ - NK; }
    else                           { src = (const float4*)wo; dst = (uint4*)wor; off = i - NQ - 2 * NK; }
    const float4 v = src[off];
    dst[off] = make_uint4(f2tf32(v.x), f2tf32(v.y), f2tf32(v.z), f2tf32(v.w));
}

// ===========================================================================
// tf32 mma.sync GEMM v2 — cp.async double-buffered, 2 CTAs/SM.
// Inputs MUST be tf32-pre-rounded. 128x128x16 tile, 256 threads, ~110 regs.
// ===========================================================================
#define GBM 128
#define GBN 128
#define GBK 16
#define ASTR (GBK + 4)
#define BSTR (GBN + 8)

__device__ __forceinline__ void gemm_core(
    int M, int N, int K,
    const float* __restrict__ A, const float* __restrict__ B,
    float* __restrict__ C, int m0, int n0)
{
    __shared__ float As[2][GBM][ASTR];   // 20480 B
    __shared__ float Bs[2][GBK][BSTR];   // 17408 B

    const int tid  = threadIdx.x;
    const int wid  = tid >> 5;
    const int lane = tid & 31;
    const int gid  = lane >> 2;
    const int tid4 = lane & 3;
    const int warp_m = (wid & 1) * 64;
    const int warp_n = (wid >> 1) * 32;

    const int ar  = tid >> 2;
    const int ac4 = tid & 3;
    const int bk  = tid >> 5;
    const int bn4 = tid & 31;

    const float* aptr = A + (size_t)(m0 + ar) * K + ac4 * 4;
    const float* bptr = B + (size_t)bk * N + n0 + bn4 * 4;

    const uint32_t a_sm = smem_u32(&As[0][ar][ac4 * 4]);
    const uint32_t b_sm = smem_u32(&Bs[0][bk][bn4 * 4]);
    const uint32_t ABUF = GBM * ASTR * 4;
    const uint32_t BBUF = GBK * BSTR * 4;

    float acc[4][4][4];
    #pragma unroll
    for (int i = 0; i < 4; i++)
        #pragma unroll
        for (int j = 0; j < 4; j++)
            #pragma unroll
            for (int r = 0; r < 4; r++) acc[i][j][r] = 0.f;

    const int nch = K / GBK;

    // Preload chunk 0 into buffer 0
    cpa16(a_sm, aptr);
    cpa16(a_sm + 64u * ASTR * 4u, aptr + (size_t)64 * K);
    cpa16(b_sm, bptr);
    cpa16(b_sm + 8u * BSTR * 4u, bptr + (size_t)8 * N);
    CP_COMMIT();

    for (int ch = 0; ch < nch; ch++) {
        const int buf = ch & 1;
        CP_WAIT(0);
        __syncthreads();   // tile ch visible; prev compute on buf^1 done

        if (ch + 1 < nch) {
            const float* ap = aptr + (size_t)(ch + 1) * GBK;
            const float* bp = bptr + (size_t)(ch + 1) * GBK * N;
            const uint32_t ao = (buf ^ 1) ? ABUF : 0u;
            const uint32_t bo = (buf ^ 1) ? BBUF : 0u;
            cpa16(a_sm + ao, ap);
            cpa16(a_sm + ao + 64u * ASTR * 4u, ap + (size_t)64 * K);
            cpa16(b_sm + bo, bp);
            cpa16(b_sm + bo + 8u * BSTR * 4u, bp + (size_t)8 * N);
            CP_COMMIT();
        }

        #pragma unroll
        for (int kk = 0; kk < 2; kk++) {
            const int kb = kk * 8;
            uint32_t af[4][4], bf[4][2];
            #pragma unroll
            for (int mi = 0; mi < 4; mi++) {
                const int r = warp_m + mi * 16 + gid;
                af[mi][0] = __float_as_uint(As[buf][r    ][kb + tid4]);
                af[mi][1] = __float_as_uint(As[buf][r + 8][kb + tid4]);
                af[mi][2] = __float_as_uint(As[buf][r    ][kb + tid4 + 4]);
                af[mi][3] = __float_as_uint(As[buf][r + 8][kb + tid4 + 4]);
            }
            #pragma unroll
            for (int ni = 0; ni < 4; ni++) {
                const int c = warp_n + ni * 8 + gid;
                bf[ni][0] = __float_as_uint(Bs[buf][kb + tid4    ][c]);
                bf[ni][1] = __float_as_uint(Bs[buf][kb + tid4 + 4][c]);
            }
            #pragma unroll
            for (int mi = 0; mi < 4; mi++)
                #pragma unroll
                for (int ni = 0; ni < 4; ni++)
                    mma_tf32(acc[mi][ni], af[mi][0], af[mi][1], af[mi][2], af[mi][3],
                             bf[ni][0], bf[ni][1]);
        }
    }

    #pragma unroll
    for (int mi = 0; mi < 4; mi++) {
        const int r = m0 + warp_m + mi * 16 + gid;
        #pragma unroll
        for (int ni = 0; ni < 4; ni++) {
            const int c = n0 + warp_n + ni * 8 + tid4 * 2;
            *(float2*)(C + (size_t)r * N + c) =
                make_float2(acc[mi][ni][0], acc[mi][ni][1]);
            *(float2*)(C + (size_t)(r + 8) * N + c) =
                make_float2(acc[mi][ni][2], acc[mi][ni][3]);
        }
    }
}

__global__ __launch_bounds__(256, 2) void gemm_mma(
    int M, int N, int K,
    const float* __restrict__ A, const float* __restrict__ B,
    float* __restrict__ C)
{
    gemm_core(M, N, K, A, B, C, blockIdx.y * GBM, blockIdx.x * GBN);
}

// Fused K+V projection: blockIdx.x 0-3 -> (wk, k), 4-7 -> (wv, v). N=512 each.
__global__ __launch_bounds__(256, 2) void gemm_kv(
    int M, int K,
    const float* __restrict__ A,
    const float* __restrict__ Bk, const float* __restrict__ Bv,
    float* __restrict__ Ck, float* __restrict__ Cv)
{
    const int nb = (int)blockIdx.x;
    const int NN = KVH * HD;  // 512
    if (nb < NN / GBN) {
        gemm_core(M, NN, K, A, Bk, Ck, blockIdx.y * GBM, nb * GBN);
    } else {
        gemm_core(M, NN, K, A, Bv, Cv, blockIdx.y * GBM, (nb - NN / GBN) * GBN);
    }
}

// ---------------------------------------------------------------------------
// Fused RMSNorm+RoPE (q,k) + tf32 round (q,k,v) — unchanged
// ---------------------------------------------------------------------------
__global__ void norm_rope_round(float* __restrict__ q, float* __restrict__ k,
                                float* __restrict__ vv,
                                const float* __restrict__ qw,
                                const float* __restrict__ kw,
                                const float* __restrict__ fc,
                                const float* __restrict__ fs)
{
    const int token = blockIdx.x;
    const int t = token & (TT - 1);
    const int y = threadIdx.y;
    const int lane = threadIdx.x;

    if (y >= HH + KVH) {
        const int head = y - HH - KVH;
        float* base = vv + ((size_t)token * KVH + head) * HD;
        float4 val = *(float4*)(base + lane * 4);
        uint32_t r0 = f2tf32(val.x), r1 = f2tf32(val.y),
                 r2 = f2tf32(val.z), r3 = f2tf32(val.w);
        *(uint4*)(base + lane * 4) = make_uint4(r0, r1, r2, r3);
        return;
    }

    const bool isq = (y < HH);
    const int head = isq ? y : (y - HH);
    const int heads = isq ? HH : KVH;
    float* u = isq ? q : k;
    const float* w = isq ? qw : kw;

    float* base = u + ((size_t)token * heads + head) * HD;
    float4 v = *(float4*)(base + lane * 4);

    float ss = v.x * v.x + v.y * v.y + v.z * v.z + v.w * v.w;
    #pragma unroll
    for (int o = 16; o > 0; o >>= 1) ss += __shfl_xor_sync(0xFFFFFFFFu, ss, o);
    const float r = rsqrtf(ss * (1.f / HD) + 1e-6f);

    const float4 wv = *(const float4*)(w + lane * 4);
    const int p = lane * 2;
    const float c0 = fc[t * (HD / 2) + p],     s0 = fs[t * (HD / 2) + p];
    const float c1 = fc[t * (HD / 2) + p + 1], s1 = fs[t * (HD / 2) + p + 1];

    const float e0 = v.x * r * wv.x, o0 = v.y * r * wv.y;
    const float e1 = v.z * r * wv.z, o1 = v.w * r * wv.w;

    uint32_t r0 = f2tf32(e0 * c0 - o0 * s0);
    uint32_t r1 = f2tf32(e0 * s0 + o0 * c0);
    uint32_t r2 = f2tf32(e1 * c1 - o1 * s1);
    uint32_t r3 = f2tf32(e1 * s1 + o1 * c1);
    *(uint4*)(base + lane * 4) = make_uint4(r0, r1, r2, r3);
}

// ===========================================================================
// Tensor-core causal flash attention v4 (unchanged except: epilogue rounds
// O to tf32 so the O-projection gemm can cp.async it raw).
// ===========================================================================
#define FTQ 64
#define FTK 64
#define KSTRK 132
#define KSTRV 136
#define PSTR 68
#define FA4_SMEM ((FTK * KSTRK + FTK * KSTRV + FTQ * PSTR) * (int)sizeof(float))

__device__ __forceinline__ float redmax4(float x) {
    x = fmaxf(x, __shfl_xor_sync(0xFFFFFFFFu, x, 1));
    x = fmaxf(x, __shfl_xor_sync(0xFFFFFFFFu, x, 2));
    return x;
}
__device__ __forceinline__ float redsum4(float x) {
    x += __shfl_xor_sync(0xFFFFFFFFu, x, 1);
    x += __shfl_xor_sync(0xFFFFFFFFu, x, 2);
    return x;
}

__device__ __forceinline__ void issue_kv_tile4(
    const float* __restrict__ kp, const float* __restrict__ vp,
    int b, int g, int kt, uint32_t ksu, uint32_t vsu, int tid)
{
    const int t0 = b * TT + kt * FTK;
    #pragma unroll
    for (int it = 0; it < 16; it++) {
        const int i = tid + it * 128;
        const int r = i >> 5, c4 = i & 31;
        const size_t go = ((size_t)(t0 + r) * KVH + g) * HD + c4 * 4;
        cpa16(ksu + (uint32_t)(r * KSTRK + c4 * 4) * 4u, kp + go);
        cpa16(vsu + (uint32_t)(r * KSTRV + c4 * 4) * 4u, vp + go);
    }
}

__global__ __launch_bounds__(128) void flash_tc(
    const float* __restrict__ q, const float* __restrict__ k,
    const float* __restrict__ v, float* __restrict__ o)
{
    extern __shared__ float sm[];
    float* Ks = sm;
    float* Vs = Ks + FTK * KSTRK;
    float* Ps = Vs + FTK * KSTRV;
    const uint32_t ksu = smem_u32(Ks);
    const uint32_t vsu = smem_u32(Vs);

    const int qt = (TT / FTQ - 1) - blockIdx.y;
    const int hb = blockIdx.x;
    const int h  = hb % HH;
    const int b  = hb / HH;
    const int g  = h / REP;
    const int tid  = threadIdx.x;
    const int wid  = tid >> 5;
    const int lane = tid & 31;
    const int gid  = lane >> 2;
    const int tid4 = lane & 3;
    const int q0 = qt * FTQ;
    const int wq = wid * 16;

    const int sstr = (wid < 2) ? KSTRK : KSTRV;
    float* Sg = (wid < 2) ? (Ks + wq * KSTRK) : (Vs + (wq - 32) * KSTRV);
    #pragma unroll
    for (int it = 0; it < 16; it++) {
        const int i = lane + it * 32;
        const int r = i >> 5, c4 = i & 31;
        const float4 qv = *(const float4*)(
            q + ((size_t)(b * TT + q0 + wq + r) * HH + h) * HD + c4 * 4);
        *(float4*)&Sg[r * sstr + c4 * 4] = qv;
    }
    __syncwarp();
    uint32_t qf[16][4];
    #pragma unroll
    for (int kf = 0; kf < 16; kf++) {
        const int kb = kf * 8;
        qf[kf][0] = __float_as_uint(Sg[gid * sstr + kb + tid4]);
        qf[kf][1] = __float_as_uint(Sg[(gid + 8) * sstr + kb + tid4]);
        qf[kf][2] = __float_as_uint(Sg[gid * sstr + kb + tid4 + 4]);
        qf[kf][3] = __float_as_uint(Sg[(gid + 8) * sstr + kb + tid4 + 4]);
    }
    __syncthreads();

    const int nkt = qt + 1;

    issue_kv_tile4(k, v, b, g, 0, ksu, vsu, tid);
    CP_COMMIT();

    float oacc[16][4];
    #pragma unroll
    for (int i = 0; i < 16; i++)
        #pragma unroll
        for (int j = 0; j < 4; j++) oacc[i][j] = 0.f;
    float m0r = -1e30f, m1r = -1e30f, l0r = 0.f, l1r = 0.f;

    const float scale = 0.08838834764831845f;
    const int r0 = q0 + wq + gid;
    const int r1 = r0 + 8;

    for (int kt = 0; kt < nkt; kt++) {
        CP_WAIT(0);
        __syncthreads();

        float sacc[8][4];
        #pragma unroll
        for (int nt = 0; nt < 8; nt++)
            #pragma unroll
            for (int j = 0; j < 4; j++) sacc[nt][j] = 0.f;
        #pragma unroll
        for (int kf = 0; kf < 16; kf++) {
            const int kb = kf * 8;
            #pragma unroll
            for (int nt = 0; nt < 8; nt++) {
                const uint32_t b0 = __float_as_uint(Ks[(nt * 8 + gid) * KSTRK + kb + tid4]);
                const uint32_t b1 = __float_as_uint(Ks[(nt * 8 + gid) * KSTRK + kb + tid4 + 4]);
                mma_tf32(sacc[nt], qf[kf][0], qf[kf][1], qf[kf][2], qf[kf][3], b0, b1);
            }
        }

        const int k0 = kt * FTK;
        float mn0 = m0r, mn1 = m1r;
        if (kt == nkt - 1) {
            #pragma unroll
            for (int nt = 0; nt < 8; nt++) {
                const int c = k0 + nt * 8 + tid4 * 2;
                float s0 = sacc[nt][0] * scale, s1 = sacc[nt][1] * scale;
                float s2 = sacc[nt][2] * scale, s3 = sacc[nt][3] * scale;
                if (c     > r0) s0 = -1e30f;
                if (c + 1 > r0) s1 = -1e30f;
                if (c     > r1) s2 = -1e30f;
                if (c + 1 > r1) s3 = -1e30f;
                sacc[nt][0] = s0; sacc[nt][1] = s1; sacc[nt][2] = s2; sacc[nt][3] = s3;
                mn0 = fmaxf(mn0, fmaxf(s0, s1));
                mn1 = fmaxf(mn1, fmaxf(s2, s3));
            }
        } else {
            #pragma unroll
            for (int nt = 0; nt < 8; nt++) {
                const float s0 = sacc[nt][0] * scale, s1 = sacc[nt][1] * scale;
                const float s2 = sacc[nt][2] * scale, s3 = sacc[nt][3] * scale;
                sacc[nt][0] = s0; sacc[nt][1] = s1; sacc[nt][2] = s2; sacc[nt][3] = s3;
                mn0 = fmaxf(mn0, fmaxf(s0, s1));
                mn1 = fmaxf(mn1, fmaxf(s2, s3));
            }
        }
        mn0 = redmax4(mn0);
        mn1 = redmax4(mn1);

        const float corr0 = __expf(m0r - mn0);
        const float corr1 = __expf(m1r - mn1);
        float ps0 = 0.f, ps1 = 0.f;
        #pragma unroll
        for (int nt = 0; nt < 8; nt++) {
            const float p0 = __expf(sacc[nt][0] - mn0);
            const float p1 = __expf(sacc[nt][1] - mn0);
            const float p2 = __expf(sacc[nt][2] - mn1);
            const float p3 = __expf(sacc[nt][3] - mn1);
            ps0 += p0 + p1;
            ps1 += p2 + p3;
            const int cc = nt * 8 + 2 * tid4;
            *(float2*)&Ps[(wq + gid) * PSTR + cc] =
                make_float2(__uint_as_float(f2tf32(p0)), __uint_as_float(f2tf32(p1)));
            *(float2*)&Ps[(wq + gid + 8) * PSTR + cc] =
                make_float2(__uint_as_float(f2tf32(p2)), __uint_as_float(f2tf32(p3)));
        }
        l0r = l0r * corr0 + redsum4(ps0);
        l1r = l1r * corr1 + redsum4(ps1);
        m0r = mn0; m1r = mn1;

        #pragma unroll
        for (int nt = 0; nt < 16; nt++) {
            oacc[nt][0] *= corr0; oacc[nt][1] *= corr0;
            oacc[nt][2] *= corr1; oacc[nt][3] *= corr1;
        }
        __syncwarp();

        #pragma unroll
        for (int kf = 0; kf < 8; kf++) {
            const int kb = kf * 8;
            const uint32_t a0 = __float_as_uint(Ps[(wq + gid) * PSTR + kb + tid4]);
            const uint32_t a1 = __float_as_uint(Ps[(wq + gid + 8) * PSTR + kb + tid4]);
            const uint32_t a2 = __float_as_uint(Ps[(wq + gid) * PSTR + kb + tid4 + 4]);
            const uint32_t a3 = __float_as_uint(Ps[(wq + gid + 8) * PSTR + kb + tid4 + 4]);
            #pragma unroll
            for (int nt = 0; nt < 16; nt++) {
                const uint32_t b0 = __float_as_uint(Vs[(kb + tid4) * KSTRV + nt * 8 + gid]);
                const uint32_t b1 = __float_as_uint(Vs[(kb + tid4 + 4) * KSTRV + nt * 8 + gid]);
                mma_tf32(oacc[nt], a0, a1, a2, a3, b0, b1);
            }
        }

        __syncthreads();
        if (kt + 1 < nkt) {
            issue_kv_tile4(k, v, b, g, kt + 1, ksu, vsu, tid);
            CP_COMMIT();
        }
    }

    // Epilogue: normalize, round to tf32 (O-proj consumes raw), store
    const float rl0 = 1.f / l0r;
    const float rl1 = 1.f / l1r;
    float* ob0 = o + ((size_t)(b * TT + r0) * HH + h) * HD;
    float* ob1 = o + ((size_t)(b * TT + r1) * HH + h) * HD;
    #pragma unroll
    for (int nt = 0; nt < 16; nt++) {
        const int c = nt * 8 + 2 * tid4;
        *(uint2*)(ob0 + c) = make_uint2(f2tf32(oacc[nt][0] * rl0), f2tf32(oacc[nt][1] * rl0));
        *(uint2*)(ob1 + c) = make_uint2(f2tf32(oacc[nt][2] * rl1), f2tf32(oacc[nt][3] * rl1));
    }
}

// ---------------------------------------------------------------------------
extern "C" void kernel_launch(void* const* d_in, const int* in_sizes, int n_in,
                              void* d_out, int out_size)
{
    const float* x    = (const float*)d_in[0];
    const float* wq   = (const float*)d_in[1];
    const float* wk   = (const float*)d_in[2];
    const float* wv   = (const float*)d_in[3];
    const float* wo   = (const float*)d_in[4];
    const float* qnw  = (const float*)d_in[5];
    const float* knw  = (const float*)d_in[6];
    const float* fcos = (const float*)d_in[7];
    const float* fsin = (const float*)d_in[8];
    float* out = (float*)d_out;

    float *q, *k, *v, *att, *xr, *wqr, *wkr, *wvr, *wor;
    cudaGetSymbolAddress((void**)&q,   g_q);
    cudaGetSymbolAddress((void**)&k,   g_k);
    cudaGetSymbolAddress((void**)&v,   g_v);
    cudaGetSymbolAddress((void**)&att, g_att);
    cudaGetSymbolAddress((void**)&xr,  g_xr);
    cudaGetSymbolAddress((void**)&wqr, g_wqr);
    cudaGetSymbolAddress((void**)&wkr, g_wkr);
    cudaGetSymbolAddress((void**)&wvr, g_wvr);
    cudaGetSymbolAddress((void**)&wor, g_wor);

    cudaFuncSetAttribute(flash_tc, cudaFuncAttributeMaxDynamicSharedMemorySize, FA4_SMEM);

    // [0] round x                       (2,097,152 float4 / 256)
    preround_x<<<(NTOK * DD / 4) / 256, 256>>>(x, xr);
    // [1] round weights                 (2,621,440 float4 / 256)
    preround_w<<<((size_t)DD * (HH + 2 * KVH) * HD + (size_t)HH * HD * DD) / 4 / 256, 256>>>(
        wq, wk, wv, wo, wqr, wkr, wvr, wor);
    // [2] K+V projections fused
    gemm_kv<<<dim3(2 * (KVH * HD) / GBN, NTOK / GBM), 256>>>(NTOK, DD, xr, wkr, wvr, k, v);
    // [3] Q projection   <- ncu capture slot (overall launch index 5)
    gemm_mma<<<dim3((HH * HD) / GBN, NTOK / GBM), 256>>>(NTOK, HH * HD, DD, xr, wqr, q);
    // [4] RMSNorm+RoPE+round
    norm_rope_round<<<NTOK, dim3(32, HH + 2 * KVH)>>>(q, k, v, qnw, knw, fcos, fsin);
    // [5] flash attention (output rounded to tf32)
    flash_tc<<<dim3(HH * BB, TT / FTQ), 128, FA4_SMEM>>>(q, k, v, att);
    // [6] output projection
    gemm_mma<<<dim3(DD / GBN, NTOK / GBM), 256>>>(NTOK, DD, HH * HD, att, wor, out);
}

// round 14
// speedup vs baseline: 1.8628x; 1.7011x over previous
#include <cuda_runtime.h>
#include <cuda_fp16.h>
#include <math.h>
#include <cstdint>

// Problem constants
#define BB 2
#define TT 2048
#define DD 2048
#define HH 16
#define KVH 4
#define HD 128
#define REP (HH / KVH)
#define NTOK (BB * TT)   // 4096

// fp32 scratch
__device__ float g_q[(size_t)NTOK * HH * HD];    // 32 MB
__device__ float g_k[(size_t)NTOK * KVH * HD];   // 8 MB
__device__ float g_v[(size_t)NTOK * KVH * HD];   // 8 MB
// fp16 operands
__device__ __half g_xh[(size_t)NTOK * DD];                 // 16 MB
__device__ __half g_wqh[(size_t)HH * HD * DD];             // 8 MB  (transposed [N][K])
__device__ __half g_wkh[(size_t)KVH * HD * DD];            // 2 MB
__device__ __half g_wvh[(size_t)KVH * HD * DD];            // 2 MB
__device__ __half g_woh[(size_t)DD * HH * HD];             // 8 MB  (transposed [N][K])
__device__ __half g_qh[(size_t)NTOK * HH * HD];            // 16 MB
__device__ __half g_kh[(size_t)NTOK * KVH * HD];           // 4 MB
__device__ __half g_vt[(size_t)BB * KVH * HD * TT];        // 4 MB  (V^T: [b*g][d][t])
__device__ __half g_atth[(size_t)NTOK * HH * HD];          // 16 MB

__device__ __forceinline__ uint32_t smem_u32(const void* p) {
    uint32_t a;
    asm("{ .reg .u64 t; cvta.to.shared.u64 t, %1; cvt.u32.u64 %0, t; }"
        : "=r"(a) : "l"(p));
    return a;
}

__device__ __forceinline__ uint32_t h2pack(float a, float b) {
    __half2 h = __floats2half2_rn(a, b);
    return *(uint32_t*)&h;
}

__device__ __forceinline__ void mma_f16(float c[4],
    uint32_t a0, uint32_t a1, uint32_t a2, uint32_t a3,
    uint32_t b0, uint32_t b1)
{
    asm volatile(
        "mma.sync.aligned.m16n8k16.row.col.f32.f16.f16.f32 "
        "{%0,%1,%2,%3}, {%4,%5,%6,%7}, {%8,%9}, {%0,%1,%2,%3};"
        : "+f"(c[0]), "+f"(c[1]), "+f"(c[2]), "+f"(c[3])
        : "r"(a0), "r"(a1), "r"(a2), "r"(a3), "r"(b0), "r"(b1));
}

__device__ __forceinline__ void cpa16(uint32_t dst, const void* src) {
    asm volatile("cp.async.cg.shared.global [%0], [%1], 16;"
                 :: "r"(dst), "l"(src));
}
#define CP_COMMIT() asm volatile("cp.async.commit_group;" ::: "memory")
#define CP_WAIT(n)  asm volatile("cp.async.wait_group %0;" :: "n"(n) : "memory")

// ---------------------------------------------------------------------------
// x -> fp16 (same layout)
// ---------------------------------------------------------------------------
__global__ void preround_xh(const float* __restrict__ x, __half* __restrict__ xh)
{
    const size_t i = (size_t)blockIdx.x * 256 + threadIdx.x;   // float4 index
    const float4 v = ((const float4*)x)[i];
    ((uint2*)xh)[i] = make_uint2(h2pack(v.x, v.y), h2pack(v.z, v.w));
}

// ---------------------------------------------------------------------------
// Weights: fp32 [K=2048][N] -> fp16 transposed [N][K]. 32x32 tiles, block 32x8.
// gridDim.x = 64 (K tiles); gridDim.y = 160 (N tiles: 64 wq, 16 wk, 16 wv, 64 wo)
// ---------------------------------------------------------------------------
__global__ void wtrans_all(const float* __restrict__ wq, const float* __restrict__ wk,
                           const float* __restrict__ wv, const float* __restrict__ wo,
                           __half* __restrict__ wqh, __half* __restrict__ wkh,
                           __half* __restrict__ wvh, __half* __restrict__ woh)
{
    __shared__ float tile[32][33];
    const int k0 = blockIdx.x * 32;
    const int y = blockIdx.y;
    const float* src; __half* dst; int N, n0;
    if (y < 64)       { src = wq; dst = wqh; N = 2048; n0 = y * 32; }
    else if (y < 80)  { src = wk; dst = wkh; N = 512;  n0 = (y - 64) * 32; }
    else if (y < 96)  { src = wv; dst = wvh; N = 512;  n0 = (y - 80) * 32; }
    else              { src = wo; dst = woh; N = 2048; n0 = (y - 96) * 32; }
    const int tx = threadIdx.x, ty = threadIdx.y;
    #pragma unroll
    for (int i = 0; i < 4; i++)
        tile[ty + i * 8][tx] = src[(size_t)(k0 + ty + i * 8) * N + n0 + tx];
    __syncthreads();
    #pragma unroll
    for (int i = 0; i < 4; i++)
        dst[(size_t)(n0 + ty + i * 8) * DD + k0 + tx] = __float2half(tile[tx][ty + i * 8]);
}

// ---------------------------------------------------------------------------
// V fp32 [t][g][d] -> V^T fp16 [(b*KVH+g)*HD + d][t]
// ---------------------------------------------------------------------------
__global__ void vtrans(const float* __restrict__ v, __half* __restrict__ vt)
{
    __shared__ float tile[32][33];
    const int t0 = blockIdx.x * 32;
    const int d0 = blockIdx.y * 32;
    const int bg = blockIdx.z;             // b*KVH + g
    const int b = bg / KVH, g = bg % KVH;
    const int tx = threadIdx.x, ty = threadIdx.y;
    #pragma unroll
    for (int i = 0; i < 4; i++) {
        const int t = t0 + ty + i * 8;
        tile[ty + i * 8][tx] = v[((size_t)(b * TT + t) * KVH + g) * HD + d0 + tx];
    }
    __syncthreads();
    #pragma unroll
    for (int i = 0; i < 4; i++) {
        const int d = d0 + ty + i * 8;
        vt[((size_t)bg * HD + d) * TT + t0 + tx] = __float2half(tile[tx][ty + i * 8]);
    }
}

// ===========================================================================
// fp16 mma.sync GEMM: C[M,N] = A[M,K] @ BT[N,K]^T, fp32 out.
// 128x128x32 tile, cp.async double-buffered, 2 CTAs/SM.
// Tiles: [128 rows][20 u32] (16 data u32 = 32 fp16 + 4 pad; conflict-free).
// ===========================================================================
#define GBM 128
#define GBN 128
#define HSTR 20

__device__ __forceinline__ void gemm_core_h(
    int M, int N, int K,
    const __half* __restrict__ A, const __half* __restrict__ BT,
    float* __restrict__ C, int m0, int n0)
{
    __shared__ uint32_t As[2][GBM][HSTR];   // 20480 B
    __shared__ uint32_t Bs[2][GBN][HSTR];   // 20480 B

    const int tid  = threadIdx.x;
    const int wid  = tid >> 5;
    const int lane = tid & 31;
    const int gid  = lane >> 2;
    const int tid4 = lane & 3;
    const int warp_m = (wid & 1) * 64;
    const int warp_n = (wid >> 1) * 32;

    // Load mapping: 512 x 16B per tile; 2 per thread. r = unit>>2, c16 = unit&3.
    const int lr = tid >> 2;     // 0..63 (+64)
    const int lc = tid & 3;      // 16B unit
    const __half* aptr = A + (size_t)(m0 + lr) * K + lc * 8;
    const __half* bptr = BT + (size_t)(n0 + lr) * K + lc * 8;
    const uint32_t a_sm = smem_u32(&As[0][lr][lc * 4]);
    const uint32_t b_sm = smem_u32(&Bs[0][lr][lc * 4]);
    const uint32_t rowo = 64u * HSTR * 4u;
    const uint32_t ABUF = GBM * HSTR * 4u;

    float acc[4][4][4];
    #pragma unroll
    for (int i = 0; i < 4; i++)
        #pragma unroll
        for (int j = 0; j < 4; j++)
            #pragma unroll
            for (int r = 0; r < 4; r++) acc[i][j][r] = 0.f;

    const int nch = K / 32;

    cpa16(a_sm, aptr);
    cpa16(a_sm + rowo, aptr + (size_t)64 * K);
    cpa16(b_sm, bptr);
    cpa16(b_sm + rowo, bptr + (size_t)64 * K);
    CP_COMMIT();

    for (int ch = 0; ch < nch; ch++) {
        const int buf = ch & 1;
        CP_WAIT(0);
        __syncthreads();

        if (ch + 1 < nch) {
            const __half* ap = aptr + (size_t)(ch + 1) * 32;
            const __half* bp = bptr + (size_t)(ch + 1) * 32;
            const uint32_t off = (buf ^ 1) ? ABUF : 0u;
            cpa16(a_sm + off, ap);
            cpa16(a_sm + off + rowo, ap + (size_t)64 * K);
            cpa16(b_sm + off, bp);
            cpa16(b_sm + off + rowo, bp + (size_t)64 * K);
            CP_COMMIT();
        }

        #pragma unroll
        for (int kk = 0; kk < 2; kk++) {
            const int pb = kk * 8;
            uint32_t af[4][4], bf[4][2];
            #pragma unroll
            for (int mi = 0; mi < 4; mi++) {
                const int r = warp_m + mi * 16 + gid;
                af[mi][0] = As[buf][r    ][pb + tid4];
                af[mi][1] = As[buf][r + 8][pb + tid4];
                af[mi][2] = As[buf][r    ][pb + tid4 + 4];
                af[mi][3] = As[buf][r + 8][pb + tid4 + 4];
            }
            #pragma unroll
            for (int ni = 0; ni < 4; ni++) {
                const int c = warp_n + ni * 8 + gid;
                bf[ni][0] = Bs[buf][c][pb + tid4];
                bf[ni][1] = Bs[buf][c][pb + tid4 + 4];
            }
            #pragma unroll
            for (int mi = 0; mi < 4; mi++)
                #pragma unroll
                for (int ni = 0; ni < 4; ni++)
                    mma_f16(acc[mi][ni], af[mi][0], af[mi][1], af[mi][2], af[mi][3],
                            bf[ni][0], bf[ni][1]);
        }
    }

    #pragma unroll
    for (int mi = 0; mi < 4; mi++) {
        const int r = m0 + warp_m + mi * 16 + gid;
        #pragma unroll
        for (int ni = 0; ni < 4; ni++) {
            const int c = n0 + warp_n + ni * 8 + tid4 * 2;
            *(float2*)(C + (size_t)r * N + c) =
                make_float2(acc[mi][ni][0], acc[mi][ni][1]);
            *(float2*)(C + (size_t)(r + 8) * N + c) =
                make_float2(acc[mi][ni][2], acc[mi][ni][3]);
        }
    }
}

__global__ __launch_bounds__(256, 2) void gemm_h(
    int M, int N, int K,
    const __half* __restrict__ A, const __half* __restrict__ BT,
    float* __restrict__ C)
{
    gemm_core_h(M, N, K, A, BT, C, blockIdx.y * GBM, blockIdx.x * GBN);
}

__global__ __launch_bounds__(256, 2) void gemm_kv_h(
    int M, int K,
    const __half* __restrict__ A,
    const __half* __restrict__ BTk, const __half* __restrict__ BTv,
    float* __restrict__ Ck, float* __restrict__ Cv)
{
    const int nb = (int)blockIdx.x;
    const int NN = KVH * HD;  // 512
    if (nb < NN / GBN) {
        gemm_core_h(M, NN, K, A, BTk, Ck, blockIdx.y * GBM, nb * GBN);
    } else {
        gemm_core_h(M, NN, K, A, BTv, Cv, blockIdx.y * GBM, (nb - NN / GBN) * GBN);
    }
}

// ---------------------------------------------------------------------------
// RMSNorm+RoPE (q,k) fp32 in -> fp16 out. block (32, HH+KVH).
// ---------------------------------------------------------------------------
__global__ void norm_rope_h(const float* __restrict__ q, const float* __restrict__ k,
                            __half* __restrict__ qh, __half* __restrict__ kh,
                            const float* __restrict__ qw, const float* __restrict__ kw,
                            const float* __restrict__ fc, const float* __restrict__ fs)
{
    const int token = blockIdx.x;
    const int t = token & (TT - 1);
    const int y = threadIdx.y;
    const int lane = threadIdx.x;

    const bool isq = (y < HH);
    const int head = isq ? y : (y - HH);
    const int heads = isq ? HH : KVH;
    const float* u = isq ? q : k;
    __half* uh = isq ? qh : kh;
    const float* w = isq ? qw : kw;

    const size_t off = ((size_t)token * heads + head) * HD + lane * 4;
    const float4 v = *(const float4*)(u + off);

    float ss = v.x * v.x + v.y * v.y + v.z * v.z + v.w * v.w;
    #pragma unroll
    for (int o = 16; o > 0; o >>= 1) ss += __shfl_xor_sync(0xFFFFFFFFu, ss, o);
    const float r = rsqrtf(ss * (1.f / HD) + 1e-6f);

    const float4 wv = *(const float4*)(w + lane * 4);
    const int p = lane * 2;
    const float c0 = fc[t * (HD / 2) + p],     s0 = fs[t * (HD / 2) + p];
    const float c1 = fc[t * (HD / 2) + p + 1], s1 = fs[t * (HD / 2) + p + 1];

    const float e0 = v.x * r * wv.x, o0 = v.y * r * wv.y;
    const float e1 = v.z * r * wv.z, o1 = v.w * r * wv.w;

    *(uint2*)(uh + off) = make_uint2(
        h2pack(e0 * c0 - o0 * s0, e0 * s0 + o0 * c0),
        h2pack(e1 * c1 - o1 * s1, e1 * s1 + o1 * c1));
}

// ===========================================================================
// fp16 tensor-core causal flash attention. TQ=64 (4 warps), TK=64.
// smem(u32): Ks[64][68] + Vs[128][36] + Ps[64][36] = 45056 B -> 2+ CTAs/SM.
// Q frags in regs (8 kfrags x 4). V^T pre-transposed in gmem.
// ===========================================================================
#define FTQ 64
#define FTK 64
#define KSTRH 68
#define VSTRH 36
#define PSTRH 36
#define FA5_SMEM ((FTK * KSTRH + HD * VSTRH + FTQ * PSTRH) * 4)

__device__ __forceinline__ float redmax4(float x) {
    x = fmaxf(x, __shfl_xor_sync(0xFFFFFFFFu, x, 1));
    x = fmaxf(x, __shfl_xor_sync(0xFFFFFFFFu, x, 2));
    return x;
}
__device__ __forceinline__ float redsum4(float x) {
    x += __shfl_xor_sync(0xFFFFFFFFu, x, 1);
    x += __shfl_xor_sync(0xFFFFFFFFu, x, 2);
    return x;
}

__device__ __forceinline__ void issue_kv_h(
    const __half* __restrict__ kh, const __half* __restrict__ vt,
    int b, int g, int kt, uint32_t ksu, uint32_t vsu, int tid)
{
    const int k0 = kt * FTK;
    // K: 64 rows x 16 x 16B
    #pragma unroll
    for (int it = 0; it < 8; it++) {
        const int i = tid + it * 128;
        const int r = i >> 4, c = i & 15;
        cpa16(ksu + (uint32_t)(r * KSTRH + c * 4) * 4u,
              kh + ((size_t)(b * TT + k0 + r) * KVH + g) * HD + c * 8);
    }
    // V^T: 128 rows x 8 x 16B
    #pragma unroll
    for (int it = 0; it < 8; it++) {
        const int i = tid + it * 128;
        const int r = i >> 3, c = i & 7;
        cpa16(vsu + (uint32_t)(r * VSTRH + c * 4) * 4u,
              vt + ((size_t)(b * KVH + g) * HD + r) * TT + k0 + c * 8);
    }
}

__global__ __launch_bounds__(128) void flash_tc(
    const __half* __restrict__ qh, const __half* __restrict__ kh,
    const __half* __restrict__ vt, __half* __restrict__ o)
{
    extern __shared__ uint32_t smu[];
    uint32_t* Ks = smu;                   // [64][68]
    uint32_t* Vs = Ks + FTK * KSTRH;      // [128][36]
    uint32_t* Ps = Vs + HD * VSTRH;       // [64][36]
    const uint32_t ksu = smem_u32(Ks);
    const uint32_t vsu = smem_u32(Vs);

    const int qt = (TT / FTQ - 1) - blockIdx.y;   // LPT
    const int hb = blockIdx.x;
    const int h  = hb % HH;
    const int b  = hb / HH;
    const int g  = h / REP;
    const int tid  = threadIdx.x;
    const int wid  = tid >> 5;
    const int lane = tid & 31;
    const int gid  = lane >> 2;
    const int tid4 = lane & 3;
    const int q0 = qt * FTQ;
    const int wq = wid * 16;

    // Stage Q rows (fp16, 256B/row): warps 0-1 in Ks, warps 2-3 in Vs
    uint32_t* Sg = (wid < 2) ? (Ks + wq * KSTRH) : (Vs + (wq - 64) * KSTRH);
    #pragma unroll
    for (int it = 0; it < 8; it++) {
        const int i = lane + it * 32;
        const int r = i >> 4, c = i & 15;
        const uint4 val = *(const uint4*)(
            qh + ((size_t)(b * TT + q0 + wq + r) * HH + h) * HD + c * 8);
        *(uint4*)&Sg[r * KSTRH + c * 4] = val;
    }
    __syncwarp();
    uint32_t qf[8][4];
    #pragma unroll
    for (int kf = 0; kf < 8; kf++) {
        qf[kf][0] = Sg[gid * KSTRH + kf * 8 + tid4];
        qf[kf][1] = Sg[(gid + 8) * KSTRH + kf * 8 + tid4];
        qf[kf][2] = Sg[gid * KSTRH + kf * 8 + tid4 + 4];
        qf[kf][3] = Sg[(gid + 8) * KSTRH + kf * 8 + tid4 + 4];
    }
    __syncthreads();

    const int nkt = qt + 1;
    issue_kv_h(kh, vt, b, g, 0, ksu, vsu, tid);
    CP_COMMIT();

    float oacc[16][4];
    #pragma unroll
    for (int i = 0; i < 16; i++)
        #pragma unroll
        for (int j = 0; j < 4; j++) oacc[i][j] = 0.f;
    float m0r = -1e30f, m1r = -1e30f, l0r = 0.f, l1r = 0.f;

    const float scale = 0.08838834764831845f;
    const int r0 = q0 + wq + gid;
    const int r1 = r0 + 8;

    for (int kt = 0; kt < nkt; kt++) {
        CP_WAIT(0);
        __syncthreads();

        // S = Q K^T : 8 nt x 8 kf
        float sacc[8][4];
        #pragma unroll
        for (int nt = 0; nt < 8; nt++)
            #pragma unroll
            for (int j = 0; j < 4; j++) sacc[nt][j] = 0.f;
        #pragma unroll
        for (int kf = 0; kf < 8; kf++) {
            #pragma unroll
            for (int nt = 0; nt < 8; nt++) {
                const uint32_t b0 = Ks[(nt * 8 + gid) * KSTRH + kf * 8 + tid4];
                const uint32_t b1 = Ks[(nt * 8 + gid) * KSTRH + kf * 8 + tid4 + 4];
                mma_f16(sacc[nt], qf[kf][0], qf[kf][1], qf[kf][2], qf[kf][3], b0, b1);
            }
        }

        const int k0 = kt * FTK;
        float mn0 = m0r, mn1 = m1r;
        if (kt == nkt - 1) {
            #pragma unroll
            for (int nt = 0; nt < 8; nt++) {
                const int c = k0 + nt * 8 + tid4 * 2;
                float s0 = sacc[nt][0] * scale, s1 = sacc[nt][1] * scale;
                float s2 = sacc[nt][2] * scale, s3 = sacc[nt][3] * scale;
                if (c     > r0) s0 = -1e30f;
                if (c + 1 > r0) s1 = -1e30f;
                if (c     > r1) s2 = -1e30f;
                if (c + 1 > r1) s3 = -1e30f;
                sacc[nt][0] = s0; sacc[nt][1] = s1; sacc[nt][2] = s2; sacc[nt][3] = s3;
                mn0 = fmaxf(mn0, fmaxf(s0, s1));
                mn1 = fmaxf(mn1, fmaxf(s2, s3));
            }
        } else {
            #pragma unroll
            for (int nt = 0; nt < 8; nt++) {
                const float s0 = sacc[nt][0] * scale, s1 = sacc[nt][1] * scale;
                const float s2 = sacc[nt][2] * scale, s3 = sacc[nt][3] * scale;
                sacc[nt][0] = s0; sacc[nt][1] = s1; sacc[nt][2] = s2; sacc[nt][3] = s3;
                mn0 = fmaxf(mn0, fmaxf(s0, s1));
                mn1 = fmaxf(mn1, fmaxf(s2, s3));
            }
        }
        mn0 = redmax4(mn0);
        mn1 = redmax4(mn1);

        const float corr0 = __expf(m0r - mn0);
        const float corr1 = __expf(m1r - mn1);
        float ps0 = 0.f, ps1 = 0.f;
        #pragma unroll
        for (int nt = 0; nt < 8; nt++) {
            const float p0 = __expf(sacc[nt][0] - mn0);
            const float p1 = __expf(sacc[nt][1] - mn0);
            const float p2 = __expf(sacc[nt][2] - mn1);
            const float p3 = __expf(sacc[nt][3] - mn1);
            ps0 += p0 + p1;
            ps1 += p2 + p3;
            Ps[(wq + gid) * PSTRH + nt * 4 + tid4]     = h2pack(p0, p1);
            Ps[(wq + gid + 8) * PSTRH + nt * 4 + tid4] = h2pack(p2, p3);
        }
        l0r = l0r * corr0 + redsum4(ps0);
        l1r = l1r * corr1 + redsum4(ps1);
        m0r = mn0; m1r = mn1;

        #pragma unroll
        for (int nt = 0; nt < 16; nt++) {
            oacc[nt][0] *= corr0; oacc[nt][1] *= corr0;
            oacc[nt][2] *= corr1; oacc[nt][3] *= corr1;
        }
        __syncwarp();   // Ps rows warp-private

        // O += P V : 16 nt x 4 kf
        #pragma unroll
        for (int kf = 0; kf < 4; kf++) {
            const uint32_t a0 = Ps[(wq + gid) * PSTRH + kf * 8 + tid4];
            const uint32_t a1 = Ps[(wq + gid + 8) * PSTRH + kf * 8 + tid4];
            const uint32_t a2 = Ps[(wq + gid) * PSTRH + kf * 8 + tid4 + 4];
            const uint32_t a3 = Ps[(wq + gid + 8) * PSTRH + kf * 8 + tid4 + 4];
            #pragma unroll
            for (int nt = 0; nt < 16; nt++) {
                const uint32_t b0 = Vs[(nt * 8 + gid) * VSTRH + kf * 8 + tid4];
                const uint32_t b1 = Vs[(nt * 8 + gid) * VSTRH + kf * 8 + tid4 + 4];
                mma_f16(oacc[nt], a0, a1, a2, a3, b0, b1);
            }
        }

        __syncthreads();
        if (kt + 1 < nkt) {
            issue_kv_h(kh, vt, b, g, kt + 1, ksu, vsu, tid);
            CP_COMMIT();
        }
    }

    // Epilogue: normalize, fp16 att (O-proj consumes raw)
    const float rl0 = 1.f / l0r;
    const float rl1 = 1.f / l1r;
    __half* ob0 = o + ((size_t)(b * TT + r0) * HH + h) * HD;
    __half* ob1 = o + ((size_t)(b * TT + r1) * HH + h) * HD;
    #pragma unroll
    for (int nt = 0; nt < 16; nt++) {
        const int c = nt * 8 + 2 * tid4;
        *(uint32_t*)(ob0 + c) = h2pack(oacc[nt][0] * rl0, oacc[nt][1] * rl0);
        *(uint32_t*)(ob1 + c) = h2pack(oacc[nt][2] * rl1, oacc[nt][3] * rl1);
    }
}

// ---------------------------------------------------------------------------
extern "C" void kernel_launch(void* const* d_in, const int* in_sizes, int n_in,
                              void* d_out, int out_size)
{
    const float* x    = (const float*)d_in[0];
    const float* wq   = (const float*)d_in[1];
    const float* wk   = (const float*)d_in[2];
    const float* wv   = (const float*)d_in[3];
    const float* wo   = (const float*)d_in[4];
    const float* qnw  = (const float*)d_in[5];
    const float* knw  = (const float*)d_in[6];
    const float* fcos = (const float*)d_in[7];
    const float* fsin = (const float*)d_in[8];
    float* out = (float*)d_out;

    float *q, *k, *v;
    __half *xh, *wqh, *wkh, *wvh, *woh, *qh, *kh, *vt, *atth;
    cudaGetSymbolAddress((void**)&q,    g_q);
    cudaGetSymbolAddress((void**)&k,    g_k);
    cudaGetSymbolAddress((void**)&v,    g_v);
    cudaGetSymbolAddress((void**)&xh,   g_xh);
    cudaGetSymbolAddress((void**)&wqh,  g_wqh);
    cudaGetSymbolAddress((void**)&wkh,  g_wkh);
    cudaGetSymbolAddress((void**)&wvh,  g_wvh);
    cudaGetSymbolAddress((void**)&woh,  g_woh);
    cudaGetSymbolAddress((void**)&qh,   g_qh);
    cudaGetSymbolAddress((void**)&kh,   g_kh);
    cudaGetSymbolAddress((void**)&vt,   g_vt);
    cudaGetSymbolAddress((void**)&atth, g_atth);

    cudaFuncSetAttribute(flash_tc, cudaFuncAttributeMaxDynamicSharedMemorySize, FA5_SMEM);

    // [0] x -> fp16
    preround_xh<<<(NTOK * DD / 4) / 256, 256>>>(x, xh);
    // [1] weights -> fp16 transposed
    wtrans_all<<<dim3(64, 160), dim3(32, 8)>>>(wq, wk, wv, wo, wqh, wkh, wvh, woh);
    // [2] K+V projections (fp16 mma)
    gemm_kv_h<<<dim3(8, NTOK / GBM), 256>>>(NTOK, DD, xh, wkh, wvh, k, v);
    // [3] Q projection   <- ncu capture slot
    gemm_h<<<dim3((HH * HD) / GBN, NTOK / GBM), 256>>>(NTOK, HH * HD, DD, xh, wqh, q);
    // [4] RMSNorm+RoPE -> fp16 q/k
    norm_rope_h<<<NTOK, dim3(32, HH + KVH)>>>(q, k, qh, kh, qnw, knw, fcos, fsin);
    // [5] V -> V^T fp16
    vtrans<<<dim3(TT / 32, HD / 32, BB * KVH), dim3(32, 8)>>>(v, vt);
    // [6] flash attention (fp16)
    flash_tc<<<dim3(HH * BB, TT / FTQ), 128, FA5_SMEM>>>(qh, kh, vt, atth);
    // [7] output projection (fp16 mma)
    gemm_h<<<dim3(DD / GBN, NTOK / GBM), 256>>>(NTOK, DD, HH * HD, atth, woh, out);
}

// round 15
// speedup vs baseline: 2.0292x; 1.0893x over previous
#include <cuda_runtime.h>
#include <cuda_fp16.h>
#include <math.h>
#include <cstdint>

// Problem constants
#define BB 2
#define TT 2048
#define DD 2048
#define HH 16
#define KVH 4
#define HD 128
#define REP (HH / KVH)
#define NTOK (BB * TT)   // 4096

// fp32 scratch
__device__ float g_q[(size_t)NTOK * HH * HD];
__device__ float g_k[(size_t)NTOK * KVH * HD];
__device__ float g_v[(size_t)NTOK * KVH * HD];
// fp16 operands
__device__ __half g_xh[(size_t)NTOK * DD];
__device__ __half g_wqh[(size_t)HH * HD * DD];             // transposed [N][K]
__device__ __half g_wkh[(size_t)KVH * HD * DD];
__device__ __half g_wvh[(size_t)KVH * HD * DD];
__device__ __half g_woh[(size_t)DD * HH * HD];             // transposed [N][K]
__device__ __half g_qh[(size_t)NTOK * HH * HD];
__device__ __half g_kh[(size_t)NTOK * KVH * HD];
__device__ __half g_vt[(size_t)BB * KVH * HD * TT];        // V^T [b*g][d][t]
__device__ __half g_atth[(size_t)NTOK * HH * HD];

__device__ __forceinline__ uint32_t smem_u32(const void* p) {
    uint32_t a;
    asm("{ .reg .u64 t; cvta.to.shared.u64 t, %1; cvt.u32.u64 %0, t; }"
        : "=r"(a) : "l"(p));
    return a;
}

__device__ __forceinline__ uint32_t h2pack(float a, float b) {
    __half2 h = __floats2half2_rn(a, b);
    return *(uint32_t*)&h;
}

__device__ __forceinline__ void mma_f16(float c[4],
    uint32_t a0, uint32_t a1, uint32_t a2, uint32_t a3,
    uint32_t b0, uint32_t b1)
{
    asm volatile(
        "mma.sync.aligned.m16n8k16.row.col.f32.f16.f16.f32 "
        "{%0,%1,%2,%3}, {%4,%5,%6,%7}, {%8,%9}, {%0,%1,%2,%3};"
        : "+f"(c[0]), "+f"(c[1]), "+f"(c[2]), "+f"(c[3])
        : "r"(a0), "r"(a1), "r"(a2), "r"(a3), "r"(b0), "r"(b1));
}

__device__ __forceinline__ void ldsm4(uint32_t& r0, uint32_t& r1,
                                      uint32_t& r2, uint32_t& r3, uint32_t addr)
{
    asm volatile("ldmatrix.sync.aligned.m8n8.x4.shared.b16 {%0,%1,%2,%3}, [%4];"
                 : "=r"(r0), "=r"(r1), "=r"(r2), "=r"(r3) : "r"(addr));
}

__device__ __forceinline__ void cpa16(uint32_t dst, const void* src) {
    asm volatile("cp.async.cg.shared.global [%0], [%1], 16;"
                 :: "r"(dst), "l"(src));
}
#define CP_COMMIT() asm volatile("cp.async.commit_group;" ::: "memory")
#define CP_WAIT(n)  asm volatile("cp.async.wait_group %0;" :: "n"(n) : "memory")

// ---------------------------------------------------------------------------
// x -> fp16
// ---------------------------------------------------------------------------
__global__ void preround_xh(const float* __restrict__ x, __half* __restrict__ xh)
{
    const size_t i = (size_t)blockIdx.x * 256 + threadIdx.x;
    const float4 v = ((const float4*)x)[i];
    ((uint2*)xh)[i] = make_uint2(h2pack(v.x, v.y), h2pack(v.z, v.w));
}

// ---------------------------------------------------------------------------
// Weights: fp32 [K][N] -> fp16 transposed [N][K]
// ---------------------------------------------------------------------------
__global__ void wtrans_all(const float* __restrict__ wq, const float* __restrict__ wk,
                           const float* __restrict__ wv, const float* __restrict__ wo,
                           __half* __restrict__ wqh, __half* __restrict__ wkh,
                           __half* __restrict__ wvh, __half* __restrict__ woh)
{
    __shared__ float tile[32][33];
    const int k0 = blockIdx.x * 32;
    const int y = blockIdx.y;
    const float* src; __half* dst; int N, n0;
    if (y < 64)       { src = wq; dst = wqh; N = 2048; n0 = y * 32; }
    else if (y < 80)  { src = wk; dst = wkh; N = 512;  n0 = (y - 64) * 32; }
    else if (y < 96)  { src = wv; dst = wvh; N = 512;  n0 = (y - 80) * 32; }
    else              { src = wo; dst = woh; N = 2048; n0 = (y - 96) * 32; }
    const int tx = threadIdx.x, ty = threadIdx.y;
    #pragma unroll
    for (int i = 0; i < 4; i++)
        tile[ty + i * 8][tx] = src[(size_t)(k0 + ty + i * 8) * N + n0 + tx];
    __syncthreads();
    #pragma unroll
    for (int i = 0; i < 4; i++)
        dst[(size_t)(n0 + ty + i * 8) * DD + k0 + tx] = __float2half(tile[tx][ty + i * 8]);
}

// ---------------------------------------------------------------------------
// V fp32 [t][g][d] -> V^T fp16 [(b*KVH+g)*HD + d][t]
// ---------------------------------------------------------------------------
__global__ void vtrans(const float* __restrict__ v, __half* __restrict__ vt)
{
    __shared__ float tile[32][33];
    const int t0 = blockIdx.x * 32;
    const int d0 = blockIdx.y * 32;
    const int bg = blockIdx.z;
    const int b = bg / KVH, g = bg % KVH;
    const int tx = threadIdx.x, ty = threadIdx.y;
    #pragma unroll
    for (int i = 0; i < 4; i++) {
        const int t = t0 + ty + i * 8;
        tile[ty + i * 8][tx] = v[((size_t)(b * TT + t) * KVH + g) * HD + d0 + tx];
    }
    __syncthreads();
    #pragma unroll
    for (int i = 0; i < 4; i++) {
        const int d = d0 + ty + i * 8;
        vt[((size_t)bg * HD + d) * TT + t0 + tx] = __float2half(tile[tx][ty + i * 8]);
    }
}

// ===========================================================================
// fp16 mma.sync GEMM with ldmatrix fragment loads. 128x128x32, 2 CTAs/SM.
// ===========================================================================
#define GBM 128
#define GBN 128
#define HSTR 20

__device__ __forceinline__ void gemm_core_h(
    int M, int N, int K,
    const __half* __restrict__ A, const __half* __restrict__ BT,
    float* __restrict__ C, int m0, int n0)
{
    __shared__ uint32_t As[2][GBM][HSTR];
    __shared__ uint32_t Bs[2][GBN][HSTR];

    const int tid  = threadIdx.x;
    const int wid  = tid >> 5;
    const int lane = tid & 31;
    const int gid  = lane >> 2;
    const int tid4 = lane & 3;
    const int warp_m = (wid & 1) * 64;
    const int warp_n = (wid >> 1) * 32;

    // ldmatrix lane->row/col mappings
    const int lrA = (lane & 7) + ((lane >> 3) & 1) * 8;   // A row in 16
    const int lkA = ((lane >> 4) & 1) * 4;                // A col u32
    const int lrB = (lane & 7) + ((lane >> 4) & 1) * 8;   // B row in 16
    const int lkB = ((lane >> 3) & 1) * 4;                // B col u32

    const int lr = tid >> 2;
    const int lc = tid & 3;
    const __half* aptr = A + (size_t)(m0 + lr) * K + lc * 8;
    const __half* bptr = BT + (size_t)(n0 + lr) * K + lc * 8;
    const uint32_t a_sm = smem_u32(&As[0][lr][lc * 4]);
    const uint32_t b_sm = smem_u32(&Bs[0][lr][lc * 4]);
    const uint32_t rowo = 64u * HSTR * 4u;
    const uint32_t ABUF = GBM * HSTR * 4u;

    float acc[4][4][4];
    #pragma unroll
    for (int i = 0; i < 4; i++)
        #pragma unroll
        for (int j = 0; j < 4; j++)
            #pragma unroll
            for (int r = 0; r < 4; r++) acc[i][j][r] = 0.f;

    const int nch = K / 32;

    cpa16(a_sm, aptr);
    cpa16(a_sm + rowo, aptr + (size_t)64 * K);
    cpa16(b_sm, bptr);
    cpa16(b_sm + rowo, bptr + (size_t)64 * K);
    CP_COMMIT();

    for (int ch = 0; ch < nch; ch++) {
        const int buf = ch & 1;
        CP_WAIT(0);
        __syncthreads();

        if (ch + 1 < nch) {
            const __half* ap = aptr + (size_t)(ch + 1) * 32;
            const __half* bp = bptr + (size_t)(ch + 1) * 32;
            const uint32_t off = (buf ^ 1) ? ABUF : 0u;
            cpa16(a_sm + off, ap);
            cpa16(a_sm + off + rowo, ap + (size_t)64 * K);
            cpa16(b_sm + off, bp);
            cpa16(b_sm + off + rowo, bp + (size_t)64 * K);
            CP_COMMIT();
        }

        #pragma unroll
        for (int kk = 0; kk < 2; kk++) {
            const int pb = kk * 8;
            uint32_t af[4][4], bf[4][2];
            #pragma unroll
            for (int mi = 0; mi < 4; mi++)
                ldsm4(af[mi][0], af[mi][1], af[mi][2], af[mi][3],
                      smem_u32(&As[buf][warp_m + mi * 16 + lrA][pb + lkA]));
            #pragma unroll
            for (int nh = 0; nh < 2; nh++)
                ldsm4(bf[nh * 2][0], bf[nh * 2][1], bf[nh * 2 + 1][0], bf[nh * 2 + 1][1],
                      smem_u32(&Bs[buf][warp_n + nh * 16 + lrB][pb + lkB]));
            #pragma unroll
            for (int mi = 0; mi < 4; mi++)
                #pragma unroll
                for (int ni = 0; ni < 4; ni++)
                    mma_f16(acc[mi][ni], af[mi][0], af[mi][1], af[mi][2], af[mi][3],
                            bf[ni][0], bf[ni][1]);
        }
    }

    #pragma unroll
    for (int mi = 0; mi < 4; mi++) {
        const int r = m0 + warp_m + mi * 16 + gid;
        #pragma unroll
        for (int ni = 0; ni < 4; ni++) {
            const int c = n0 + warp_n + ni * 8 + tid4 * 2;
            *(float2*)(C + (size_t)r * N + c) =
                make_float2(acc[mi][ni][0], acc[mi][ni][1]);
            *(float2*)(C + (size_t)(r + 8) * N + c) =
                make_float2(acc[mi][ni][2], acc[mi][ni][3]);
        }
    }
}

__global__ __launch_bounds__(256, 2) void gemm_h(
    int M, int N, int K,
    const __half* __restrict__ A, const __half* __restrict__ BT,
    float* __restrict__ C)
{
    gemm_core_h(M, N, K, A, BT, C, blockIdx.y * GBM, blockIdx.x * GBN);
}

__global__ __launch_bounds__(256, 2) void gemm_kv_h(
    int M, int K,
    const __half* __restrict__ A,
    const __half* __restrict__ BTk, const __half* __restrict__ BTv,
    float* __restrict__ Ck, float* __restrict__ Cv)
{
    const int nb = (int)blockIdx.x;
    const int NN = KVH * HD;
    if (nb < NN / GBN) {
        gemm_core_h(M, NN, K, A, BTk, Ck, blockIdx.y * GBM, nb * GBN);
    } else {
        gemm_core_h(M, NN, K, A, BTv, Cv, blockIdx.y * GBM, (nb - NN / GBN) * GBN);
    }
}

// ---------------------------------------------------------------------------
// RMSNorm+RoPE (q,k) fp32 in -> fp16 out.
// ---------------------------------------------------------------------------
__global__ void norm_rope_h(const float* __restrict__ q, const float* __restrict__ k,
                            __half* __restrict__ qh, __half* __restrict__ kh,
                            const float* __restrict__ qw, const float* __restrict__ kw,
                            const float* __restrict__ fc, const float* __restrict__ fs)
{
    const int token = blockIdx.x;
    const int t = token & (TT - 1);
    const int y = threadIdx.y;
    const int lane = threadIdx.x;

    const bool isq = (y < HH);
    const int head = isq ? y : (y - HH);
    const int heads = isq ? HH : KVH;
    const float* u = isq ? q : k;
    __half* uh = isq ? qh : kh;
    const float* w = isq ? qw : kw;

    const size_t off = ((size_t)token * heads + head) * HD + lane * 4;
    const float4 v = *(const float4*)(u + off);

    float ss = v.x * v.x + v.y * v.y + v.z * v.z + v.w * v.w;
    #pragma unroll
    for (int o = 16; o > 0; o >>= 1) ss += __shfl_xor_sync(0xFFFFFFFFu, ss, o);
    const float r = rsqrtf(ss * (1.f / HD) + 1e-6f);

    const float4 wv = *(const float4*)(w + lane * 4);
    const int p = lane * 2;
    const float c0 = fc[t * (HD / 2) + p],     s0 = fs[t * (HD / 2) + p];
    const float c1 = fc[t * (HD / 2) + p + 1], s1 = fs[t * (HD / 2) + p + 1];

    const float e0 = v.x * r * wv.x, o0 = v.y * r * wv.y;
    const float e1 = v.z * r * wv.z, o1 = v.w * r * wv.w;

    *(uint2*)(uh + off) = make_uint2(
        h2pack(e0 * c0 - o0 * s0, e0 * s0 + o0 * c0),
        h2pack(e1 * c1 - o1 * s1, e1 * s1 + o1 * c1));
}

// ===========================================================================
// fp16 flash attention with ldmatrix fragment loads. TQ=64, TK=64, 128 thr.
// smem(u32): Ks[64][68] + Vs[128][36] + Ps[64][36] = 45056 B.
// ===========================================================================
#define FTQ 64
#define FTK 64
#define KSTRH 68
#define VSTRH 36
#define PSTRH 36
#define FA5_SMEM ((FTK * KSTRH + HD * VSTRH + FTQ * PSTRH) * 4)

__device__ __forceinline__ float redmax4(float x) {
    x = fmaxf(x, __shfl_xor_sync(0xFFFFFFFFu, x, 1));
    x = fmaxf(x, __shfl_xor_sync(0xFFFFFFFFu, x, 2));
    return x;
}
__device__ __forceinline__ float redsum4(float x) {
    x += __shfl_xor_sync(0xFFFFFFFFu, x, 1);
    x += __shfl_xor_sync(0xFFFFFFFFu, x, 2);
    return x;
}

__device__ __forceinline__ void issue_kv_h(
    const __half* __restrict__ kh, const __half* __restrict__ vt,
    int b, int g, int kt, uint32_t ksu, uint32_t vsu, int tid)
{
    const int k0 = kt * FTK;
    #pragma unroll
    for (int it = 0; it < 8; it++) {
        const int i = tid + it * 128;
        const int r = i >> 4, c = i & 15;
        cpa16(ksu + (uint32_t)(r * KSTRH + c * 4) * 4u,
              kh + ((size_t)(b * TT + k0 + r) * KVH + g) * HD + c * 8);
    }
    #pragma unroll
    for (int it = 0; it < 8; it++) {
        const int i = tid + it * 128;
        const int r = i >> 3, c = i & 7;
        cpa16(vsu + (uint32_t)(r * VSTRH + c * 4) * 4u,
              vt + ((size_t)(b * KVH + g) * HD + r) * TT + k0 + c * 8);
    }
}

__global__ __launch_bounds__(128) void flash_tc(
    const __half* __restrict__ qh, const __half* __restrict__ kh,
    const __half* __restrict__ vt, __half* __restrict__ o)
{
    extern __shared__ uint32_t smu[];
    uint32_t* Ks = smu;
    uint32_t* Vs = Ks + FTK * KSTRH;
    uint32_t* Ps = Vs + HD * VSTRH;
    const uint32_t ksu = smem_u32(Ks);
    const uint32_t vsu = smem_u32(Vs);
    const uint32_t psu = smem_u32(Ps);

    const int qt = (TT / FTQ - 1) - blockIdx.y;   // LPT
    const int hb = blockIdx.x;
    const int h  = hb % HH;
    const int b  = hb / HH;
    const int g  = h / REP;
    const int tid  = threadIdx.x;
    const int wid  = tid >> 5;
    const int lane = tid & 31;
    const int gid  = lane >> 2;
    const int tid4 = lane & 3;
    const int q0 = qt * FTQ;
    const int wq = wid * 16;

    // ldmatrix lane mappings
    const int lrA = (lane & 7) + ((lane >> 3) & 1) * 8;
    const int lkA = ((lane >> 4) & 1) * 4;
    const int lrB = (lane & 7) + ((lane >> 4) & 1) * 8;
    const int lkB = ((lane >> 3) & 1) * 4;

    // Stage Q rows: warps 0-1 in Ks, warps 2-3 in Vs
    uint32_t* Sg = (wid < 2) ? (Ks + wq * KSTRH) : (Vs + (wq - 64) * KSTRH);
    #pragma unroll
    for (int it = 0; it < 8; it++) {
        const int i = lane + it * 32;
        const int r = i >> 4, c = i & 15;
        const uint4 val = *(const uint4*)(
            qh + ((size_t)(b * TT + q0 + wq + r) * HH + h) * HD + c * 8);
        *(uint4*)&Sg[r * KSTRH + c * 4] = val;
    }
    __syncwarp();
    uint32_t qf[8][4];
    #pragma unroll
    for (int kf = 0; kf < 8; kf++)
        ldsm4(qf[kf][0], qf[kf][1], qf[kf][2], qf[kf][3],
              smem_u32(&Sg[lrA * KSTRH + kf * 8 + lkA]));
    __syncthreads();

    const int nkt = qt + 1;
    issue_kv_h(kh, vt, b, g, 0, ksu, vsu, tid);
    CP_COMMIT();

    float oacc[16][4];
    #pragma unroll
    for (int i = 0; i < 16; i++)
        #pragma unroll
        for (int j = 0; j < 4; j++) oacc[i][j] = 0.f;
    float m0r = -1e30f, m1r = -1e30f, l0r = 0.f, l1r = 0.f;

    const float scale = 0.08838834764831845f;
    const int r0 = q0 + wq + gid;
    const int r1 = r0 + 8;

    for (int kt = 0; kt < nkt; kt++) {
        CP_WAIT(0);
        __syncthreads();

        // S = Q K^T : 8 nt x 8 kf (ldmatrix B)
        float sacc[8][4];
        #pragma unroll
        for (int nt = 0; nt < 8; nt++)
            #pragma unroll
            for (int j = 0; j < 4; j++) sacc[nt][j] = 0.f;
        #pragma unroll
        for (int kf = 0; kf < 8; kf++) {
            #pragma unroll
            for (int nh = 0; nh < 4; nh++) {
                uint32_t b00, b01, b10, b11;
                ldsm4(b00, b01, b10, b11,
                      ksu + (uint32_t)((nh * 16 + lrB) * KSTRH + kf * 8 + lkB) * 4u);
                mma_f16(sacc[nh * 2],     qf[kf][0], qf[kf][1], qf[kf][2], qf[kf][3], b00, b01);
                mma_f16(sacc[nh * 2 + 1], qf[kf][0], qf[kf][1], qf[kf][2], qf[kf][3], b10, b11);
            }
        }

        const int k0 = kt * FTK;
        float mn0 = m0r, mn1 = m1r;
        if (kt == nkt - 1) {
            #pragma unroll
            for (int nt = 0; nt < 8; nt++) {
                const int c = k0 + nt * 8 + tid4 * 2;
                float s0 = sacc[nt][0] * scale, s1 = sacc[nt][1] * scale;
                float s2 = sacc[nt][2] * scale, s3 = sacc[nt][3] * scale;
                if (c     > r0) s0 = -1e30f;
                if (c + 1 > r0) s1 = -1e30f;
                if (c     > r1) s2 = -1e30f;
                if (c + 1 > r1) s3 = -1e30f;
                sacc[nt][0] = s0; sacc[nt][1] = s1; sacc[nt][2] = s2; sacc[nt][3] = s3;
                mn0 = fmaxf(mn0, fmaxf(s0, s1));
                mn1 = fmaxf(mn1, fmaxf(s2, s3));
            }
        } else {
            #pragma unroll
            for (int nt = 0; nt < 8; nt++) {
                const float s0 = sacc[nt][0] * scale, s1 = sacc[nt][1] * scale;
                const float s2 = sacc[nt][2] * scale, s3 = sacc[nt][3] * scale;
                sacc[nt][0] = s0; sacc[nt][1] = s1; sacc[nt][2] = s2; sacc[nt][3] = s3;
                mn0 = fmaxf(mn0, fmaxf(s0, s1));
                mn1 = fmaxf(mn1, fmaxf(s2, s3));
            }
        }
        mn0 = redmax4(mn0);
        mn1 = redmax4(mn1);

        const float corr0 = __expf(m0r - mn0);
        const float corr1 = __expf(m1r - mn1);
        float ps0 = 0.f, ps1 = 0.f;
        #pragma unroll
        for (int nt = 0; nt < 8; nt++) {
            const float p0 = __expf(sacc[nt][0] - mn0);
            const float p1 = __expf(sacc[nt][1] - mn0);
            const float p2 = __expf(sacc[nt][2] - mn1);
            const float p3 = __expf(sacc[nt][3] - mn1);
            ps0 += p0 + p1;
            ps1 += p2 + p3;
            Ps[(wq + gid) * PSTRH + nt * 4 + tid4]     = h2pack(p0, p1);
            Ps[(wq + gid + 8) * PSTRH + nt * 4 + tid4] = h2pack(p2, p3);
        }
        l0r = l0r * corr0 + redsum4(ps0);
        l1r = l1r * corr1 + redsum4(ps1);
        m0r = mn0; m1r = mn1;

        #pragma unroll
        for (int nt = 0; nt < 16; nt++) {
            oacc[nt][0] *= corr0; oacc[nt][1] *= corr0;
            oacc[nt][2] *= corr1; oacc[nt][3] *= corr1;
        }
        __syncwarp();   // Ps rows warp-private

        // O += P V : 16 nt x 4 kf (ldmatrix A + B)
        #pragma unroll
        for (int kf = 0; kf < 4; kf++) {
            uint32_t a0, a1, a2, a3;
            ldsm4(a0, a1, a2, a3,
                  psu + (uint32_t)((wq + lrA) * PSTRH + kf * 8 + lkA) * 4u);
            #pragma unroll
            for (int nh = 0; nh < 8; nh++) {
                uint32_t b00, b01, b10, b11;
                ldsm4(b00, b01, b10, b11,
                      vsu + (uint32_t)((nh * 16 + lrB) * VSTRH + kf * 8 + lkB) * 4u);
                mma_f16(oacc[nh * 2],     a0, a1, a2, a3, b00, b01);
                mma_f16(oacc[nh * 2 + 1], a0, a1, a2, a3, b10, b11);
            }
        }

        __syncthreads();
        if (kt + 1 < nkt) {
            issue_kv_h(kh, vt, b, g, kt + 1, ksu, vsu, tid);
            CP_COMMIT();
        }
    }

    // Epilogue
    const float rl0 = 1.f / l0r;
    const float rl1 = 1.f / l1r;
    __half* ob0 = o + ((size_t)(b * TT + r0) * HH + h) * HD;
    __half* ob1 = o + ((size_t)(b * TT + r1) * HH + h) * HD;
    #pragma unroll
    for (int nt = 0; nt < 16; nt++) {
        const int c = nt * 8 + 2 * tid4;
        *(uint32_t*)(ob0 + c) = h2pack(oacc[nt][0] * rl0, oacc[nt][1] * rl0);
        *(uint32_t*)(ob1 + c) = h2pack(oacc[nt][2] * rl1, oacc[nt][3] * rl1);
    }
}

// ---------------------------------------------------------------------------
extern "C" void kernel_launch(void* const* d_in, const int* in_sizes, int n_in,
                              void* d_out, int out_size)
{
    const float* x    = (const float*)d_in[0];
    const float* wq   = (const float*)d_in[1];
    const float* wk   = (const float*)d_in[2];
    const float* wv   = (const float*)d_in[3];
    const float* wo   = (const float*)d_in[4];
    const float* qnw  = (const float*)d_in[5];
    const float* knw  = (const float*)d_in[6];
    const float* fcos = (const float*)d_in[7];
    const float* fsin = (const float*)d_in[8];
    float* out = (float*)d_out;

    float *q, *k, *v;
    __half *xh, *wqh, *wkh, *wvh, *woh, *qh, *kh, *vt, *atth;
    cudaGetSymbolAddress((void**)&q,    g_q);
    cudaGetSymbolAddress((void**)&k,    g_k);
    cudaGetSymbolAddress((void**)&v,    g_v);
    cudaGetSymbolAddress((void**)&xh,   g_xh);
    cudaGetSymbolAddress((void**)&wqh,  g_wqh);
    cudaGetSymbolAddress((void**)&wkh,  g_wkh);
    cudaGetSymbolAddress((void**)&wvh,  g_wvh);
    cudaGetSymbolAddress((void**)&woh,  g_woh);
    cudaGetSymbolAddress((void**)&qh,   g_qh);
    cudaGetSymbolAddress((void**)&kh,   g_kh);
    cudaGetSymbolAddress((void**)&vt,   g_vt);
    cudaGetSymbolAddress((void**)&atth, g_atth);

    cudaFuncSetAttribute(flash_tc, cudaFuncAttributeMaxDynamicSharedMemorySize, FA5_SMEM);

    // [0] x -> fp16
    preround_xh<<<(NTOK * DD / 4) / 256, 256>>>(x, xh);
    // [1] weights -> fp16 transposed
    wtrans_all<<<dim3(64, 160), dim3(32, 8)>>>(wq, wk, wv, wo, wqh, wkh, wvh, woh);
    // [2] K+V projections
    gemm_kv_h<<<dim3(8, NTOK / GBM), 256>>>(NTOK, DD, xh, wkh, wvh, k, v);
    // [3] Q projection   <- ncu capture slot
    gemm_h<<<dim3((HH * HD) / GBN, NTOK / GBM), 256>>>(NTOK, HH * HD, DD, xh, wqh, q);
    // [4] RMSNorm+RoPE -> fp16 q/k
    norm_rope_h<<<NTOK, dim3(32, HH + KVH)>>>(q, k, qh, kh, qnw, knw, fcos, fsin);
    // [5] V -> V^T fp16
    vtrans<<<dim3(TT / 32, HD / 32, BB * KVH), dim3(32, 8)>>>(v, vt);
    // [6] flash attention
    flash_tc<<<dim3(HH * BB, TT / FTQ), 128, FA5_SMEM>>>(qh, kh, vt, atth);
    // [7] output projection
    gemm_h<<<dim3(DD / GBN, NTOK / GBM), 256>>>(NTOK, DD, HH * HD, atth, woh, out);
}

// round 16
// speedup vs baseline: 2.0588x; 1.0146x over previous
#include <cuda_runtime.h>
#include <cuda_fp16.h>
#include <math.h>
#include <cstdint>

// Problem constants
#define BB 2
#define TT 2048
#define DD 2048
#define HH 16
#define KVH 4
#define HD 128
#define REP (HH / KVH)
#define NTOK (BB * TT)   // 4096

// fp32 scratch
__device__ float g_q[(size_t)NTOK * HH * HD];
__device__ float g_k[(size_t)NTOK * KVH * HD];
__device__ float g_v[(size_t)NTOK * KVH * HD];
// fp16 operands
__device__ __half g_xh[(size_t)NTOK * DD];
__device__ __half g_wqh[(size_t)HH * HD * DD];             // transposed [N][K]
__device__ __half g_wkh[(size_t)KVH * HD * DD];
__device__ __half g_wvh[(size_t)KVH * HD * DD];
__device__ __half g_woh[(size_t)DD * HH * HD];             // transposed [N][K]
__device__ __half g_qh[(size_t)NTOK * HH * HD];
__device__ __half g_kh[(size_t)NTOK * KVH * HD];
__device__ __half g_vt[(size_t)BB * KVH * HD * TT];        // V^T [b*g][d][t]
__device__ __half g_atth[(size_t)NTOK * HH * HD];

__device__ __forceinline__ uint32_t smem_u32(const void* p) {
    uint32_t a;
    asm("{ .reg .u64 t; cvta.to.shared.u64 t, %1; cvt.u32.u64 %0, t; }"
        : "=r"(a) : "l"(p));
    return a;
}

__device__ __forceinline__ uint32_t h2pack(float a, float b) {
    __half2 h = __floats2half2_rn(a, b);
    return *(uint32_t*)&h;
}

__device__ __forceinline__ void mma_f16(float c[4],
    uint32_t a0, uint32_t a1, uint32_t a2, uint32_t a3,
    uint32_t b0, uint32_t b1)
{
    asm volatile(
        "mma.sync.aligned.m16n8k16.row.col.f32.f16.f16.f32 "
        "{%0,%1,%2,%3}, {%4,%5,%6,%7}, {%8,%9}, {%0,%1,%2,%3};"
        : "+f"(c[0]), "+f"(c[1]), "+f"(c[2]), "+f"(c[3])
        : "r"(a0), "r"(a1), "r"(a2), "r"(a3), "r"(b0), "r"(b1));
}

__device__ __forceinline__ void ldsm4(uint32_t& r0, uint32_t& r1,
                                      uint32_t& r2, uint32_t& r3, uint32_t addr)
{
    asm volatile("ldmatrix.sync.aligned.m8n8.x4.shared.b16 {%0,%1,%2,%3}, [%4];"
                 : "=r"(r0), "=r"(r1), "=r"(r2), "=r"(r3) : "r"(addr));
}

__device__ __forceinline__ void cpa16(uint32_t dst, const void* src) {
    asm volatile("cp.async.cg.shared.global [%0], [%1], 16;"
                 :: "r"(dst), "l"(src));
}
#define CP_COMMIT() asm volatile("cp.async.commit_group;" ::: "memory")
#define CP_WAIT(n)  asm volatile("cp.async.wait_group %0;" :: "n"(n) : "memory")

// ---------------------------------------------------------------------------
// x -> fp16
// ---------------------------------------------------------------------------
__global__ void preround_xh(const float* __restrict__ x, __half* __restrict__ xh)
{
    const size_t i = (size_t)blockIdx.x * 256 + threadIdx.x;
    const float4 v = ((const float4*)x)[i];
    ((uint2*)xh)[i] = make_uint2(h2pack(v.x, v.y), h2pack(v.z, v.w));
}

// ---------------------------------------------------------------------------
// Weights: fp32 [K][N] -> fp16 transposed [N][K]
// ---------------------------------------------------------------------------
__global__ void wtrans_all(const float* __restrict__ wq, const float* __restrict__ wk,
                           const float* __restrict__ wv, const float* __restrict__ wo,
                           __half* __restrict__ wqh, __half* __restrict__ wkh,
                           __half* __restrict__ wvh, __half* __restrict__ woh)
{
    __shared__ float tile[32][33];
    const int k0 = blockIdx.x * 32;
    const int y = blockIdx.y;
    const float* src; __half* dst; int N, n0;
    if (y < 64)       { src = wq; dst = wqh; N = 2048; n0 = y * 32; }
    else if (y < 80)  { src = wk; dst = wkh; N = 512;  n0 = (y - 64) * 32; }
    else if (y < 96)  { src = wv; dst = wvh; N = 512;  n0 = (y - 80) * 32; }
    else              { src = wo; dst = woh; N = 2048; n0 = (y - 96) * 32; }
    const int tx = threadIdx.x, ty = threadIdx.y;
    #pragma unroll
    for (int i = 0; i < 4; i++)
        tile[ty + i * 8][tx] = src[(size_t)(k0 + ty + i * 8) * N + n0 + tx];
    __syncthreads();
    #pragma unroll
    for (int i = 0; i < 4; i++)
        dst[(size_t)(n0 + ty + i * 8) * DD + k0 + tx] = __float2half(tile[tx][ty + i * 8]);
}

// ---------------------------------------------------------------------------
// V fp32 [t][g][d] -> V^T fp16 [(b*KVH+g)*HD + d][t]
// ---------------------------------------------------------------------------
__global__ void vtrans(const float* __restrict__ v, __half* __restrict__ vt)
{
    __shared__ float tile[32][33];
    const int t0 = blockIdx.x * 32;
    const int d0 = blockIdx.y * 32;
    const int bg = blockIdx.z;
    const int b = bg / KVH, g = bg % KVH;
    const int tx = threadIdx.x, ty = threadIdx.y;
    #pragma unroll
    for (int i = 0; i < 4; i++) {
        const int t = t0 + ty + i * 8;
        tile[ty + i * 8][tx] = v[((size_t)(b * TT + t) * KVH + g) * HD + d0 + tx];
    }
    __syncthreads();
    #pragma unroll
    for (int i = 0; i < 4; i++) {
        const int d = d0 + ty + i * 8;
        vt[((size_t)bg * HD + d) * TT + t0 + tx] = __float2half(tile[tx][ty + i * 8]);
    }
}

// ===========================================================================
// fp16 mma.sync GEMM, 3-stage cp.async pipeline (CP_WAIT(1): loads get
// ~2 chunk-times to land). 128x128x32 tiles, ldmatrix frags, 2 CTAs/SM.
// Dynamic smem: 3 stages x (As 10240 B + Bs 10240 B) = 61440 B/CTA.
// ===========================================================================
#define GBM 128
#define GBN 128
#define HSTR 20
#define GSTG 3
#define STGU (GBM * HSTR)                  // u32 per As (or Bs) stage = 2560
#define GEMM_SMEM3 (2 * GSTG * STGU * 4)   // 61440 B

__device__ __forceinline__ void gemm_core_h(
    int M, int N, int K,
    const __half* __restrict__ A, const __half* __restrict__ BT,
    float* __restrict__ C, int m0, int n0)
{
    extern __shared__ uint32_t smu[];
    // layout: As stage 0..2, then Bs stage 0..2
    uint32_t* Asm = smu;
    uint32_t* Bsm = smu + GSTG * STGU;

    const int tid  = threadIdx.x;
    const int wid  = tid >> 5;
    const int lane = tid & 31;
    const int gid  = lane >> 2;
    const int tid4 = lane & 3;
    const int warp_m = (wid & 1) * 64;
    const int warp_n = (wid >> 1) * 32;

    // ldmatrix lane->row/col mappings
    const int lrA = (lane & 7) + ((lane >> 3) & 1) * 8;
    const int lkA = ((lane >> 4) & 1) * 4;
    const int lrB = (lane & 7) + ((lane >> 4) & 1) * 8;
    const int lkB = ((lane >> 3) & 1) * 4;

    const int lr = tid >> 2;
    const int lc = tid & 3;
    const __half* aptr = A + (size_t)(m0 + lr) * K + lc * 8;
    const __half* bptr = BT + (size_t)(n0 + lr) * K + lc * 8;
    const uint32_t a_sm0 = smem_u32(Asm) + (uint32_t)(lr * HSTR + lc * 4) * 4u;
    const uint32_t b_sm0 = smem_u32(Bsm) + (uint32_t)(lr * HSTR + lc * 4) * 4u;
    const uint32_t rowo = 64u * HSTR * 4u;
    const uint32_t STGB = STGU * 4u;       // stage stride in bytes

    float acc[4][4][4];
    #pragma unroll
    for (int i = 0; i < 4; i++)
        #pragma unroll
        for (int j = 0; j < 4; j++)
            #pragma unroll
            for (int r = 0; r < 4; r++) acc[i][j][r] = 0.f;

    const int nch = K / 32;

    // Prologue: issue chunks 0,1 into stages 0,1
    #pragma unroll
    for (int pc = 0; pc < 2; pc++) {
        const __half* ap = aptr + (size_t)pc * 32;
        const __half* bp = bptr + (size_t)pc * 32;
        const uint32_t so = pc * STGB;
        cpa16(a_sm0 + so, ap);
        cpa16(a_sm0 + so + rowo, ap + (size_t)64 * K);
        cpa16(b_sm0 + so, bp);
        cpa16(b_sm0 + so + rowo, bp + (size_t)64 * K);
        CP_COMMIT();
    }

    int stage = 0;
    for (int ch = 0; ch < nch; ch++) {
        if (ch + 1 < nch) { CP_WAIT(1); } else { CP_WAIT(0); }
        __syncthreads();   // chunk ch visible; compute(ch-1) finished everywhere

        if (ch + 2 < nch) {
            const int ns = (stage + 2 >= GSTG) ? (stage + 2 - GSTG) : (stage + 2);
            const __half* ap = aptr + (size_t)(ch + 2) * 32;
            const __half* bp = bptr + (size_t)(ch + 2) * 32;
            const uint32_t so = ns * STGB;
            cpa16(a_sm0 + so, ap);
            cpa16(a_sm0 + so + rowo, ap + (size_t)64 * K);
            cpa16(b_sm0 + so, bp);
            cpa16(b_sm0 + so + rowo, bp + (size_t)64 * K);
            CP_COMMIT();
        }

        const uint32_t* As = Asm + stage * STGU;
        const uint32_t* Bs = Bsm + stage * STGU;
        #pragma unroll
        for (int kk = 0; kk < 2; kk++) {
            const int pb = kk * 8;
            uint32_t af[4][4], bf[4][2];
            #pragma unroll
            for (int mi = 0; mi < 4; mi++)
                ldsm4(af[mi][0], af[mi][1], af[mi][2], af[mi][3],
                      smem_u32(&As[(warp_m + mi * 16 + lrA) * HSTR + pb + lkA]));
            #pragma unroll
            for (int nh = 0; nh < 2; nh++)
                ldsm4(bf[nh * 2][0], bf[nh * 2][1], bf[nh * 2 + 1][0], bf[nh * 2 + 1][1],
                      smem_u32(&Bs[(warp_n + nh * 16 + lrB) * HSTR + pb + lkB]));
            #pragma unroll
            for (int mi = 0; mi < 4; mi++)
                #pragma unroll
                for (int ni = 0; ni < 4; ni++)
                    mma_f16(acc[mi][ni], af[mi][0], af[mi][1], af[mi][2], af[mi][3],
                            bf[ni][0], bf[ni][1]);
        }
        stage = (stage + 1 >= GSTG) ? 0 : (stage + 1);
    }

    #pragma unroll
    for (int mi = 0; mi < 4; mi++) {
        const int r = m0 + warp_m + mi * 16 + gid;
        #pragma unroll
        for (int ni = 0; ni < 4; ni++) {
            const int c = n0 + warp_n + ni * 8 + tid4 * 2;
            *(float2*)(C + (size_t)r * N + c) =
                make_float2(acc[mi][ni][0], acc[mi][ni][1]);
            *(float2*)(C + (size_t)(r + 8) * N + c) =
                make_float2(acc[mi][ni][2], acc[mi][ni][3]);
        }
    }
}

__global__ __launch_bounds__(256, 2) void gemm_h(
    int M, int N, int K,
    const __half* __restrict__ A, const __half* __restrict__ BT,
    float* __restrict__ C)
{
    gemm_core_h(M, N, K, A, BT, C, blockIdx.y * GBM, blockIdx.x * GBN);
}

__global__ __launch_bounds__(256, 2) void gemm_kv_h(
    int M, int K,
    const __half* __restrict__ A,
    const __half* __restrict__ BTk, const __half* __restrict__ BTv,
    float* __restrict__ Ck, float* __restrict__ Cv)
{
    const int nb = (int)blockIdx.x;
    const int NN = KVH * HD;
    if (nb < NN / GBN) {
        gemm_core_h(M, NN, K, A, BTk, Ck, blockIdx.y * GBM, nb * GBN);
    } else {
        gemm_core_h(M, NN, K, A, BTv, Cv, blockIdx.y * GBM, (nb - NN / GBN) * GBN);
    }
}

// ---------------------------------------------------------------------------
// RMSNorm+RoPE (q,k) fp32 in -> fp16 out.
// ---------------------------------------------------------------------------
__global__ void norm_rope_h(const float* __restrict__ q, const float* __restrict__ k,
                            __half* __restrict__ qh, __half* __restrict__ kh,
                            const float* __restrict__ qw, const float* __restrict__ kw,
                            const float* __restrict__ fc, const float* __restrict__ fs)
{
    const int token = blockIdx.x;
    const int t = token & (TT - 1);
    const int y = threadIdx.y;
    const int lane = threadIdx.x;

    const bool isq = (y < HH);
    const int head = isq ? y : (y - HH);
    const int heads = isq ? HH : KVH;
    const float* u = isq ? q : k;
    __half* uh = isq ? qh : kh;
    const float* w = isq ? qw : kw;

    const size_t off = ((size_t)token * heads + head) * HD + lane * 4;
    const float4 v = *(const float4*)(u + off);

    float ss = v.x * v.x + v.y * v.y + v.z * v.z + v.w * v.w;
    #pragma unroll
    for (int o = 16; o > 0; o >>= 1) ss += __shfl_xor_sync(0xFFFFFFFFu, ss, o);
    const float r = rsqrtf(ss * (1.f / HD) + 1e-6f);

    const float4 wv = *(const float4*)(w + lane * 4);
    const int p = lane * 2;
    const float c0 = fc[t * (HD / 2) + p],     s0 = fs[t * (HD / 2) + p];
    const float c1 = fc[t * (HD / 2) + p + 1], s1 = fs[t * (HD / 2) + p + 1];

    const float e0 = v.x * r * wv.x, o0 = v.y * r * wv.y;
    const float e1 = v.z * r * wv.z, o1 = v.w * r * wv.w;

    *(uint2*)(uh + off) = make_uint2(
        h2pack(e0 * c0 - o0 * s0, e0 * s0 + o0 * c0),
        h2pack(e1 * c1 - o1 * s1, e1 * s1 + o1 * c1));
}

// ===========================================================================
// fp16 flash attention (unchanged from R15 — passing).
// ===========================================================================
#define FTQ 64
#define FTK 64
#define KSTRH 68
#define VSTRH 36
#define PSTRH 36
#define FA5_SMEM ((FTK * KSTRH + HD * VSTRH + FTQ * PSTRH) * 4)

__device__ __forceinline__ float redmax4(float x) {
    x = fmaxf(x, __shfl_xor_sync(0xFFFFFFFFu, x, 1));
    x = fmaxf(x, __shfl_xor_sync(0xFFFFFFFFu, x, 2));
    return x;
}
__device__ __forceinline__ float redsum4(float x) {
    x += __shfl_xor_sync(0xFFFFFFFFu, x, 1);
    x += __shfl_xor_sync(0xFFFFFFFFu, x, 2);
    return x;
}

__device__ __forceinline__ void issue_kv_h(
    const __half* __restrict__ kh, const __half* __restrict__ vt,
    int b, int g, int kt, uint32_t ksu, uint32_t vsu, int tid)
{
    const int k0 = kt * FTK;
    #pragma unroll
    for (int it = 0; it < 8; it++) {
        const int i = tid + it * 128;
        const int r = i >> 4, c = i & 15;
        cpa16(ksu + (uint32_t)(r * KSTRH + c * 4) * 4u,
              kh + ((size_t)(b * TT + k0 + r) * KVH + g) * HD + c * 8);
    }
    #pragma unroll
    for (int it = 0; it < 8; it++) {
        const int i = tid + it * 128;
        const int r = i >> 3, c = i & 7;
        cpa16(vsu + (uint32_t)(r * VSTRH + c * 4) * 4u,
              vt + ((size_t)(b * KVH + g) * HD + r) * TT + k0 + c * 8);
    }
}

__global__ __launch_bounds__(128) void flash_tc(
    const __half* __restrict__ qh, const __half* __restrict__ kh,
    const __half* __restrict__ vt, __half* __restrict__ o)
{
    extern __shared__ uint32_t smu[];
    uint32_t* Ks = smu;
    uint32_t* Vs = Ks + FTK * KSTRH;
    uint32_t* Ps = Vs + HD * VSTRH;
    const uint32_t ksu = smem_u32(Ks);
    const uint32_t vsu = smem_u32(Vs);
    const uint32_t psu = smem_u32(Ps);

    const int qt = (TT / FTQ - 1) - blockIdx.y;   // LPT
    const int hb = blockIdx.x;
    const int h  = hb % HH;
    const int b  = hb / HH;
    const int g  = h / REP;
    const int tid  = threadIdx.x;
    const int wid  = tid >> 5;
    const int lane = tid & 31;
    const int gid  = lane >> 2;
    const int tid4 = lane & 3;
    const int q0 = qt * FTQ;
    const int wq = wid * 16;

    const int lrA = (lane & 7) + ((lane >> 3) & 1) * 8;
    const int lkA = ((lane >> 4) & 1) * 4;
    const int lrB = (lane & 7) + ((lane >> 4) & 1) * 8;
    const int lkB = ((lane >> 3) & 1) * 4;

    uint32_t* Sg = (wid < 2) ? (Ks + wq * KSTRH) : (Vs + (wq - 64) * KSTRH);
    #pragma unroll
    for (int it = 0; it < 8; it++) {
        const int i = lane + it * 32;
        const int r = i >> 4, c = i & 15;
        const uint4 val = *(const uint4*)(
            qh + ((size_t)(b * TT + q0 + wq + r) * HH + h) * HD + c * 8);
        *(uint4*)&Sg[r * KSTRH + c * 4] = val;
    }
    __syncwarp();
    uint32_t qf[8][4];
    #pragma unroll
    for (int kf = 0; kf < 8; kf++)
        ldsm4(qf[kf][0], qf[kf][1], qf[kf][2], qf[kf][3],
              smem_u32(&Sg[lrA * KSTRH + kf * 8 + lkA]));
    __syncthreads();

    const int nkt = qt + 1;
    issue_kv_h(kh, vt, b, g, 0, ksu, vsu, tid);
    CP_COMMIT();

    float oacc[16][4];
    #pragma unroll
    for (int i = 0; i < 16; i++)
        #pragma unroll
        for (int j = 0; j < 4; j++) oacc[i][j] = 0.f;
    float m0r = -1e30f, m1r = -1e30f, l0r = 0.f, l1r = 0.f;

    const float scale = 0.08838834764831845f;
    const int r0 = q0 + wq + gid;
    const int r1 = r0 + 8;

    for (int kt = 0; kt < nkt; kt++) {
        CP_WAIT(0);
        __syncthreads();

        float sacc[8][4];
        #pragma unroll
        for (int nt = 0; nt < 8; nt++)
            #pragma unroll
            for (int j = 0; j < 4; j++) sacc[nt][j] = 0.f;
        #pragma unroll
        for (int kf = 0; kf < 8; kf++) {
            #pragma unroll
            for (int nh = 0; nh < 4; nh++) {
                uint32_t b00, b01, b10, b11;
                ldsm4(b00, b01, b10, b11,
                      ksu + (uint32_t)((nh * 16 + lrB) * KSTRH + kf * 8 + lkB) * 4u);
                mma_f16(sacc[nh * 2],     qf[kf][0], qf[kf][1], qf[kf][2], qf[kf][3], b00, b01);
                mma_f16(sacc[nh * 2 + 1], qf[kf][0], qf[kf][1], qf[kf][2], qf[kf][3], b10, b11);
            }
        }

        const int k0 = kt * FTK;
        float mn0 = m0r, mn1 = m1r;
        if (kt == nkt - 1) {
            #pragma unroll
            for (int nt = 0; nt < 8; nt++) {
                const int c = k0 + nt * 8 + tid4 * 2;
                float s0 = sacc[nt][0] * scale, s1 = sacc[nt][1] * scale;
                float s2 = sacc[nt][2] * scale, s3 = sacc[nt][3] * scale;
                if (c     > r0) s0 = -1e30f;
                if (c + 1 > r0) s1 = -1e30f;
                if (c     > r1) s2 = -1e30f;
                if (c + 1 > r1) s3 = -1e30f;
                sacc[nt][0] = s0; sacc[nt][1] = s1; sacc[nt][2] = s2; sacc[nt][3] = s3;
                mn0 = fmaxf(mn0, fmaxf(s0, s1));
                mn1 = fmaxf(mn1, fmaxf(s2, s3));
            }
        } else {
            #pragma unroll
            for (int nt = 0; nt < 8; nt++) {
                const float s0 = sacc[nt][0] * scale, s1 = sacc[nt][1] * scale;
                const float s2 = sacc[nt][2] * scale, s3 = sacc[nt][3] * scale;
                sacc[nt][0] = s0; sacc[nt][1] = s1; sacc[nt][2] = s2; sacc[nt][3] = s3;
                mn0 = fmaxf(mn0, fmaxf(s0, s1));
                mn1 = fmaxf(mn1, fmaxf(s2, s3));
            }
        }
        mn0 = redmax4(mn0);
        mn1 = redmax4(mn1);

        const float corr0 = __expf(m0r - mn0);
        const float corr1 = __expf(m1r - mn1);
        float ps0 = 0.f, ps1 = 0.f;
        #pragma unroll
        for (int nt = 0; nt < 8; nt++) {
            const float p0 = __expf(sacc[nt][0] - mn0);
            const float p1 = __expf(sacc[nt][1] - mn0);
            const float p2 = __expf(sacc[nt][2] - mn1);
            const float p3 = __expf(sacc[nt][3] - mn1);
            ps0 += p0 + p1;
            ps1 += p2 + p3;
            Ps[(wq + gid) * PSTRH + nt * 4 + tid4]     = h2pack(p0, p1);
            Ps[(wq + gid + 8) * PSTRH + nt * 4 + tid4] = h2pack(p2, p3);
        }
        l0r = l0r * corr0 + redsum4(ps0);
        l1r = l1r * corr1 + redsum4(ps1);
        m0r = mn0; m1r = mn1;

        #pragma unroll
        for (int nt = 0; nt < 16; nt++) {
            oacc[nt][0] *= corr0; oacc[nt][1] *= corr0;
            oacc[nt][2] *= corr1; oacc[nt][3] *= corr1;
        }
        __syncwarp();

        #pragma unroll
        for (int kf = 0; kf < 4; kf++) {
            uint32_t a0, a1, a2, a3;
            ldsm4(a0, a1, a2, a3,
                  psu + (uint32_t)((wq + lrA) * PSTRH + kf * 8 + lkA) * 4u);
            #pragma unroll
            for (int nh = 0; nh < 8; nh++) {
                uint32_t b00, b01, b10, b11;
                ldsm4(b00, b01, b10, b11,
                      vsu + (uint32_t)((nh * 16 + lrB) * VSTRH + kf * 8 + lkB) * 4u);
                mma_f16(oacc[nh * 2],     a0, a1, a2, a3, b00, b01);
                mma_f16(oacc[nh * 2 + 1], a0, a1, a2, a3, b10, b11);
            }
        }

        __syncthreads();
        if (kt + 1 < nkt) {
            issue_kv_h(kh, vt, b, g, kt + 1, ksu, vsu, tid);
            CP_COMMIT();
        }
    }

    const float rl0 = 1.f / l0r;
    const float rl1 = 1.f / l1r;
    __half* ob0 = o + ((size_t)(b * TT + r0) * HH + h) * HD;
    __half* ob1 = o + ((size_t)(b * TT + r1) * HH + h) * HD;
    #pragma unroll
    for (int nt = 0; nt < 16; nt++) {
        const int c = nt * 8 + 2 * tid4;
        *(uint32_t*)(ob0 + c) = h2pack(oacc[nt][0] * rl0, oacc[nt][1] * rl0);
        *(uint32_t*)(ob1 + c) = h2pack(oacc[nt][2] * rl1, oacc[nt][3] * rl1);
    }
}

// ---------------------------------------------------------------------------
extern "C" void kernel_launch(void* const* d_in, const int* in_sizes, int n_in,
                              void* d_out, int out_size)
{
    const float* x    = (const float*)d_in[0];
    const float* wq   = (const float*)d_in[1];
    const float* wk   = (const float*)d_in[2];
    const float* wv   = (const float*)d_in[3];
    const float* wo   = (const float*)d_in[4];
    const float* qnw  = (const float*)d_in[5];
    const float* knw  = (const float*)d_in[6];
    const float* fcos = (const float*)d_in[7];
    const float* fsin = (const float*)d_in[8];
    float* out = (float*)d_out;

    float *q, *k, *v;
    __half *xh, *wqh, *wkh, *wvh, *woh, *qh, *kh, *vt, *atth;
    cudaGetSymbolAddress((void**)&q,    g_q);
    cudaGetSymbolAddress((void**)&k,    g_k);
    cudaGetSymbolAddress((void**)&v,    g_v);
    cudaGetSymbolAddress((void**)&xh,   g_xh);
    cudaGetSymbolAddress((void**)&wqh,  g_wqh);
    cudaGetSymbolAddress((void**)&wkh,  g_wkh);
    cudaGetSymbolAddress((void**)&wvh,  g_wvh);
    cudaGetSymbolAddress((void**)&woh,  g_woh);
    cudaGetSymbolAddress((void**)&qh,   g_qh);
    cudaGetSymbolAddress((void**)&kh,   g_kh);
    cudaGetSymbolAddress((void**)&vt,   g_vt);
    cudaGetSymbolAddress((void**)&atth, g_atth);

    cudaFuncSetAttribute(flash_tc, cudaFuncAttributeMaxDynamicSharedMemorySize, FA5_SMEM);
    cudaFuncSetAttribute(gemm_h, cudaFuncAttributeMaxDynamicSharedMemorySize, GEMM_SMEM3);
    cudaFuncSetAttribute(gemm_kv_h, cudaFuncAttributeMaxDynamicSharedMemorySize, GEMM_SMEM3);

    // [0] x -> fp16
    preround_xh<<<(NTOK * DD / 4) / 256, 256>>>(x, xh);
    // [1] weights -> fp16 transposed
    wtrans_all<<<dim3(64, 160), dim3(32, 8)>>>(wq, wk, wv, wo, wqh, wkh, wvh, woh);
    // [2] K+V projections
    gemm_kv_h<<<dim3(8, NTOK / GBM), 256, GEMM_SMEM3>>>(NTOK, DD, xh, wkh, wvh, k, v);
    // [3] Q projection   <- ncu capture slot
    gemm_h<<<dim3((HH * HD) / GBN, NTOK / GBM), 256, GEMM_SMEM3>>>(NTOK, HH * HD, DD, xh, wqh, q);
    // [4] RMSNorm+RoPE -> fp16 q/k
    norm_rope_h<<<NTOK, dim3(32, HH + KVH)>>>(q, k, qh, kh, qnw, knw, fcos, fsin);
    // [5] V -> V^T fp16
    vtrans<<<dim3(TT / 32, HD / 32, BB * KVH), dim3(32, 8)>>>(v, vt);
    // [6] flash attention
    flash_tc<<<dim3(HH * BB, TT / FTQ), 128, FA5_SMEM>>>(qh, kh, vt, atth);
    // [7] output projection
    gemm_h<<<dim3(DD / GBN, NTOK / GBM), 256, GEMM_SMEM3>>>(NTOK, DD, HH * HD, atth, woh, out);
}

// round 17
// speedup vs baseline: 2.1049x; 1.0224x over previous
#include <cuda_runtime.h>
#include <cuda_fp16.h>
#include <math.h>
#include <cstdint>

// Problem constants
#define BB 2
#define TT 2048
#define DD 2048
#define HH 16
#define KVH 4
#define HD 128
#define REP (HH / KVH)
#define NTOK (BB * TT)   // 4096

// fp32 scratch
__device__ float g_q[(size_t)NTOK * HH * HD];
__device__ float g_k[(size_t)NTOK * KVH * HD];
__device__ float g_v[(size_t)NTOK * KVH * HD];
// fp16 operands
__device__ __half g_xh[(size_t)NTOK * DD];
__device__ __half g_wqh[(size_t)HH * HD * DD];             // transposed [N][K]
__device__ __half g_wkh[(size_t)KVH * HD * DD];
__device__ __half g_wvh[(size_t)KVH * HD * DD];
__device__ __half g_woh[(size_t)DD * HH * HD];             // transposed [N][K]
__device__ __half g_qh[(size_t)NTOK * HH * HD];
__device__ __half g_kh[(size_t)NTOK * KVH * HD];
__device__ __half g_vt[(size_t)BB * KVH * HD * TT];        // V^T [b*g][d][t]
__device__ __half g_atth[(size_t)NTOK * HH * HD];

__device__ __forceinline__ uint32_t smem_u32(const void* p) {
    uint32_t a;
    asm("{ .reg .u64 t; cvta.to.shared.u64 t, %1; cvt.u32.u64 %0, t; }"
        : "=r"(a) : "l"(p));
    return a;
}

__device__ __forceinline__ uint32_t h2pack(float a, float b) {
    __half2 h = __floats2half2_rn(a, b);
    return *(uint32_t*)&h;
}

__device__ __forceinline__ void mma_f16(float c[4],
    uint32_t a0, uint32_t a1, uint32_t a2, uint32_t a3,
    uint32_t b0, uint32_t b1)
{
    asm volatile(
        "mma.sync.aligned.m16n8k16.row.col.f32.f16.f16.f32 "
        "{%0,%1,%2,%3}, {%4,%5,%6,%7}, {%8,%9}, {%0,%1,%2,%3};"
        : "+f"(c[0]), "+f"(c[1]), "+f"(c[2]), "+f"(c[3])
        : "r"(a0), "r"(a1), "r"(a2), "r"(a3), "r"(b0), "r"(b1));
}

__device__ __forceinline__ void ldsm4(uint32_t& r0, uint32_t& r1,
                                      uint32_t& r2, uint32_t& r3, uint32_t addr)
{
    asm volatile("ldmatrix.sync.aligned.m8n8.x4.shared.b16 {%0,%1,%2,%3}, [%4];"
                 : "=r"(r0), "=r"(r1), "=r"(r2), "=r"(r3) : "r"(addr));
}

__device__ __forceinline__ void cpa16(uint32_t dst, const void* src) {
    asm volatile("cp.async.cg.shared.global [%0], [%1], 16;"
                 :: "r"(dst), "l"(src));
}
#define CP_COMMIT() asm volatile("cp.async.commit_group;" ::: "memory")
#define CP_WAIT(n)  asm volatile("cp.async.wait_group %0;" :: "n"(n) : "memory")

// ---------------------------------------------------------------------------
// x -> fp16
// ---------------------------------------------------------------------------
__global__ void preround_xh(const float* __restrict__ x, __half* __restrict__ xh)
{
    const size_t i = (size_t)blockIdx.x * 256 + threadIdx.x;
    const float4 v = ((const float4*)x)[i];
    ((uint2*)xh)[i] = make_uint2(h2pack(v.x, v.y), h2pack(v.z, v.w));
}

// ---------------------------------------------------------------------------
// Weights: fp32 [K][N] -> fp16 transposed [N][K]
// ---------------------------------------------------------------------------
__global__ void wtrans_all(const float* __restrict__ wq, const float* __restrict__ wk,
                           const float* __restrict__ wv, const float* __restrict__ wo,
                           __half* __restrict__ wqh, __half* __restrict__ wkh,
                           __half* __restrict__ wvh, __half* __restrict__ woh)
{
    __shared__ float tile[32][33];
    const int k0 = blockIdx.x * 32;
    const int y = blockIdx.y;
    const float* src; __half* dst; int N, n0;
    if (y < 64)       { src = wq; dst = wqh; N = 2048; n0 = y * 32; }
    else if (y < 80)  { src = wk; dst = wkh; N = 512;  n0 = (y - 64) * 32; }
    else if (y < 96)  { src = wv; dst = wvh; N = 512;  n0 = (y - 80) * 32; }
    else              { src = wo; dst = woh; N = 2048; n0 = (y - 96) * 32; }
    const int tx = threadIdx.x, ty = threadIdx.y;
    #pragma unroll
    for (int i = 0; i < 4; i++)
        tile[ty + i * 8][tx] = src[(size_t)(k0 + ty + i * 8) * N + n0 + tx];
    __syncthreads();
    #pragma unroll
    for (int i = 0; i < 4; i++)
        dst[(size_t)(n0 + ty + i * 8) * DD + k0 + tx] = __float2half(tile[tx][ty + i * 8]);
}

// ---------------------------------------------------------------------------
// V fp32 [t][g][d] -> V^T fp16 [(b*KVH+g)*HD + d][t]
// ---------------------------------------------------------------------------
__global__ void vtrans(const float* __restrict__ v, __half* __restrict__ vt)
{
    __shared__ float tile[32][33];
    const int t0 = blockIdx.x * 32;
    const int d0 = blockIdx.y * 32;
    const int bg = blockIdx.z;
    const int b = bg / KVH, g = bg % KVH;
    const int tx = threadIdx.x, ty = threadIdx.y;
    #pragma unroll
    for (int i = 0; i < 4; i++) {
        const int t = t0 + ty + i * 8;
        tile[ty + i * 8][tx] = v[((size_t)(b * TT + t) * KVH + g) * HD + d0 + tx];
    }
    __syncthreads();
    #pragma unroll
    for (int i = 0; i < 4; i++) {
        const int d = d0 + ty + i * 8;
        vt[((size_t)bg * HD + d) * TT + t0 + tx] = __float2half(tile[tx][ty + i * 8]);
    }
}

// ===========================================================================
// fp16 mma.sync GEMM core: 3-stage cp.async pipeline, ldmatrix frags,
// 128x128x32 tiles, 2 CTAs/SM. (unchanged from R16 — at format ceiling)
// ===========================================================================
#define GBM 128
#define GBN 128
#define HSTR 20
#define GSTG 3
#define STGU (GBM * HSTR)
#define GEMM_SMEM3 (2 * GSTG * STGU * 4)   // 61440 B

__device__ __forceinline__ void gemm_core_h(
    int M, int N, int K,
    const __half* __restrict__ A, const __half* __restrict__ BT,
    float* __restrict__ C, int m0, int n0)
{
    extern __shared__ uint32_t smu[];
    uint32_t* Asm = smu;
    uint32_t* Bsm = smu + GSTG * STGU;

    const int tid  = threadIdx.x;
    const int wid  = tid >> 5;
    const int lane = tid & 31;
    const int gid  = lane >> 2;
    const int tid4 = lane & 3;
    const int warp_m = (wid & 1) * 64;
    const int warp_n = (wid >> 1) * 32;

    const int lrA = (lane & 7) + ((lane >> 3) & 1) * 8;
    const int lkA = ((lane >> 4) & 1) * 4;
    const int lrB = (lane & 7) + ((lane >> 4) & 1) * 8;
    const int lkB = ((lane >> 3) & 1) * 4;

    const int lr = tid >> 2;
    const int lc = tid & 3;
    const __half* aptr = A + (size_t)(m0 + lr) * K + lc * 8;
    const __half* bptr = BT + (size_t)(n0 + lr) * K + lc * 8;
    const uint32_t a_sm0 = smem_u32(Asm) + (uint32_t)(lr * HSTR + lc * 4) * 4u;
    const uint32_t b_sm0 = smem_u32(Bsm) + (uint32_t)(lr * HSTR + lc * 4) * 4u;
    const uint32_t rowo = 64u * HSTR * 4u;
    const uint32_t STGB = STGU * 4u;

    float acc[4][4][4];
    #pragma unroll
    for (int i = 0; i < 4; i++)
        #pragma unroll
        for (int j = 0; j < 4; j++)
            #pragma unroll
            for (int r = 0; r < 4; r++) acc[i][j][r] = 0.f;

    const int nch = K / 32;

    #pragma unroll
    for (int pc = 0; pc < 2; pc++) {
        const __half* ap = aptr + (size_t)pc * 32;
        const __half* bp = bptr + (size_t)pc * 32;
        const uint32_t so = pc * STGB;
        cpa16(a_sm0 + so, ap);
        cpa16(a_sm0 + so + rowo, ap + (size_t)64 * K);
        cpa16(b_sm0 + so, bp);
        cpa16(b_sm0 + so + rowo, bp + (size_t)64 * K);
        CP_COMMIT();
    }

    int stage = 0;
    for (int ch = 0; ch < nch; ch++) {
        if (ch + 1 < nch) { CP_WAIT(1); } else { CP_WAIT(0); }
        __syncthreads();

        if (ch + 2 < nch) {
            const int ns = (stage + 2 >= GSTG) ? (stage + 2 - GSTG) : (stage + 2);
            const __half* ap = aptr + (size_t)(ch + 2) * 32;
            const __half* bp = bptr + (size_t)(ch + 2) * 32;
            const uint32_t so = ns * STGB;
            cpa16(a_sm0 + so, ap);
            cpa16(a_sm0 + so + rowo, ap + (size_t)64 * K);
            cpa16(b_sm0 + so, bp);
            cpa16(b_sm0 + so + rowo, bp + (size_t)64 * K);
            CP_COMMIT();
        }

        const uint32_t* As = Asm + stage * STGU;
        const uint32_t* Bs = Bsm + stage * STGU;
        #pragma unroll
        for (int kk = 0; kk < 2; kk++) {
            const int pb = kk * 8;
            uint32_t af[4][4], bf[4][2];
            #pragma unroll
            for (int mi = 0; mi < 4; mi++)
                ldsm4(af[mi][0], af[mi][1], af[mi][2], af[mi][3],
                      smem_u32(&As[(warp_m + mi * 16 + lrA) * HSTR + pb + lkA]));
            #pragma unroll
            for (int nh = 0; nh < 2; nh++)
                ldsm4(bf[nh * 2][0], bf[nh * 2][1], bf[nh * 2 + 1][0], bf[nh * 2 + 1][1],
                      smem_u32(&Bs[(warp_n + nh * 16 + lrB) * HSTR + pb + lkB]));
            #pragma unroll
            for (int mi = 0; mi < 4; mi++)
                #pragma unroll
                for (int ni = 0; ni < 4; ni++)
                    mma_f16(acc[mi][ni], af[mi][0], af[mi][1], af[mi][2], af[mi][3],
                            bf[ni][0], bf[ni][1]);
        }
        stage = (stage + 1 >= GSTG) ? 0 : (stage + 1);
    }

    #pragma unroll
    for (int mi = 0; mi < 4; mi++) {
        const int r = m0 + warp_m + mi * 16 + gid;
        #pragma unroll
        for (int ni = 0; ni < 4; ni++) {
            const int c = n0 + warp_n + ni * 8 + tid4 * 2;
            *(float2*)(C + (size_t)r * N + c) =
                make_float2(acc[mi][ni][0], acc[mi][ni][1]);
            *(float2*)(C + (size_t)(r + 8) * N + c) =
                make_float2(acc[mi][ni][2], acc[mi][ni][3]);
        }
    }
}

__global__ __launch_bounds__(256, 2) void gemm_h(
    int M, int N, int K,
    const __half* __restrict__ A, const __half* __restrict__ BT,
    float* __restrict__ C)
{
    gemm_core_h(M, N, K, A, BT, C, blockIdx.y * GBM, blockIdx.x * GBN);
}

// Fused Q+K+V projection, ONE launch: grid.x 0-15 -> Q, 16-19 -> K, 20-23 -> V.
// 768 CTAs total = 2.59 waves of 296 slots (vs 0.86 + 1.73 with two tails).
__global__ __launch_bounds__(256, 2) void gemm_qkv_h(
    int M, int K,
    const __half* __restrict__ A,
    const __half* __restrict__ BTq, const __half* __restrict__ BTk,
    const __half* __restrict__ BTv,
    float* __restrict__ Cq, float* __restrict__ Ck, float* __restrict__ Cv)
{
    const int nb = (int)blockIdx.x;
    const int NQ = HH * HD;    // 2048
    const int NKV = KVH * HD;  // 512
    if (nb < NQ / GBN) {
        gemm_core_h(M, NQ, K, A, BTq, Cq, blockIdx.y * GBM, nb * GBN);
    } else if (nb < NQ / GBN + NKV / GBN) {
        gemm_core_h(M, NKV, K, A, BTk, Ck, blockIdx.y * GBM, (nb - NQ / GBN) * GBN);
    } else {
        gemm_core_h(M, NKV, K, A, BTv, Cv, blockIdx.y * GBM,
                    (nb - NQ / GBN - NKV / GBN) * GBN);
    }
}

// ---------------------------------------------------------------------------
// RMSNorm+RoPE (q,k) fp32 in -> fp16 out.
// ---------------------------------------------------------------------------
__global__ void norm_rope_h(const float* __restrict__ q, const float* __restrict__ k,
                            __half* __restrict__ qh, __half* __restrict__ kh,
                            const float* __restrict__ qw, const float* __restrict__ kw,
                            const float* __restrict__ fc, const float* __restrict__ fs)
{
    const int token = blockIdx.x;
    const int t = token & (TT - 1);
    const int y = threadIdx.y;
    const int lane = threadIdx.x;

    const bool isq = (y < HH);
    const int head = isq ? y : (y - HH);
    const int heads = isq ? HH : KVH;
    const float* u = isq ? q : k;
    __half* uh = isq ? qh : kh;
    const float* w = isq ? qw : kw;

    const size_t off = ((size_t)token * heads + head) * HD + lane * 4;
    const float4 v = *(const float4*)(u + off);

    float ss = v.x * v.x + v.y * v.y + v.z * v.z + v.w * v.w;
    #pragma unroll
    for (int o = 16; o > 0; o >>= 1) ss += __shfl_xor_sync(0xFFFFFFFFu, ss, o);
    const float r = rsqrtf(ss * (1.f / HD) + 1e-6f);

    const float4 wv = *(const float4*)(w + lane * 4);
    const int p = lane * 2;
    const float c0 = fc[t * (HD / 2) + p],     s0 = fs[t * (HD / 2) + p];
    const float c1 = fc[t * (HD / 2) + p + 1], s1 = fs[t * (HD / 2) + p + 1];

    const float e0 = v.x * r * wv.x, o0 = v.y * r * wv.y;
    const float e1 = v.z * r * wv.z, o1 = v.w * r * wv.w;

    *(uint2*)(uh + off) = make_uint2(
        h2pack(e0 * c0 - o0 * s0, e0 * s0 + o0 * c0),
        h2pack(e1 * c1 - o1 * s1, e1 * s1 + o1 * c1));
}

// ===========================================================================
// fp16 flash attention (unchanged — passing).
// ===========================================================================
#define FTQ 64
#define FTK 64
#define KSTRH 68
#define VSTRH 36
#define PSTRH 36
#define FA5_SMEM ((FTK * KSTRH + HD * VSTRH + FTQ * PSTRH) * 4)

__device__ __forceinline__ float redmax4(float x) {
    x = fmaxf(x, __shfl_xor_sync(0xFFFFFFFFu, x, 1));
    x = fmaxf(x, __shfl_xor_sync(0xFFFFFFFFu, x, 2));
    return x;
}
__device__ __forceinline__ float redsum4(float x) {
    x += __shfl_xor_sync(0xFFFFFFFFu, x, 1);
    x += __shfl_xor_sync(0xFFFFFFFFu, x, 2);
    return x;
}

__device__ __forceinline__ void issue_kv_h(
    const __half* __restrict__ kh, const __half* __restrict__ vt,
    int b, int g, int kt, uint32_t ksu, uint32_t vsu, int tid)
{
    const int k0 = kt * FTK;
    #pragma unroll
    for (int it = 0; it < 8; it++) {
        const int i = tid + it * 128;
        const int r = i >> 4, c = i & 15;
        cpa16(ksu + (uint32_t)(r * KSTRH + c * 4) * 4u,
              kh + ((size_t)(b * TT + k0 + r) * KVH + g) * HD + c * 8);
    }
    #pragma unroll
    for (int it = 0; it < 8; it++) {
        const int i = tid + it * 128;
        const int r = i >> 3, c = i & 7;
        cpa16(vsu + (uint32_t)(r * VSTRH + c * 4) * 4u,
              vt + ((size_t)(b * KVH + g) * HD + r) * TT + k0 + c * 8);
    }
}

__global__ __launch_bounds__(128) void flash_tc(
    const __half* __restrict__ qh, const __half* __restrict__ kh,
    const __half* __restrict__ vt, __half* __restrict__ o)
{
    extern __shared__ uint32_t smu[];
    uint32_t* Ks = smu;
    uint32_t* Vs = Ks + FTK * KSTRH;
    uint32_t* Ps = Vs + HD * VSTRH;
    const uint32_t ksu = smem_u32(Ks);
    const uint32_t vsu = smem_u32(Vs);
    const uint32_t psu = smem_u32(Ps);

    const int qt = (TT / FTQ - 1) - blockIdx.y;   // LPT
    const int hb = blockIdx.x;
    const int h  = hb % HH;
    const int b  = hb / HH;
    const int g  = h / REP;
    const int tid  = threadIdx.x;
    const int wid  = tid >> 5;
    const int lane = tid & 31;
    const int gid  = lane >> 2;
    const int tid4 = lane & 3;
    const int q0 = qt * FTQ;
    const int wq = wid * 16;

    const int lrA = (lane & 7) + ((lane >> 3) & 1) * 8;
    const int lkA = ((lane >> 4) & 1) * 4;
    const int lrB = (lane & 7) + ((lane >> 4) & 1) * 8;
    const int lkB = ((lane >> 3) & 1) * 4;

    uint32_t* Sg = (wid < 2) ? (Ks + wq * KSTRH) : (Vs + (wq - 64) * KSTRH);
    #pragma unroll
    for (int it = 0; it < 8; it++) {
        const int i = lane + it * 32;
        const int r = i >> 4, c = i & 15;
        const uint4 val = *(const uint4*)(
            qh + ((size_t)(b * TT + q0 + wq + r) * HH + h) * HD + c * 8);
        *(uint4*)&Sg[r * KSTRH + c * 4] = val;
    }
    __syncwarp();
    uint32_t qf[8][4];
    #pragma unroll
    for (int kf = 0; kf < 8; kf++)
        ldsm4(qf[kf][0], qf[kf][1], qf[kf][2], qf[kf][3],
              smem_u32(&Sg[lrA * KSTRH + kf * 8 + lkA]));
    __syncthreads();

    const int nkt = qt + 1;
    issue_kv_h(kh, vt, b, g, 0, ksu, vsu, tid);
    CP_COMMIT();

    float oacc[16][4];
    #pragma unroll
    for (int i = 0; i < 16; i++)
        #pragma unroll
        for (int j = 0; j < 4; j++) oacc[i][j] = 0.f;
    float m0r = -1e30f, m1r = -1e30f, l0r = 0.f, l1r = 0.f;

    const float scale = 0.08838834764831845f;
    const int r0 = q0 + wq + gid;
    const int r1 = r0 + 8;

    for (int kt = 0; kt < nkt; kt++) {
        CP_WAIT(0);
        __syncthreads();

        float sacc[8][4];
        #pragma unroll
        for (int nt = 0; nt < 8; nt++)
            #pragma unroll
            for (int j = 0; j < 4; j++) sacc[nt][j] = 0.f;
        #pragma unroll
        for (int kf = 0; kf < 8; kf++) {
            #pragma unroll
            for (int nh = 0; nh < 4; nh++) {
                uint32_t b00, b01, b10, b11;
                ldsm4(b00, b01, b10, b11,
                      ksu + (uint32_t)((nh * 16 + lrB) * KSTRH + kf * 8 + lkB) * 4u);
                mma_f16(sacc[nh * 2],     qf[kf][0], qf[kf][1], qf[kf][2], qf[kf][3], b00, b01);
                mma_f16(sacc[nh * 2 + 1], qf[kf][0], qf[kf][1], qf[kf][2], qf[kf][3], b10, b11);
            }
        }

        const int k0 = kt * FTK;
        float mn0 = m0r, mn1 = m1r;
        if (kt == nkt - 1) {
            #pragma unroll
            for (int nt = 0; nt < 8; nt++) {
                const int c = k0 + nt * 8 + tid4 * 2;
                float s0 = sacc[nt][0] * scale, s1 = sacc[nt][1] * scale;
                float s2 = sacc[nt][2] * scale, s3 = sacc[nt][3] * scale;
                if (c     > r0) s0 = -1e30f;
                if (c + 1 > r0) s1 = -1e30f;
                if (c     > r1) s2 = -1e30f;
                if (c + 1 > r1) s3 = -1e30f;
                sacc[nt][0] = s0; sacc[nt][1] = s1; sacc[nt][2] = s2; sacc[nt][3] = s3;
                mn0 = fmaxf(mn0, fmaxf(s0, s1));
                mn1 = fmaxf(mn1, fmaxf(s2, s3));
            }
        } else {
            #pragma unroll
            for (int nt = 0; nt < 8; nt++) {
                const float s0 = sacc[nt][0] * scale, s1 = sacc[nt][1] * scale;
                const float s2 = sacc[nt][2] * scale, s3 = sacc[nt][3] * scale;
                sacc[nt][0] = s0; sacc[nt][1] = s1; sacc[nt][2] = s2; sacc[nt][3] = s3;
                mn0 = fmaxf(mn0, fmaxf(s0, s1));
                mn1 = fmaxf(mn1, fmaxf(s2, s3));
            }
        }
        mn0 = redmax4(mn0);
        mn1 = redmax4(mn1);

        const float corr0 = __expf(m0r - mn0);
        const float corr1 = __expf(m1r - mn1);
        float ps0 = 0.f, ps1 = 0.f;
        #pragma unroll
        for (int nt = 0; nt < 8; nt++) {
            const float p0 = __expf(sacc[nt][0] - mn0);
            const float p1 = __expf(sacc[nt][1] - mn0);
            const float p2 = __expf(sacc[nt][2] - mn1);
            const float p3 = __expf(sacc[nt][3] - mn1);
            ps0 += p0 + p1;
            ps1 += p2 + p3;
            Ps[(wq + gid) * PSTRH + nt * 4 + tid4]     = h2pack(p0, p1);
            Ps[(wq + gid + 8) * PSTRH + nt * 4 + tid4] = h2pack(p2, p3);
        }
        l0r = l0r * corr0 + redsum4(ps0);
        l1r = l1r * corr1 + redsum4(ps1);
        m0r = mn0; m1r = mn1;

        #pragma unroll
        for (int nt = 0; nt < 16; nt++) {
            oacc[nt][0] *= corr0; oacc[nt][1] *= corr0;
            oacc[nt][2] *= corr1; oacc[nt][3] *= corr1;
        }
        __syncwarp();

        #pragma unroll
        for (int kf = 0; kf < 4; kf++) {
            uint32_t a0, a1, a2, a3;
            ldsm4(a0, a1, a2, a3,
                  psu + (uint32_t)((wq + lrA) * PSTRH + kf * 8 + lkA) * 4u);
            #pragma unroll
            for (int nh = 0; nh < 8; nh++) {
                uint32_t b00, b01, b10, b11;
                ldsm4(b00, b01, b10, b11,
                      vsu + (uint32_t)((nh * 16 + lrB) * VSTRH + kf * 8 + lkB) * 4u);
                mma_f16(oacc[nh * 2],     a0, a1, a2, a3, b00, b01);
                mma_f16(oacc[nh * 2 + 1], a0, a1, a2, a3, b10, b11);
            }
        }

        __syncthreads();
        if (kt + 1 < nkt) {
            issue_kv_h(kh, vt, b, g, kt + 1, ksu, vsu, tid);
            CP_COMMIT();
        }
    }

    const float rl0 = 1.f / l0r;
    const float rl1 = 1.f / l1r;
    __half* ob0 = o + ((size_t)(b * TT + r0) * HH + h) * HD;
    __half* ob1 = o + ((size_t)(b * TT + r1) * HH + h) * HD;
    #pragma unroll
    for (int nt = 0; nt < 16; nt++) {
        const int c = nt * 8 + 2 * tid4;
        *(uint32_t*)(ob0 + c) = h2pack(oacc[nt][0] * rl0, oacc[nt][1] * rl0);
        *(uint32_t*)(ob1 + c) = h2pack(oacc[nt][2] * rl1, oacc[nt][3] * rl1);
    }
}

// ---------------------------------------------------------------------------
extern "C" void kernel_launch(void* const* d_in, const int* in_sizes, int n_in,
                              void* d_out, int out_size)
{
    const float* x    = (const float*)d_in[0];
    const float* wq   = (const float*)d_in[1];
    const float* wk   = (const float*)d_in[2];
    const float* wv   = (const float*)d_in[3];
    const float* wo   = (const float*)d_in[4];
    const float* qnw  = (const float*)d_in[5];
    const float* knw  = (const float*)d_in[6];
    const float* fcos = (const float*)d_in[7];
    const float* fsin = (const float*)d_in[8];
    float* out = (float*)d_out;

    float *q, *k, *v;
    __half *xh, *wqh, *wkh, *wvh, *woh, *qh, *kh, *vt, *atth;
    cudaGetSymbolAddress((void**)&q,    g_q);
    cudaGetSymbolAddress((void**)&k,    g_k);
    cudaGetSymbolAddress((void**)&v,    g_v);
    cudaGetSymbolAddress((void**)&xh,   g_xh);
    cudaGetSymbolAddress((void**)&wqh,  g_wqh);
    cudaGetSymbolAddress((void**)&wkh,  g_wkh);
    cudaGetSymbolAddress((void**)&wvh,  g_wvh);
    cudaGetSymbolAddress((void**)&woh,  g_woh);
    cudaGetSymbolAddress((void**)&qh,   g_qh);
    cudaGetSymbolAddress((void**)&kh,   g_kh);
    cudaGetSymbolAddress((void**)&vt,   g_vt);
    cudaGetSymbolAddress((void**)&atth, g_atth);

    cudaFuncSetAttribute(flash_tc, cudaFuncAttributeMaxDynamicSharedMemorySize, FA5_SMEM);
    cudaFuncSetAttribute(gemm_h, cudaFuncAttributeMaxDynamicSharedMemorySize, GEMM_SMEM3);
    cudaFuncSetAttribute(gemm_qkv_h, cudaFuncAttributeMaxDynamicSharedMemorySize, GEMM_SMEM3);

    // [0] x -> fp16
    preround_xh<<<(NTOK * DD / 4) / 256, 256>>>(x, xh);
    // [1] weights -> fp16 transposed
    wtrans_all<<<dim3(64, 160), dim3(32, 8)>>>(wq, wk, wv, wo, wqh, wkh, wvh, woh);
    // [2] Q+K+V projections, ONE launch (768 CTAs)   <- ncu capture slot
    gemm_qkv_h<<<dim3(24, NTOK / GBM), 256, GEMM_SMEM3>>>(
        NTOK, DD, xh, wqh, wkh, wvh, q, k, v);
    // [3] RMSNorm+RoPE -> fp16 q/k
    norm_rope_h<<<NTOK, dim3(32, HH + KVH)>>>(q, k, qh, kh, qnw, knw, fcos, fsin);
    // [4] V -> V^T fp16
    vtrans<<<dim3(TT / 32, HD / 32, BB * KVH), dim3(32, 8)>>>(v, vt);
    // [5] flash attention
    flash_tc<<<dim3(HH * BB, TT / FTQ), 128, FA5_SMEM>>>(qh, kh, vt, atth);
    // [6] output projection
    gemm_h<<<dim3(DD / GBN, NTOK / GBM), 256, GEMM_SMEM3>>>(NTOK, DD, HH * HD, atth, woh, out);
}